// round 5
// baseline (speedup 1.0000x reference)
#include <cuda_runtime.h>
#include <cstdint>
#include <math.h>

#define NN 100000
#define NG 100
#define NE 1000000
#define HD 256
#define NT 4

#define ASTRIDE 36
#define BSTRIDE 136
#define ASTG (128 * ASTRIDE)
#define BSTG (32 * BSTRIDE)
#define GEMM_SMEM ((2 * ASTG + 2 * BSTG) * 4)

__device__ float g_htf[(size_t)NN * HD];    // tf32-rounded node state (sole copy)
__device__ float g_trans[(size_t)NN * NT * HD];
__device__ float g_msgs[(size_t)NN * HD];   // tf32-rounded at store
__device__ float g_gx[(size_t)NN * 3 * HD];
__device__ float g_gh[(size_t)NN * 3 * HD];
__device__ float g_twr[2 * NT * HD * HD];   // tf32-rounded weights
__device__ float g_gWr[2 * HD * 3 * HD];
__device__ float g_gUr[2 * HD * 3 * HD];
__device__ float g_gate[NN];
__device__ float g_outs[2 * NN];
__device__ float g_sums[NG];
__device__ unsigned g_gmax;
__device__ int g_deg[NN];
__device__ int g_rowoff[NN + 1];
__device__ int g_cursor[NN];
__device__ int g_csr[NE];
__device__ int g_cum[NG];

__device__ __forceinline__ float to_tf32(float x) {
  unsigned u;
  asm("cvt.rna.tf32.f32 %0, %1;" : "=r"(u) : "f"(x));
  return __uint_as_float(u);
}
__device__ __forceinline__ void mma_tf32(float* d, const unsigned* a, const unsigned* b) {
  asm volatile(
      "mma.sync.aligned.m16n8k8.row.col.f32.tf32.tf32.f32 "
      "{%0,%1,%2,%3}, {%4,%5,%6,%7}, {%8,%9}, {%0,%1,%2,%3};\n"
      : "+f"(d[0]), "+f"(d[1]), "+f"(d[2]), "+f"(d[3])
      : "r"(a[0]), "r"(a[1]), "r"(a[2]), "r"(a[3]), "r"(b[0]), "r"(b[1]));
}
__device__ __forceinline__ void cpa16(float* dst, const float* src, bool pred) {
  unsigned d = (unsigned)__cvta_generic_to_shared(dst);
  int sz = pred ? 16 : 0;
  asm volatile("cp.async.cg.shared.global [%0], [%1], 16, %2;\n" :: "r"(d), "l"(src), "r"(sz));
}
__device__ __forceinline__ unsigned fenc(float f) {
  unsigned u = __float_as_uint(f);
  return (u & 0x80000000u) ? ~u : (u | 0x80000000u);
}
__device__ __forceinline__ float fdec(unsigned e) {
  return (e & 0x80000000u) ? __uint_as_float(e & 0x7fffffffu) : __uint_as_float(~e);
}
__device__ __forceinline__ int find_seg(int v) {
  int lo = 0, hi = NG;
  while (lo < hi) { int mid = (lo + hi) >> 1; if (g_cum[mid] > v) hi = mid; else lo = mid + 1; }
  return lo;
}
__device__ __forceinline__ float gru1(float xz, float xr, float xh,
                                      float hz, float hr, float hh, float h) {
  float z = 1.f / (1.f + expf(-(xz + hz)));
  float r = 1.f / (1.f + expf(-(xr + hr)));
  float c = tanhf(xh + r * hh);
  return z * h + (1.f - z) * c;
}

__global__ void k_h_init(const int* __restrict__ nodes, const float* __restrict__ embed) {
  int idx = blockIdx.x * blockDim.x + threadIdx.x;
  if (idx >= NN * HD) return;
  int v = idx >> 8, j = idx & 255;
  int tok = __ldg(&nodes[v]);
  int pos = __ldg(&nodes[NN + v]);
  int p = pos < 512 ? pos : 512;
  float pe = 0.f;
  if (p > 0) {
    float ang = (float)(p - 1) * exp2f(-(float)j * 0.10381025296523f);
    pe = (j & 1) ? cosf(ang) : sinf(ang);
  }
  g_htf[idx] = to_tf32(__ldg(&embed[(size_t)tok * HD + j]) + pe);
}

__global__ void k_round_w(const float* __restrict__ tw, const float* __restrict__ gW,
                          const float* __restrict__ gU) {
  int i = blockIdx.x * blockDim.x + threadIdx.x;
  if (i < 2 * NT * HD * HD) g_twr[i] = to_tf32(__ldg(&tw[i]));
  if (i < 2 * HD * 3 * HD) {
    g_gWr[i] = to_tf32(__ldg(&gW[i]));
    g_gUr[i] = to_tf32(__ldg(&gU[i]));
  }
}

__global__ void k_init_misc(const int* __restrict__ sizes, float* __restrict__ out) {
  int i = blockIdx.x * blockDim.x + threadIdx.x;
  if (i < NN) g_deg[i] = 0;
  if (blockIdx.x == 0) {
    int t = threadIdx.x;
    if (t < NG) g_sums[t] = 0.f;
    if (t < 2 * NG) out[t] = 0.f;
    if (t == 0) {
      g_gmax = 0u;
      int s = 0;
      for (int g = 0; g < NG; g++) { s += sizes[g]; g_cum[g] = s; }
    }
  }
}

__global__ void k_count(const int* __restrict__ edges) {
  int i = blockIdx.x * blockDim.x + threadIdx.x;
  if (i < NE) atomicAdd(&g_deg[edges[3 * i + 2]], 1);
}

__global__ void k_scan() {
  __shared__ int sCarry;
  __shared__ int warpTot[32];
  int tid = threadIdx.x;
  int lane = tid & 31, wid = tid >> 5;
  if (tid == 0) sCarry = 0;
  __syncthreads();
  for (int base = 0; base < NN; base += 1024) {
    int i = base + tid;
    int v = (i < NN) ? g_deg[i] : 0;
    int x = v;
#pragma unroll
    for (int off = 1; off < 32; off <<= 1) {
      int y = __shfl_up_sync(~0u, x, off);
      if (lane >= off) x += y;
    }
    if (lane == 31) warpTot[wid] = x;
    __syncthreads();
    if (wid == 0) {
      int w = warpTot[lane];
#pragma unroll
      for (int off = 1; off < 32; off <<= 1) {
        int y = __shfl_up_sync(~0u, w, off);
        if (lane >= off) w += y;
      }
      warpTot[lane] = w;
    }
    __syncthreads();
    int warpPrefix = (wid > 0) ? warpTot[wid - 1] : 0;
    int incl = x + warpPrefix;
    int excl = incl - v;
    int carry = sCarry;
    if (i < NN) { g_rowoff[i] = carry + excl; g_cursor[i] = carry + excl; }
    __syncthreads();
    if (tid == 1023) sCarry = carry + incl;
    __syncthreads();
  }
  if (tid == 0) g_rowoff[NN] = sCarry;
}

__global__ void k_fill(const int* __restrict__ edges) {
  int i = blockIdx.x * blockDim.x + threadIdx.x;
  if (i >= NE) return;
  int et = edges[3 * i], src = edges[3 * i + 1], tgt = edges[3 * i + 2];
  int p = atomicAdd(&g_cursor[tgt], 1);
  g_csr[p] = (src << 2) | et;
}

// C[M, gridX*128] = A[M,256] @ B (+bias); inputs pre-rounded to tf32.
// blockIdx.x = N tile (fastest -> same A row-tile resident in L2),
// blockIdx.y = M tile. 2-stage cp.async pipeline, BK=32.
__global__ __launch_bounds__(256)
void k_gemm(const float* __restrict__ A, int M,
            const float* __restrict__ B, int ldb, int nblk, long nblkStride,
            const float* __restrict__ bias, int biasBlkStride,
            float* __restrict__ C, int ldc) {
  extern __shared__ float sm[];
  float* As = sm;               // [2][128][36]
  float* Bs = sm + 2 * ASTG;    // [2][32][136]
  int m0 = blockIdx.y * 128;
  int n0 = blockIdx.x * 128;
  int tB = n0 / nblk;
  int nb0 = n0 - tB * nblk;
  const float* Bblk = B + (size_t)tB * nblkStride + nb0;
  int tid = threadIdx.x, lane = tid & 31, warp = tid >> 5;
  int wm = (warp & 3) * 32, wn = (warp >> 2) * 64;
  int ar = tid >> 3, ac = (tid & 7) * 4;
  int br = tid >> 5, bc = (tid & 31) * 4;
  size_t arow[4];
  bool apred[4];
#pragma unroll
  for (int p = 0; p < 4; p++) {
    int r = m0 + ar + p * 32;
    apred[p] = r < M;
    arow[p] = apred[p] ? (size_t)r : 0;
  }

  float acc[2][8][4];
#pragma unroll
  for (int i = 0; i < 2; i++)
#pragma unroll
    for (int j = 0; j < 8; j++)
#pragma unroll
      for (int k = 0; k < 4; k++) acc[i][j][k] = 0.f;

#pragma unroll
  for (int p = 0; p < 4; p++)
    cpa16(&As[(ar + p * 32) * ASTRIDE + ac], A + arow[p] * HD + ac, apred[p]);
#pragma unroll
  for (int p = 0; p < 4; p++)
    cpa16(&Bs[(br + p * 8) * BSTRIDE + bc], Bblk + (size_t)(br + p * 8) * ldb + bc, true);
  asm volatile("cp.async.commit_group;\n");

#pragma unroll
  for (int kt = 0; kt < 8; kt++) {
    int s = kt & 1;
    if (kt < 7) {
      int s2 = (kt + 1) & 1;
      int k0 = (kt + 1) * 32;
#pragma unroll
      for (int p = 0; p < 4; p++)
        cpa16(&As[s2 * ASTG + (ar + p * 32) * ASTRIDE + ac], A + arow[p] * HD + k0 + ac, apred[p]);
#pragma unroll
      for (int p = 0; p < 4; p++)
        cpa16(&Bs[s2 * BSTG + (br + p * 8) * BSTRIDE + bc],
              Bblk + (size_t)(k0 + br + p * 8) * ldb + bc, true);
      asm volatile("cp.async.commit_group;\n");
      asm volatile("cp.async.wait_group 1;\n");
    } else {
      asm volatile("cp.async.wait_group 0;\n");
    }
    __syncthreads();
    const float* Asb = As + s * ASTG;
    const float* Bsb = Bs + s * BSTG;
#pragma unroll
    for (int ks = 0; ks < 4; ks++) {
      int kk = ks * 8;
      unsigned af[2][4], bf[8][2];
#pragma unroll
      for (int mt = 0; mt < 2; mt++) {
        int r = wm + mt * 16 + (lane >> 2);
        int cA = kk + (lane & 3);
        af[mt][0] = __float_as_uint(Asb[r * ASTRIDE + cA]);
        af[mt][1] = __float_as_uint(Asb[(r + 8) * ASTRIDE + cA]);
        af[mt][2] = __float_as_uint(Asb[r * ASTRIDE + cA + 4]);
        af[mt][3] = __float_as_uint(Asb[(r + 8) * ASTRIDE + cA + 4]);
      }
#pragma unroll
      for (int nt = 0; nt < 8; nt++) {
        int cN = wn + nt * 8 + (lane >> 2);
        int rB = kk + (lane & 3);
        bf[nt][0] = __float_as_uint(Bsb[rB * BSTRIDE + cN]);
        bf[nt][1] = __float_as_uint(Bsb[(rB + 4) * BSTRIDE + cN]);
      }
#pragma unroll
      for (int mt = 0; mt < 2; mt++)
#pragma unroll
        for (int nt = 0; nt < 8; nt++) mma_tf32(acc[mt][nt], af[mt], bf[nt]);
    }
    __syncthreads();
  }

#pragma unroll
  for (int mt = 0; mt < 2; mt++) {
    int r0 = m0 + wm + mt * 16 + (lane >> 2);
#pragma unroll
    for (int nt = 0; nt < 8; nt++) {
      int cc = wn + nt * 8 + 2 * (lane & 3);
      float b0 = __ldg(&bias[(size_t)tB * biasBlkStride + nb0 + cc]);
      float b1 = __ldg(&bias[(size_t)tB * biasBlkStride + nb0 + cc + 1]);
      int gn = n0 + cc;
      if (r0 < M) {
        C[(size_t)r0 * ldc + gn] = acc[mt][nt][0] + b0;
        C[(size_t)r0 * ldc + gn + 1] = acc[mt][nt][1] + b1;
      }
      if (r0 + 8 < M) {
        C[(size_t)(r0 + 8) * ldc + gn] = acc[mt][nt][2] + b0;
        C[(size_t)(r0 + 8) * ldc + gn + 1] = acc[mt][nt][3] + b1;
      }
    }
  }
}

__global__ void k_msgs() {
  int gw = (blockIdx.x * blockDim.x + threadIdx.x) >> 5;
  int lane = threadIdx.x & 31;
  if (gw >= NN) return;
  int beg = g_rowoff[gw], end = g_rowoff[gw + 1];
  float4 a0 = make_float4(0.f, 0.f, 0.f, 0.f);
  float4 a1 = make_float4(0.f, 0.f, 0.f, 0.f);
  int i = beg;
  for (; i + 1 < end; i += 2) {
    int e0 = __ldg(&g_csr[i]), e1 = __ldg(&g_csr[i + 1]);
    const float4* p0 = (const float4*)(g_trans +
        ((size_t)(e0 >> 2) * (NT * HD) + (size_t)(e0 & 3) * HD));
    const float4* p1 = (const float4*)(g_trans +
        ((size_t)(e1 >> 2) * (NT * HD) + (size_t)(e1 & 3) * HD));
    float4 x0 = __ldg(p0 + lane), x1 = __ldg(p0 + lane + 32);
    float4 y0 = __ldg(p1 + lane), y1 = __ldg(p1 + lane + 32);
    a0.x += x0.x + y0.x; a0.y += x0.y + y0.y; a0.z += x0.z + y0.z; a0.w += x0.w + y0.w;
    a1.x += x1.x + y1.x; a1.y += x1.y + y1.y; a1.z += x1.z + y1.z; a1.w += x1.w + y1.w;
  }
  if (i < end) {
    int e0 = __ldg(&g_csr[i]);
    const float4* p0 = (const float4*)(g_trans +
        ((size_t)(e0 >> 2) * (NT * HD) + (size_t)(e0 & 3) * HD));
    float4 x0 = __ldg(p0 + lane), x1 = __ldg(p0 + lane + 32);
    a0.x += x0.x; a0.y += x0.y; a0.z += x0.z; a0.w += x0.w;
    a1.x += x1.x; a1.y += x1.y; a1.z += x1.z; a1.w += x1.w;
  }
  a0.x = to_tf32(a0.x); a0.y = to_tf32(a0.y); a0.z = to_tf32(a0.z); a0.w = to_tf32(a0.w);
  a1.x = to_tf32(a1.x); a1.y = to_tf32(a1.y); a1.z = to_tf32(a1.z); a1.w = to_tf32(a1.w);
  float4* o = (float4*)(g_msgs + (size_t)gw * HD);
  o[lane] = a0;
  o[lane + 32] = a1;
}

__global__ void k_gru() {
  int idx = blockIdx.x * blockDim.x + threadIdx.x;
  if (idx >= NN * 64) return;
  int v = idx >> 6, q = idx & 63;
  const float4* px = (const float4*)(g_gx + (size_t)v * 768);
  const float4* ph = (const float4*)(g_gh + (size_t)v * 768);
  float4 xz = px[q], xr = px[q + 64], xh = px[q + 128];
  float4 hz = ph[q], hr = ph[q + 64], hh = ph[q + 128];
  float4 hv = ((const float4*)g_htf)[idx];
  float4 r;
  r.x = to_tf32(gru1(xz.x, xr.x, xh.x, hz.x, hr.x, hh.x, hv.x));
  r.y = to_tf32(gru1(xz.y, xr.y, xh.y, hz.y, hr.y, hh.y, hv.y));
  r.z = to_tf32(gru1(xz.z, xr.z, xh.z, hz.z, hr.z, hh.z, hv.z));
  r.w = to_tf32(gru1(xz.w, xr.w, xh.w, hz.w, hr.w, hh.w, hv.w));
  ((float4*)g_htf)[idx] = r;
}

__global__ void k_readout1(const float* __restrict__ gateW, const float* __restrict__ gateB,
                           const float* __restrict__ outW, const float* __restrict__ outB) {
  int warp = threadIdx.x >> 5, lane = threadIdx.x & 31;
  int v = blockIdx.x * 8 + warp;
  float g = 0.f, o0 = 0.f, o1 = 0.f;
  if (v < NN) {
    const float* hv = g_htf + (size_t)v * HD;
#pragma unroll 4
    for (int j = lane; j < HD; j += 32) {
      float x = hv[j];
      g += x * __ldg(&gateW[j]);
      float2 w = __ldg((const float2*)outW + j);
      o0 += x * w.x;
      o1 += x * w.y;
    }
  }
#pragma unroll
  for (int off = 16; off; off >>= 1) {
    g += __shfl_xor_sync(~0u, g, off);
    o0 += __shfl_xor_sync(~0u, o0, off);
    o1 += __shfl_xor_sync(~0u, o1, off);
  }
  float gl = g + __ldg(gateB);
  if (v < NN && lane == 0) {
    g_gate[v] = gl;
    g_outs[2 * v] = o0 + __ldg(&outB[0]);
    g_outs[2 * v + 1] = o1 + __ldg(&outB[1]);
  }
  __shared__ float smax[8];
  if (lane == 0) smax[warp] = (v < NN) ? gl : -3.4e38f;
  __syncthreads();
  if (threadIdx.x == 0) {
    float m = smax[0];
#pragma unroll
    for (int i = 1; i < 8; i++) m = fmaxf(m, smax[i]);
    atomicMax(&g_gmax, fenc(m));
  }
}

__global__ void k_readout2() {
  int v = blockIdx.x * blockDim.x + threadIdx.x;
  __shared__ float part[4];
  __shared__ int s0;
  if (threadIdx.x < 4) part[threadIdx.x] = 0.f;
  if (threadIdx.x == 0) s0 = find_seg(blockIdx.x * blockDim.x);
  __syncthreads();
  if (v < NN) {
    float e = expf(g_gate[v] - fdec(g_gmax));
    g_gate[v] = e;
    int s = find_seg(v);
    atomicAdd(&part[s - s0], e);
  }
  __syncthreads();
  if (threadIdx.x < 4 && part[threadIdx.x] != 0.f)
    atomicAdd(&g_sums[s0 + threadIdx.x], part[threadIdx.x]);
}

__global__ void k_readout3(float* __restrict__ out) {
  int v = blockIdx.x * blockDim.x + threadIdx.x;
  __shared__ float p0[4], p1[4];
  __shared__ int s0;
  if (threadIdx.x < 4) { p0[threadIdx.x] = 0.f; p1[threadIdx.x] = 0.f; }
  if (threadIdx.x == 0) s0 = find_seg(blockIdx.x * blockDim.x);
  __syncthreads();
  if (v < NN) {
    int s = find_seg(v);
    float w = g_gate[v] / (g_sums[s] + 1e-16f);
    atomicAdd(&p0[s - s0], g_outs[2 * v] * w);
    atomicAdd(&p1[s - s0], g_outs[2 * v + 1] * w);
  }
  __syncthreads();
  if (threadIdx.x < 4) {
    int s = s0 + threadIdx.x;
    if (s < NG && (p0[threadIdx.x] != 0.f || p1[threadIdx.x] != 0.f)) {
      atomicAdd(&out[2 * s], p0[threadIdx.x]);
      atomicAdd(&out[2 * s + 1], p1[threadIdx.x]);
    }
  }
}

extern "C" void kernel_launch(void* const* d_in, const int* in_sizes, int n_in,
                              void* d_out, int out_size) {
  const int* nodes = (const int*)d_in[0];
  const int* gsizes = (const int*)d_in[1];
  const int* edges = (const int*)d_in[2];
  const float* embed = (const float*)d_in[3];
  const float* tw = (const float*)d_in[4];
  const float* tb = (const float*)d_in[5];
  const float* gW = (const float*)d_in[6];
  const float* gU = (const float*)d_in[7];
  const float* gbi = (const float*)d_in[8];
  const float* gbr = (const float*)d_in[9];
  const float* gateW = (const float*)d_in[10];
  const float* gateB = (const float*)d_in[11];
  const float* outW = (const float*)d_in[12];
  const float* outB = (const float*)d_in[13];
  float* out = (float*)d_out;

  cudaFuncSetAttribute(k_gemm, cudaFuncAttributeMaxDynamicSharedMemorySize, GEMM_SMEM);

  float* htf;   cudaGetSymbolAddress((void**)&htf, g_htf);
  float* trptr; cudaGetSymbolAddress((void**)&trptr, g_trans);
  float* msptr; cudaGetSymbolAddress((void**)&msptr, g_msgs);
  float* gxptr; cudaGetSymbolAddress((void**)&gxptr, g_gx);
  float* ghptr; cudaGetSymbolAddress((void**)&ghptr, g_gh);
  float* twr;   cudaGetSymbolAddress((void**)&twr, g_twr);
  float* gWr;   cudaGetSymbolAddress((void**)&gWr, g_gWr);
  float* gUr;   cudaGetSymbolAddress((void**)&gUr, g_gUr);

  const int steps[2] = {3, 1};
  dim3 gT(8, (NN + 127) / 128);
  dim3 gG(6, (NN + 127) / 128);

  // launches 0-2: prerequisites for the first trans GEMM
  k_h_init<<<(NN * HD + 255) / 256, 256>>>(nodes, embed);
  k_round_w<<<(2 * NT * HD * HD + 255) / 256, 256>>>(tw, gW, gU);
  k_init_misc<<<(NN + 255) / 256, 256>>>(gsizes, out);
  // launch 3: first trans GEMM (profiled slot)
  k_gemm<<<gT, 256, GEMM_SMEM>>>(htf, NN, twr, HD, HD, (long)HD * HD, tb, HD, trptr, NT * HD);
  // CSR build (needed before first k_msgs)
  k_count<<<(NE + 255) / 256, 256>>>(edges);
  k_scan<<<1, 1024>>>();
  k_fill<<<(NE + 255) / 256, 256>>>(edges);

  for (int l = 0; l < 2; l++) {
    const float* Wt = twr + (size_t)l * NT * HD * HD;
    const float* bt = tb + (size_t)l * NT * HD;
    const float* Wx = gWr + (size_t)l * HD * 768;
    const float* Uh = gUr + (size_t)l * HD * 768;
    const float* bi = gbi + (size_t)l * 768;
    const float* br = gbr + (size_t)l * 768;
    for (int s = 0; s < steps[l]; s++) {
      if (l != 0 || s != 0)
        k_gemm<<<gT, 256, GEMM_SMEM>>>(htf, NN, Wt, HD, HD, (long)HD * HD, bt, HD, trptr, NT * HD);
      k_msgs<<<(NN * 32 + 255) / 256, 256>>>();
      k_gemm<<<gG, 256, GEMM_SMEM>>>(msptr, NN, Wx, 768, 768, 0, bi, 0, gxptr, 768);
      k_gemm<<<gG, 256, GEMM_SMEM>>>(htf, NN, Uh, 768, 768, 0, br, 0, ghptr, 768);
      k_gru<<<(NN * 64 + 255) / 256, 256>>>();
    }
  }
  k_readout1<<<(NN + 7) / 8, 256>>>(gateW, gateB, outW, outB);
  k_readout2<<<(NN + 255) / 256, 256>>>();
  k_readout3<<<(NN + 255) / 256, 256>>>(out);
}

// round 6
// speedup vs baseline: 1.5581x; 1.5581x over previous
#include <cuda_runtime.h>
#include <cstdint>
#include <math.h>

#define NN 100000
#define NG 100
#define NE 1000000
#define HD 256
#define NT 4

#define ASTRIDE 36
#define BSTRIDE 136
#define ASTG (128 * ASTRIDE)
#define BSTG (32 * BSTRIDE)
#define GEMM_SMEM ((2 * ASTG + 2 * BSTG) * 4)

__device__ float g_htf[(size_t)NN * HD];    // tf32-rounded node state (sole copy)
__device__ float g_trans[(size_t)NN * NT * HD];
__device__ float g_msgs[(size_t)NN * HD];   // tf32-rounded at store
__device__ float g_gx[(size_t)NN * 3 * HD];
__device__ float g_gh[(size_t)NN * 3 * HD];
__device__ float g_twr[2 * NT * HD * HD];   // tf32-rounded weights
__device__ float g_gWr[2 * HD * 3 * HD];
__device__ float g_gUr[2 * HD * 3 * HD];
__device__ float g_gate[NN];
__device__ float g_outs[2 * NN];
__device__ float g_sums[NG];
__device__ unsigned g_gmax;
__device__ int g_deg[NN];
__device__ int g_rowoff[NN + 1];
__device__ int g_cursor[NN];
__device__ int g_csr[NE];
__device__ int g_cum[NG];

__device__ __forceinline__ float to_tf32(float x) {
  unsigned u;
  asm("cvt.rna.tf32.f32 %0, %1;" : "=r"(u) : "f"(x));
  return __uint_as_float(u);
}
__device__ __forceinline__ void mma_tf32(float* d, const unsigned* a, const unsigned* b) {
  asm volatile(
      "mma.sync.aligned.m16n8k8.row.col.f32.tf32.tf32.f32 "
      "{%0,%1,%2,%3}, {%4,%5,%6,%7}, {%8,%9}, {%0,%1,%2,%3};\n"
      : "+f"(d[0]), "+f"(d[1]), "+f"(d[2]), "+f"(d[3])
      : "r"(a[0]), "r"(a[1]), "r"(a[2]), "r"(a[3]), "r"(b[0]), "r"(b[1]));
}
__device__ __forceinline__ void cpa16(float* dst, const float* src, bool pred) {
  unsigned d = (unsigned)__cvta_generic_to_shared(dst);
  int sz = pred ? 16 : 0;
  asm volatile("cp.async.cg.shared.global [%0], [%1], 16, %2;\n" :: "r"(d), "l"(src), "r"(sz));
}
__device__ __forceinline__ unsigned fenc(float f) {
  unsigned u = __float_as_uint(f);
  return (u & 0x80000000u) ? ~u : (u | 0x80000000u);
}
__device__ __forceinline__ float fdec(unsigned e) {
  return (e & 0x80000000u) ? __uint_as_float(e & 0x7fffffffu) : __uint_as_float(~e);
}
__device__ __forceinline__ int find_seg(int v) {
  int lo = 0, hi = NG;
  while (lo < hi) { int mid = (lo + hi) >> 1; if (g_cum[mid] > v) hi = mid; else lo = mid + 1; }
  return lo;
}
__device__ __forceinline__ float gru1(float xz, float xr, float xh,
                                      float hz, float hr, float hh, float h) {
  float z = 1.f / (1.f + expf(-(xz + hz)));
  float r = 1.f / (1.f + expf(-(xr + hr)));
  float c = tanhf(xh + r * hh);
  return z * h + (1.f - z) * c;
}

__global__ void k_h_init(const int* __restrict__ nodes, const float* __restrict__ embed) {
  int idx = blockIdx.x * blockDim.x + threadIdx.x;
  if (idx >= NN * HD) return;
  int v = idx >> 8, j = idx & 255;
  int tok = __ldg(&nodes[v]);
  int pos = __ldg(&nodes[NN + v]);
  int p = pos < 512 ? pos : 512;
  float pe = 0.f;
  if (p > 0) {
    float ang = (float)(p - 1) * exp2f(-(float)j * 0.10381025296523f);
    pe = (j & 1) ? cosf(ang) : sinf(ang);
  }
  g_htf[idx] = to_tf32(__ldg(&embed[(size_t)tok * HD + j]) + pe);
}

__global__ void k_round_w(const float* __restrict__ tw, const float* __restrict__ gW,
                          const float* __restrict__ gU) {
  int i = blockIdx.x * blockDim.x + threadIdx.x;
  if (i < 2 * NT * HD * HD) g_twr[i] = to_tf32(__ldg(&tw[i]));
  if (i < 2 * HD * 3 * HD) {
    g_gWr[i] = to_tf32(__ldg(&gW[i]));
    g_gUr[i] = to_tf32(__ldg(&gU[i]));
  }
}

__global__ void k_init_misc(const int* __restrict__ sizes, float* __restrict__ out) {
  int i = blockIdx.x * blockDim.x + threadIdx.x;
  if (i < NN) g_deg[i] = 0;
  if (blockIdx.x == 0) {
    int t = threadIdx.x;
    if (t < NG) g_sums[t] = 0.f;
    if (t < 2 * NG) out[t] = 0.f;
    if (t == 0) {
      g_gmax = 0u;
      int s = 0;
      for (int g = 0; g < NG; g++) { s += sizes[g]; g_cum[g] = s; }
    }
  }
}

__global__ void k_count(const int* __restrict__ edges) {
  int i = blockIdx.x * blockDim.x + threadIdx.x;
  if (i < NE) atomicAdd(&g_deg[edges[3 * i + 2]], 1);
}

__global__ void k_scan() {
  __shared__ int sCarry;
  __shared__ int warpTot[32];
  int tid = threadIdx.x;
  int lane = tid & 31, wid = tid >> 5;
  if (tid == 0) sCarry = 0;
  __syncthreads();
  for (int base = 0; base < NN; base += 1024) {
    int i = base + tid;
    int v = (i < NN) ? g_deg[i] : 0;
    int x = v;
#pragma unroll
    for (int off = 1; off < 32; off <<= 1) {
      int y = __shfl_up_sync(~0u, x, off);
      if (lane >= off) x += y;
    }
    if (lane == 31) warpTot[wid] = x;
    __syncthreads();
    if (wid == 0) {
      int w = warpTot[lane];
#pragma unroll
      for (int off = 1; off < 32; off <<= 1) {
        int y = __shfl_up_sync(~0u, w, off);
        if (lane >= off) w += y;
      }
      warpTot[lane] = w;
    }
    __syncthreads();
    int warpPrefix = (wid > 0) ? warpTot[wid - 1] : 0;
    int incl = x + warpPrefix;
    int excl = incl - v;
    int carry = sCarry;
    if (i < NN) { g_rowoff[i] = carry + excl; g_cursor[i] = carry + excl; }
    __syncthreads();
    if (tid == 1023) sCarry = carry + incl;
    __syncthreads();
  }
  if (tid == 0) g_rowoff[NN] = sCarry;
}

__global__ void k_fill(const int* __restrict__ edges) {
  int i = blockIdx.x * blockDim.x + threadIdx.x;
  if (i >= NE) return;
  int et = edges[3 * i], src = edges[3 * i + 1], tgt = edges[3 * i + 2];
  int p = atomicAdd(&g_cursor[tgt], 1);
  g_csr[p] = (src << 2) | et;
}

// C[M, gridY*128] = A[M,256] @ B (+bias); inputs pre-rounded to tf32.
// M-fastest raster; 2-stage cp.async pipeline, BK=32; 2 CTAs/SM.
__global__ __launch_bounds__(256, 2)
void k_gemm(const float* __restrict__ A, int M,
            const float* __restrict__ B, int ldb, int nblk, long nblkStride,
            const float* __restrict__ bias, int biasBlkStride,
            float* __restrict__ C, int ldc) {
  extern __shared__ float sm[];
  float* As = sm;               // [2][128][36]
  float* Bs = sm + 2 * ASTG;    // [2][32][136]
  int m0 = blockIdx.x * 128;
  int n0 = blockIdx.y * 128;
  int tB = n0 / nblk;
  int nb0 = n0 - tB * nblk;
  const float* Bblk = B + (size_t)tB * nblkStride + nb0;
  int tid = threadIdx.x, lane = tid & 31, warp = tid >> 5;
  int wm = (warp & 3) * 32, wn = (warp >> 2) * 64;
  int ar = tid >> 3, ac = (tid & 7) * 4;
  int br = tid >> 5, bc = (tid & 31) * 4;
  const float* Arow = A + (size_t)(m0 + ar) * HD;  // base; p offsets constant

  float acc[2][8][4];
#pragma unroll
  for (int i = 0; i < 2; i++)
#pragma unroll
    for (int j = 0; j < 8; j++)
#pragma unroll
      for (int k = 0; k < 4; k++) acc[i][j][k] = 0.f;

#pragma unroll
  for (int p = 0; p < 4; p++)
    cpa16(&As[(ar + p * 32) * ASTRIDE + ac], Arow + (size_t)p * 32 * HD + ac,
          (m0 + ar + p * 32) < M);
#pragma unroll
  for (int p = 0; p < 4; p++)
    cpa16(&Bs[(br + p * 8) * BSTRIDE + bc], Bblk + (size_t)(br + p * 8) * ldb + bc, true);
  asm volatile("cp.async.commit_group;\n");

#pragma unroll
  for (int kt = 0; kt < 8; kt++) {
    int s = kt & 1;
    if (kt < 7) {
      int s2 = (kt + 1) & 1;
      int k0 = (kt + 1) * 32;
#pragma unroll
      for (int p = 0; p < 4; p++)
        cpa16(&As[s2 * ASTG + (ar + p * 32) * ASTRIDE + ac],
              Arow + (size_t)p * 32 * HD + k0 + ac, (m0 + ar + p * 32) < M);
#pragma unroll
      for (int p = 0; p < 4; p++)
        cpa16(&Bs[s2 * BSTG + (br + p * 8) * BSTRIDE + bc],
              Bblk + (size_t)(k0 + br + p * 8) * ldb + bc, true);
      asm volatile("cp.async.commit_group;\n");
      asm volatile("cp.async.wait_group 1;\n");
    } else {
      asm volatile("cp.async.wait_group 0;\n");
    }
    __syncthreads();
    const float* Asb = As + s * ASTG;
    const float* Bsb = Bs + s * BSTG;
#pragma unroll
    for (int ks = 0; ks < 4; ks++) {
      int kk = ks * 8;
      unsigned af[2][4], bf[8][2];
#pragma unroll
      for (int mt = 0; mt < 2; mt++) {
        int r = wm + mt * 16 + (lane >> 2);
        int cA = kk + (lane & 3);
        af[mt][0] = __float_as_uint(Asb[r * ASTRIDE + cA]);
        af[mt][1] = __float_as_uint(Asb[(r + 8) * ASTRIDE + cA]);
        af[mt][2] = __float_as_uint(Asb[r * ASTRIDE + cA + 4]);
        af[mt][3] = __float_as_uint(Asb[(r + 8) * ASTRIDE + cA + 4]);
      }
#pragma unroll
      for (int nt = 0; nt < 8; nt++) {
        int cN = wn + nt * 8 + (lane >> 2);
        int rB = kk + (lane & 3);
        bf[nt][0] = __float_as_uint(Bsb[rB * BSTRIDE + cN]);
        bf[nt][1] = __float_as_uint(Bsb[(rB + 4) * BSTRIDE + cN]);
      }
#pragma unroll
      for (int mt = 0; mt < 2; mt++)
#pragma unroll
        for (int nt = 0; nt < 8; nt++) mma_tf32(acc[mt][nt], af[mt], bf[nt]);
    }
    __syncthreads();
  }

#pragma unroll
  for (int mt = 0; mt < 2; mt++) {
    int r0 = m0 + wm + mt * 16 + (lane >> 2);
#pragma unroll
    for (int nt = 0; nt < 8; nt++) {
      int cc = wn + nt * 8 + 2 * (lane & 3);
      float b0 = __ldg(&bias[(size_t)tB * biasBlkStride + nb0 + cc]);
      float b1 = __ldg(&bias[(size_t)tB * biasBlkStride + nb0 + cc + 1]);
      int gn = n0 + cc;
      if (r0 < M) {
        C[(size_t)r0 * ldc + gn] = acc[mt][nt][0] + b0;
        C[(size_t)r0 * ldc + gn + 1] = acc[mt][nt][1] + b1;
      }
      if (r0 + 8 < M) {
        C[(size_t)(r0 + 8) * ldc + gn] = acc[mt][nt][2] + b0;
        C[(size_t)(r0 + 8) * ldc + gn + 1] = acc[mt][nt][3] + b1;
      }
    }
  }
}

__global__ void k_msgs() {
  int gw = (blockIdx.x * blockDim.x + threadIdx.x) >> 5;
  int lane = threadIdx.x & 31;
  if (gw >= NN) return;
  int beg = g_rowoff[gw], end = g_rowoff[gw + 1];
  float4 a0 = make_float4(0.f, 0.f, 0.f, 0.f);
  float4 a1 = make_float4(0.f, 0.f, 0.f, 0.f);
  int i = beg;
  for (; i + 1 < end; i += 2) {
    int e0 = __ldg(&g_csr[i]), e1 = __ldg(&g_csr[i + 1]);
    const float4* p0 = (const float4*)(g_trans +
        ((size_t)(e0 >> 2) * (NT * HD) + (size_t)(e0 & 3) * HD));
    const float4* p1 = (const float4*)(g_trans +
        ((size_t)(e1 >> 2) * (NT * HD) + (size_t)(e1 & 3) * HD));
    float4 x0 = __ldg(p0 + lane), x1 = __ldg(p0 + lane + 32);
    float4 y0 = __ldg(p1 + lane), y1 = __ldg(p1 + lane + 32);
    a0.x += x0.x + y0.x; a0.y += x0.y + y0.y; a0.z += x0.z + y0.z; a0.w += x0.w + y0.w;
    a1.x += x1.x + y1.x; a1.y += x1.y + y1.y; a1.z += x1.z + y1.z; a1.w += x1.w + y1.w;
  }
  if (i < end) {
    int e0 = __ldg(&g_csr[i]);
    const float4* p0 = (const float4*)(g_trans +
        ((size_t)(e0 >> 2) * (NT * HD) + (size_t)(e0 & 3) * HD));
    float4 x0 = __ldg(p0 + lane), x1 = __ldg(p0 + lane + 32);
    a0.x += x0.x; a0.y += x0.y; a0.z += x0.z; a0.w += x0.w;
    a1.x += x1.x; a1.y += x1.y; a1.z += x1.z; a1.w += x1.w;
  }
  a0.x = to_tf32(a0.x); a0.y = to_tf32(a0.y); a0.z = to_tf32(a0.z); a0.w = to_tf32(a0.w);
  a1.x = to_tf32(a1.x); a1.y = to_tf32(a1.y); a1.z = to_tf32(a1.z); a1.w = to_tf32(a1.w);
  float4* o = (float4*)(g_msgs + (size_t)gw * HD);
  o[lane] = a0;
  o[lane + 32] = a1;
}

__global__ void k_gru() {
  int idx = blockIdx.x * blockDim.x + threadIdx.x;
  if (idx >= NN * 64) return;
  int v = idx >> 6, q = idx & 63;
  const float4* px = (const float4*)(g_gx + (size_t)v * 768);
  const float4* ph = (const float4*)(g_gh + (size_t)v * 768);
  float4 xz = px[q], xr = px[q + 64], xh = px[q + 128];
  float4 hz = ph[q], hr = ph[q + 64], hh = ph[q + 128];
  float4 hv = ((const float4*)g_htf)[idx];
  float4 r;
  r.x = to_tf32(gru1(xz.x, xr.x, xh.x, hz.x, hr.x, hh.x, hv.x));
  r.y = to_tf32(gru1(xz.y, xr.y, xh.y, hz.y, hr.y, hh.y, hv.y));
  r.z = to_tf32(gru1(xz.z, xr.z, xh.z, hz.z, hr.z, hh.z, hv.z));
  r.w = to_tf32(gru1(xz.w, xr.w, xh.w, hz.w, hr.w, hh.w, hv.w));
  ((float4*)g_htf)[idx] = r;
}

__global__ void k_readout1(const float* __restrict__ gateW, const float* __restrict__ gateB,
                           const float* __restrict__ outW, const float* __restrict__ outB) {
  int warp = threadIdx.x >> 5, lane = threadIdx.x & 31;
  int v = blockIdx.x * 8 + warp;
  float g = 0.f, o0 = 0.f, o1 = 0.f;
  if (v < NN) {
    const float* hv = g_htf + (size_t)v * HD;
#pragma unroll 4
    for (int j = lane; j < HD; j += 32) {
      float x = hv[j];
      g += x * __ldg(&gateW[j]);
      float2 w = __ldg((const float2*)outW + j);
      o0 += x * w.x;
      o1 += x * w.y;
    }
  }
#pragma unroll
  for (int off = 16; off; off >>= 1) {
    g += __shfl_xor_sync(~0u, g, off);
    o0 += __shfl_xor_sync(~0u, o0, off);
    o1 += __shfl_xor_sync(~0u, o1, off);
  }
  float gl = g + __ldg(gateB);
  if (v < NN && lane == 0) {
    g_gate[v] = gl;
    g_outs[2 * v] = o0 + __ldg(&outB[0]);
    g_outs[2 * v + 1] = o1 + __ldg(&outB[1]);
  }
  __shared__ float smax[8];
  if (lane == 0) smax[warp] = (v < NN) ? gl : -3.4e38f;
  __syncthreads();
  if (threadIdx.x == 0) {
    float m = smax[0];
#pragma unroll
    for (int i = 1; i < 8; i++) m = fmaxf(m, smax[i]);
    atomicMax(&g_gmax, fenc(m));
  }
}

__global__ void k_readout2() {
  int v = blockIdx.x * blockDim.x + threadIdx.x;
  __shared__ float part[4];
  __shared__ int s0;
  if (threadIdx.x < 4) part[threadIdx.x] = 0.f;
  if (threadIdx.x == 0) s0 = find_seg(blockIdx.x * blockDim.x);
  __syncthreads();
  if (v < NN) {
    float e = expf(g_gate[v] - fdec(g_gmax));
    g_gate[v] = e;
    int s = find_seg(v);
    atomicAdd(&part[s - s0], e);
  }
  __syncthreads();
  if (threadIdx.x < 4 && part[threadIdx.x] != 0.f)
    atomicAdd(&g_sums[s0 + threadIdx.x], part[threadIdx.x]);
}

__global__ void k_readout3(float* __restrict__ out) {
  int v = blockIdx.x * blockDim.x + threadIdx.x;
  __shared__ float p0[4], p1[4];
  __shared__ int s0;
  if (threadIdx.x < 4) { p0[threadIdx.x] = 0.f; p1[threadIdx.x] = 0.f; }
  if (threadIdx.x == 0) s0 = find_seg(blockIdx.x * blockDim.x);
  __syncthreads();
  if (v < NN) {
    int s = find_seg(v);
    float w = g_gate[v] / (g_sums[s] + 1e-16f);
    atomicAdd(&p0[s - s0], g_outs[2 * v] * w);
    atomicAdd(&p1[s - s0], g_outs[2 * v + 1] * w);
  }
  __syncthreads();
  if (threadIdx.x < 4) {
    int s = s0 + threadIdx.x;
    if (s < NG && (p0[threadIdx.x] != 0.f || p1[threadIdx.x] != 0.f)) {
      atomicAdd(&out[2 * s], p0[threadIdx.x]);
      atomicAdd(&out[2 * s + 1], p1[threadIdx.x]);
    }
  }
}

extern "C" void kernel_launch(void* const* d_in, const int* in_sizes, int n_in,
                              void* d_out, int out_size) {
  const int* nodes = (const int*)d_in[0];
  const int* gsizes = (const int*)d_in[1];
  const int* edges = (const int*)d_in[2];
  const float* embed = (const float*)d_in[3];
  const float* tw = (const float*)d_in[4];
  const float* tb = (const float*)d_in[5];
  const float* gW = (const float*)d_in[6];
  const float* gU = (const float*)d_in[7];
  const float* gbi = (const float*)d_in[8];
  const float* gbr = (const float*)d_in[9];
  const float* gateW = (const float*)d_in[10];
  const float* gateB = (const float*)d_in[11];
  const float* outW = (const float*)d_in[12];
  const float* outB = (const float*)d_in[13];
  float* out = (float*)d_out;

  cudaFuncSetAttribute(k_gemm, cudaFuncAttributeMaxDynamicSharedMemorySize, GEMM_SMEM);

  float* htf;   cudaGetSymbolAddress((void**)&htf, g_htf);
  float* trptr; cudaGetSymbolAddress((void**)&trptr, g_trans);
  float* msptr; cudaGetSymbolAddress((void**)&msptr, g_msgs);
  float* gxptr; cudaGetSymbolAddress((void**)&gxptr, g_gx);
  float* ghptr; cudaGetSymbolAddress((void**)&ghptr, g_gh);
  float* twr;   cudaGetSymbolAddress((void**)&twr, g_twr);
  float* gWr;   cudaGetSymbolAddress((void**)&gWr, g_gWr);
  float* gUr;   cudaGetSymbolAddress((void**)&gUr, g_gUr);

  const int steps[2] = {3, 1};
  dim3 gT((NN + 127) / 128, 8);
  dim3 gG((NN + 127) / 128, 6);

  // launches 0-2: prerequisites for the first trans GEMM
  k_h_init<<<(NN * HD + 255) / 256, 256>>>(nodes, embed);
  k_round_w<<<(2 * NT * HD * HD + 255) / 256, 256>>>(tw, gW, gU);
  k_init_misc<<<(NN + 255) / 256, 256>>>(gsizes, out);
  // launch 3: first trans GEMM (profiled slot)
  k_gemm<<<gT, 256, GEMM_SMEM>>>(htf, NN, twr, HD, HD, (long)HD * HD, tb, HD, trptr, NT * HD);
  // CSR build (needed before first k_msgs)
  k_count<<<(NE + 255) / 256, 256>>>(edges);
  k_scan<<<1, 1024>>>();
  k_fill<<<(NE + 255) / 256, 256>>>(edges);

  for (int l = 0; l < 2; l++) {
    const float* Wt = twr + (size_t)l * NT * HD * HD;
    const float* bt = tb + (size_t)l * NT * HD;
    const float* Wx = gWr + (size_t)l * HD * 768;
    const float* Uh = gUr + (size_t)l * HD * 768;
    const float* bi = gbi + (size_t)l * 768;
    const float* br = gbr + (size_t)l * 768;
    for (int s = 0; s < steps[l]; s++) {
      if (l != 0 || s != 0)
        k_gemm<<<gT, 256, GEMM_SMEM>>>(htf, NN, Wt, HD, HD, (long)HD * HD, bt, HD, trptr, NT * HD);
      k_msgs<<<(NN * 32 + 255) / 256, 256>>>();
      k_gemm<<<gG, 256, GEMM_SMEM>>>(msptr, NN, Wx, 768, 768, 0, bi, 0, gxptr, 768);
      k_gemm<<<gG, 256, GEMM_SMEM>>>(htf, NN, Uh, 768, 768, 0, br, 0, ghptr, 768);
      k_gru<<<(NN * 64 + 255) / 256, 256>>>();
    }
  }
  k_readout1<<<(NN + 7) / 8, 256>>>(gateW, gateB, outW, outB);
  k_readout2<<<(NN + 255) / 256, 256>>>();
  k_readout3<<<(NN + 255) / 256, 256>>>(out);
}

// round 7
// speedup vs baseline: 1.5649x; 1.0044x over previous
#include <cuda_runtime.h>
#include <cstdint>
#include <math.h>

#define NN 100000
#define NG 100
#define NE 1000000
#define HD 256
#define NT 4

#define ASTRIDE 36
#define BSTRIDE 136
#define ASTG (128 * ASTRIDE)
#define BSTG (32 * BSTRIDE)
#define GEMM_SMEM ((2 * ASTG + 2 * BSTG) * 4)

__device__ float g_htf[(size_t)NN * HD];    // tf32-rounded node state (sole copy)
__device__ float g_trans[(size_t)NN * NT * HD];
__device__ float g_msgs[(size_t)NN * HD];   // tf32-rounded at store
__device__ float g_gx[(size_t)NN * 3 * HD];
__device__ float g_gh[(size_t)NN * 3 * HD];
__device__ float g_twr[2 * NT * HD * HD];   // tf32-rounded weights
__device__ float g_gWr[2 * HD * 3 * HD];
__device__ float g_gUr[2 * HD * 3 * HD];
__device__ float g_gate[NN];
__device__ float g_outs[2 * NN];
__device__ float g_sums[NG];
__device__ unsigned g_gmax;
__device__ int g_deg[NN];
__device__ int g_rowoff[NN + 1];
__device__ int g_cursor[NN];
__device__ int g_csr[NE];
__device__ int g_cum[NG];

__device__ __forceinline__ float to_tf32(float x) {
  unsigned u;
  asm("cvt.rna.tf32.f32 %0, %1;" : "=r"(u) : "f"(x));
  return __uint_as_float(u);
}
__device__ __forceinline__ void mma_tf32(float* d, const unsigned* a, const unsigned* b) {
  asm volatile(
      "mma.sync.aligned.m16n8k8.row.col.f32.tf32.tf32.f32 "
      "{%0,%1,%2,%3}, {%4,%5,%6,%7}, {%8,%9}, {%0,%1,%2,%3};\n"
      : "+f"(d[0]), "+f"(d[1]), "+f"(d[2]), "+f"(d[3])
      : "r"(a[0]), "r"(a[1]), "r"(a[2]), "r"(a[3]), "r"(b[0]), "r"(b[1]));
}
__device__ __forceinline__ void cpa16(float* dst, const float* src, bool pred) {
  unsigned d = (unsigned)__cvta_generic_to_shared(dst);
  int sz = pred ? 16 : 0;
  asm volatile("cp.async.cg.shared.global [%0], [%1], 16, %2;\n" :: "r"(d), "l"(src), "r"(sz));
}
__device__ __forceinline__ unsigned fenc(float f) {
  unsigned u = __float_as_uint(f);
  return (u & 0x80000000u) ? ~u : (u | 0x80000000u);
}
__device__ __forceinline__ float fdec(unsigned e) {
  return (e & 0x80000000u) ? __uint_as_float(e & 0x7fffffffu) : __uint_as_float(~e);
}
__device__ __forceinline__ int find_seg(int v) {
  int lo = 0, hi = NG;
  while (lo < hi) { int mid = (lo + hi) >> 1; if (g_cum[mid] > v) hi = mid; else lo = mid + 1; }
  return lo;
}
__device__ __forceinline__ float gru1(float xz, float xr, float xh,
                                      float hz, float hr, float hh, float h) {
  float z = 1.f / (1.f + expf(-(xz + hz)));
  float r = 1.f / (1.f + expf(-(xr + hr)));
  float c = tanhf(xh + r * hh);
  return z * h + (1.f - z) * c;
}

__global__ void k_h_init(const int* __restrict__ nodes, const float* __restrict__ embed) {
  int idx = blockIdx.x * blockDim.x + threadIdx.x;
  if (idx >= NN * HD) return;
  int v = idx >> 8, j = idx & 255;
  int tok = __ldg(&nodes[v]);
  int pos = __ldg(&nodes[NN + v]);
  int p = pos < 512 ? pos : 512;
  float pe = 0.f;
  if (p > 0) {
    float ang = (float)(p - 1) * exp2f(-(float)j * 0.10381025296523f);
    pe = (j & 1) ? cosf(ang) : sinf(ang);
  }
  g_htf[idx] = to_tf32(__ldg(&embed[(size_t)tok * HD + j]) + pe);
}

__global__ void k_round_w(const float* __restrict__ tw, const float* __restrict__ gW,
                          const float* __restrict__ gU) {
  int i = blockIdx.x * blockDim.x + threadIdx.x;
  if (i < 2 * NT * HD * HD) g_twr[i] = to_tf32(__ldg(&tw[i]));
  if (i < 2 * HD * 3 * HD) {
    g_gWr[i] = to_tf32(__ldg(&gW[i]));
    g_gUr[i] = to_tf32(__ldg(&gU[i]));
  }
}

__global__ void k_init_misc(const int* __restrict__ sizes, float* __restrict__ out) {
  int i = blockIdx.x * blockDim.x + threadIdx.x;
  if (i < NN) g_deg[i] = 0;
  if (blockIdx.x == 0) {
    int t = threadIdx.x;
    if (t < NG) g_sums[t] = 0.f;
    if (t < 2 * NG) out[t] = 0.f;
    if (t == 0) {
      g_gmax = 0u;
      int s = 0;
      for (int g = 0; g < NG; g++) { s += sizes[g]; g_cum[g] = s; }
    }
  }
}

__global__ void k_count(const int* __restrict__ edges) {
  int i = blockIdx.x * blockDim.x + threadIdx.x;
  if (i < NE) atomicAdd(&g_deg[edges[3 * i + 2]], 1);
}

__global__ void k_scan() {
  __shared__ int sCarry;
  __shared__ int warpTot[32];
  int tid = threadIdx.x;
  int lane = tid & 31, wid = tid >> 5;
  if (tid == 0) sCarry = 0;
  __syncthreads();
  for (int base = 0; base < NN; base += 1024) {
    int i = base + tid;
    int v = (i < NN) ? g_deg[i] : 0;
    int x = v;
#pragma unroll
    for (int off = 1; off < 32; off <<= 1) {
      int y = __shfl_up_sync(~0u, x, off);
      if (lane >= off) x += y;
    }
    if (lane == 31) warpTot[wid] = x;
    __syncthreads();
    if (wid == 0) {
      int w = warpTot[lane];
#pragma unroll
      for (int off = 1; off < 32; off <<= 1) {
        int y = __shfl_up_sync(~0u, w, off);
        if (lane >= off) w += y;
      }
      warpTot[lane] = w;
    }
    __syncthreads();
    int warpPrefix = (wid > 0) ? warpTot[wid - 1] : 0;
    int incl = x + warpPrefix;
    int excl = incl - v;
    int carry = sCarry;
    if (i < NN) { g_rowoff[i] = carry + excl; g_cursor[i] = carry + excl; }
    __syncthreads();
    if (tid == 1023) sCarry = carry + incl;
    __syncthreads();
  }
  if (tid == 0) g_rowoff[NN] = sCarry;
}

__global__ void k_fill(const int* __restrict__ edges) {
  int i = blockIdx.x * blockDim.x + threadIdx.x;
  if (i >= NE) return;
  int et = edges[3 * i], src = edges[3 * i + 1], tgt = edges[3 * i + 2];
  int p = atomicAdd(&g_cursor[tgt], 1);
  g_csr[p] = (src << 2) | et;
}

// C[M, gridX*128] = A[M,256] @ B (+bias); inputs pre-rounded to tf32.
// N-tile = blockIdx.x (fastest; A row-slab stays L2-resident),
// M-tile = blockIdx.y. 2-stage cp.async pipeline, BK=32; 2 CTAs/SM.
__global__ __launch_bounds__(256, 2)
void k_gemm(const float* __restrict__ A, int M,
            const float* __restrict__ B, int ldb, int nblk, long nblkStride,
            const float* __restrict__ bias, int biasBlkStride,
            float* __restrict__ C, int ldc) {
  extern __shared__ float sm[];
  float* As = sm;               // [2][128][36]
  float* Bs = sm + 2 * ASTG;    // [2][32][136]
  int m0 = blockIdx.y * 128;
  int n0 = blockIdx.x * 128;
  int tB = n0 / nblk;
  int nb0 = n0 - tB * nblk;
  const float* Bblk = B + (size_t)tB * nblkStride + nb0;
  int tid = threadIdx.x, lane = tid & 31, warp = tid >> 5;
  int wm = (warp & 3) * 32, wn = (warp >> 2) * 64;
  int ar = tid >> 3, ac = (tid & 7) * 4;
  int br = tid >> 5, bc = (tid & 31) * 4;
  const float* Arow = A + (size_t)(m0 + ar) * HD;  // base; p offsets constant

  float acc[2][8][4];
#pragma unroll
  for (int i = 0; i < 2; i++)
#pragma unroll
    for (int j = 0; j < 8; j++)
#pragma unroll
      for (int k = 0; k < 4; k++) acc[i][j][k] = 0.f;

#pragma unroll
  for (int p = 0; p < 4; p++)
    cpa16(&As[(ar + p * 32) * ASTRIDE + ac], Arow + (size_t)p * 32 * HD + ac,
          (m0 + ar + p * 32) < M);
#pragma unroll
  for (int p = 0; p < 4; p++)
    cpa16(&Bs[(br + p * 8) * BSTRIDE + bc], Bblk + (size_t)(br + p * 8) * ldb + bc, true);
  asm volatile("cp.async.commit_group;\n");

#pragma unroll
  for (int kt = 0; kt < 8; kt++) {
    int s = kt & 1;
    if (kt < 7) {
      int s2 = (kt + 1) & 1;
      int k0 = (kt + 1) * 32;
#pragma unroll
      for (int p = 0; p < 4; p++)
        cpa16(&As[s2 * ASTG + (ar + p * 32) * ASTRIDE + ac],
              Arow + (size_t)p * 32 * HD + k0 + ac, (m0 + ar + p * 32) < M);
#pragma unroll
      for (int p = 0; p < 4; p++)
        cpa16(&Bs[s2 * BSTG + (br + p * 8) * BSTRIDE + bc],
              Bblk + (size_t)(k0 + br + p * 8) * ldb + bc, true);
      asm volatile("cp.async.commit_group;\n");
      asm volatile("cp.async.wait_group 1;\n");
    } else {
      asm volatile("cp.async.wait_group 0;\n");
    }
    __syncthreads();
    const float* Asb = As + s * ASTG;
    const float* Bsb = Bs + s * BSTG;
#pragma unroll
    for (int ks = 0; ks < 4; ks++) {
      int kk = ks * 8;
      unsigned af[2][4], bf[8][2];
#pragma unroll
      for (int mt = 0; mt < 2; mt++) {
        int r = wm + mt * 16 + (lane >> 2);
        int cA = kk + (lane & 3);
        af[mt][0] = __float_as_uint(Asb[r * ASTRIDE + cA]);
        af[mt][1] = __float_as_uint(Asb[(r + 8) * ASTRIDE + cA]);
        af[mt][2] = __float_as_uint(Asb[r * ASTRIDE + cA + 4]);
        af[mt][3] = __float_as_uint(Asb[(r + 8) * ASTRIDE + cA + 4]);
      }
#pragma unroll
      for (int nt = 0; nt < 8; nt++) {
        int cN = wn + nt * 8 + (lane >> 2);
        int rB = kk + (lane & 3);
        bf[nt][0] = __float_as_uint(Bsb[rB * BSTRIDE + cN]);
        bf[nt][1] = __float_as_uint(Bsb[(rB + 4) * BSTRIDE + cN]);
      }
#pragma unroll
      for (int mt = 0; mt < 2; mt++)
#pragma unroll
        for (int nt = 0; nt < 8; nt++) mma_tf32(acc[mt][nt], af[mt], bf[nt]);
    }
    __syncthreads();
  }

#pragma unroll
  for (int mt = 0; mt < 2; mt++) {
    int r0 = m0 + wm + mt * 16 + (lane >> 2);
#pragma unroll
    for (int nt = 0; nt < 8; nt++) {
      int cc = wn + nt * 8 + 2 * (lane & 3);
      float b0 = __ldg(&bias[(size_t)tB * biasBlkStride + nb0 + cc]);
      float b1 = __ldg(&bias[(size_t)tB * biasBlkStride + nb0 + cc + 1]);
      int gn = n0 + cc;
      if (r0 < M) {
        C[(size_t)r0 * ldc + gn] = acc[mt][nt][0] + b0;
        C[(size_t)r0 * ldc + gn + 1] = acc[mt][nt][1] + b1;
      }
      if (r0 + 8 < M) {
        C[(size_t)(r0 + 8) * ldc + gn] = acc[mt][nt][2] + b0;
        C[(size_t)(r0 + 8) * ldc + gn + 1] = acc[mt][nt][3] + b1;
      }
    }
  }
}

__global__ void k_msgs() {
  int gw = (blockIdx.x * blockDim.x + threadIdx.x) >> 5;
  int lane = threadIdx.x & 31;
  if (gw >= NN) return;
  int beg = g_rowoff[gw], end = g_rowoff[gw + 1];
  float4 a0 = make_float4(0.f, 0.f, 0.f, 0.f);
  float4 a1 = make_float4(0.f, 0.f, 0.f, 0.f);
  int i = beg;
  for (; i + 1 < end; i += 2) {
    int e0 = __ldg(&g_csr[i]), e1 = __ldg(&g_csr[i + 1]);
    const float4* p0 = (const float4*)(g_trans +
        ((size_t)(e0 >> 2) * (NT * HD) + (size_t)(e0 & 3) * HD));
    const float4* p1 = (const float4*)(g_trans +
        ((size_t)(e1 >> 2) * (NT * HD) + (size_t)(e1 & 3) * HD));
    float4 x0 = __ldg(p0 + lane), x1 = __ldg(p0 + lane + 32);
    float4 y0 = __ldg(p1 + lane), y1 = __ldg(p1 + lane + 32);
    a0.x += x0.x + y0.x; a0.y += x0.y + y0.y; a0.z += x0.z + y0.z; a0.w += x0.w + y0.w;
    a1.x += x1.x + y1.x; a1.y += x1.y + y1.y; a1.z += x1.z + y1.z; a1.w += x1.w + y1.w;
  }
  if (i < end) {
    int e0 = __ldg(&g_csr[i]);
    const float4* p0 = (const float4*)(g_trans +
        ((size_t)(e0 >> 2) * (NT * HD) + (size_t)(e0 & 3) * HD));
    float4 x0 = __ldg(p0 + lane), x1 = __ldg(p0 + lane + 32);
    a0.x += x0.x; a0.y += x0.y; a0.z += x0.z; a0.w += x0.w;
    a1.x += x1.x; a1.y += x1.y; a1.z += x1.z; a1.w += x1.w;
  }
  a0.x = to_tf32(a0.x); a0.y = to_tf32(a0.y); a0.z = to_tf32(a0.z); a0.w = to_tf32(a0.w);
  a1.x = to_tf32(a1.x); a1.y = to_tf32(a1.y); a1.z = to_tf32(a1.z); a1.w = to_tf32(a1.w);
  float4* o = (float4*)(g_msgs + (size_t)gw * HD);
  o[lane] = a0;
  o[lane + 32] = a1;
}

__global__ void k_gru() {
  int idx = blockIdx.x * blockDim.x + threadIdx.x;
  if (idx >= NN * 64) return;
  int v = idx >> 6, q = idx & 63;
  const float4* px = (const float4*)(g_gx + (size_t)v * 768);
  const float4* ph = (const float4*)(g_gh + (size_t)v * 768);
  float4 xz = px[q], xr = px[q + 64], xh = px[q + 128];
  float4 hz = ph[q], hr = ph[q + 64], hh = ph[q + 128];
  float4 hv = ((const float4*)g_htf)[idx];
  float4 r;
  r.x = to_tf32(gru1(xz.x, xr.x, xh.x, hz.x, hr.x, hh.x, hv.x));
  r.y = to_tf32(gru1(xz.y, xr.y, xh.y, hz.y, hr.y, hh.y, hv.y));
  r.z = to_tf32(gru1(xz.z, xr.z, xh.z, hz.z, hr.z, hh.z, hv.z));
  r.w = to_tf32(gru1(xz.w, xr.w, xh.w, hz.w, hr.w, hh.w, hv.w));
  ((float4*)g_htf)[idx] = r;
}

__global__ void k_readout1(const float* __restrict__ gateW, const float* __restrict__ gateB,
                           const float* __restrict__ outW, const float* __restrict__ outB) {
  int warp = threadIdx.x >> 5, lane = threadIdx.x & 31;
  int v = blockIdx.x * 8 + warp;
  float g = 0.f, o0 = 0.f, o1 = 0.f;
  if (v < NN) {
    const float* hv = g_htf + (size_t)v * HD;
#pragma unroll 4
    for (int j = lane; j < HD; j += 32) {
      float x = hv[j];
      g += x * __ldg(&gateW[j]);
      float2 w = __ldg((const float2*)outW + j);
      o0 += x * w.x;
      o1 += x * w.y;
    }
  }
#pragma unroll
  for (int off = 16; off; off >>= 1) {
    g += __shfl_xor_sync(~0u, g, off);
    o0 += __shfl_xor_sync(~0u, o0, off);
    o1 += __shfl_xor_sync(~0u, o1, off);
  }
  float gl = g + __ldg(gateB);
  if (v < NN && lane == 0) {
    g_gate[v] = gl;
    g_outs[2 * v] = o0 + __ldg(&outB[0]);
    g_outs[2 * v + 1] = o1 + __ldg(&outB[1]);
  }
  __shared__ float smax[8];
  if (lane == 0) smax[warp] = (v < NN) ? gl : -3.4e38f;
  __syncthreads();
  if (threadIdx.x == 0) {
    float m = smax[0];
#pragma unroll
    for (int i = 1; i < 8; i++) m = fmaxf(m, smax[i]);
    atomicMax(&g_gmax, fenc(m));
  }
}

__global__ void k_readout2() {
  int v = blockIdx.x * blockDim.x + threadIdx.x;
  __shared__ float part[4];
  __shared__ int s0;
  if (threadIdx.x < 4) part[threadIdx.x] = 0.f;
  if (threadIdx.x == 0) s0 = find_seg(blockIdx.x * blockDim.x);
  __syncthreads();
  if (v < NN) {
    float e = expf(g_gate[v] - fdec(g_gmax));
    g_gate[v] = e;
    int s = find_seg(v);
    atomicAdd(&part[s - s0], e);
  }
  __syncthreads();
  if (threadIdx.x < 4 && part[threadIdx.x] != 0.f)
    atomicAdd(&g_sums[s0 + threadIdx.x], part[threadIdx.x]);
}

__global__ void k_readout3(float* __restrict__ out) {
  int v = blockIdx.x * blockDim.x + threadIdx.x;
  __shared__ float p0[4], p1[4];
  __shared__ int s0;
  if (threadIdx.x < 4) { p0[threadIdx.x] = 0.f; p1[threadIdx.x] = 0.f; }
  if (threadIdx.x == 0) s0 = find_seg(blockIdx.x * blockDim.x);
  __syncthreads();
  if (v < NN) {
    int s = find_seg(v);
    float w = g_gate[v] / (g_sums[s] + 1e-16f);
    atomicAdd(&p0[s - s0], g_outs[2 * v] * w);
    atomicAdd(&p1[s - s0], g_outs[2 * v + 1] * w);
  }
  __syncthreads();
  if (threadIdx.x < 4) {
    int s = s0 + threadIdx.x;
    if (s < NG && (p0[threadIdx.x] != 0.f || p1[threadIdx.x] != 0.f)) {
      atomicAdd(&out[2 * s], p0[threadIdx.x]);
      atomicAdd(&out[2 * s + 1], p1[threadIdx.x]);
    }
  }
}

extern "C" void kernel_launch(void* const* d_in, const int* in_sizes, int n_in,
                              void* d_out, int out_size) {
  const int* nodes = (const int*)d_in[0];
  const int* gsizes = (const int*)d_in[1];
  const int* edges = (const int*)d_in[2];
  const float* embed = (const float*)d_in[3];
  const float* tw = (const float*)d_in[4];
  const float* tb = (const float*)d_in[5];
  const float* gW = (const float*)d_in[6];
  const float* gU = (const float*)d_in[7];
  const float* gbi = (const float*)d_in[8];
  const float* gbr = (const float*)d_in[9];
  const float* gateW = (const float*)d_in[10];
  const float* gateB = (const float*)d_in[11];
  const float* outW = (const float*)d_in[12];
  const float* outB = (const float*)d_in[13];
  float* out = (float*)d_out;

  cudaFuncSetAttribute(k_gemm, cudaFuncAttributeMaxDynamicSharedMemorySize, GEMM_SMEM);

  float* htf;   cudaGetSymbolAddress((void**)&htf, g_htf);
  float* trptr; cudaGetSymbolAddress((void**)&trptr, g_trans);
  float* msptr; cudaGetSymbolAddress((void**)&msptr, g_msgs);
  float* gxptr; cudaGetSymbolAddress((void**)&gxptr, g_gx);
  float* ghptr; cudaGetSymbolAddress((void**)&ghptr, g_gh);
  float* twr;   cudaGetSymbolAddress((void**)&twr, g_twr);
  float* gWr;   cudaGetSymbolAddress((void**)&gWr, g_gWr);
  float* gUr;   cudaGetSymbolAddress((void**)&gUr, g_gUr);

  const int steps[2] = {3, 1};
  dim3 gT(8, (NN + 127) / 128);
  dim3 gG(6, (NN + 127) / 128);

  // launches 0-2: prerequisites for the first trans GEMM
  k_h_init<<<(NN * HD + 255) / 256, 256>>>(nodes, embed);
  k_round_w<<<(2 * NT * HD * HD + 255) / 256, 256>>>(tw, gW, gU);
  k_init_misc<<<(NN + 255) / 256, 256>>>(gsizes, out);
  // launch 3: first trans GEMM (profiled slot)
  k_gemm<<<gT, 256, GEMM_SMEM>>>(htf, NN, twr, HD, HD, (long)HD * HD, tb, HD, trptr, NT * HD);
  // CSR build (needed before first k_msgs)
  k_count<<<(NE + 255) / 256, 256>>>(edges);
  k_scan<<<1, 1024>>>();
  k_fill<<<(NE + 255) / 256, 256>>>(edges);

  for (int l = 0; l < 2; l++) {
    const float* Wt = twr + (size_t)l * NT * HD * HD;
    const float* bt = tb + (size_t)l * NT * HD;
    const float* Wx = gWr + (size_t)l * HD * 768;
    const float* Uh = gUr + (size_t)l * HD * 768;
    const float* bi = gbi + (size_t)l * 768;
    const float* br = gbr + (size_t)l * 768;
    for (int s = 0; s < steps[l]; s++) {
      if (l != 0 || s != 0)
        k_gemm<<<gT, 256, GEMM_SMEM>>>(htf, NN, Wt, HD, HD, (long)HD * HD, bt, HD, trptr, NT * HD);
      k_msgs<<<(NN * 32 + 255) / 256, 256>>>();
      k_gemm<<<gG, 256, GEMM_SMEM>>>(msptr, NN, Wx, 768, 768, 0, bi, 0, gxptr, 768);
      k_gemm<<<gG, 256, GEMM_SMEM>>>(htf, NN, Uh, 768, 768, 0, br, 0, ghptr, 768);
      k_gru<<<(NN * 64 + 255) / 256, 256>>>();
    }
  }
  k_readout1<<<(NN + 7) / 8, 256>>>(gateW, gateB, outW, outB);
  k_readout2<<<(NN + 255) / 256, 256>>>();
  k_readout3<<<(NN + 255) / 256, 256>>>(out);
}

// round 9
// speedup vs baseline: 2.3823x; 1.5223x over previous
#include <cuda_runtime.h>
#include <cuda_fp16.h>
#include <cstdint>
#include <math.h>

#define NN 100000
#define NG 100
#define NE 1000000
#define HD 256
#define NT 4

// fp16 GEMM smem (bytes):
// [0, 40960)        : 2 stages x (A 10240 + B 10240)   (tiles 128x32 halves, pad 40)
// [40960, 108544)   : epilogue stage: 8 warps x 32x66 floats
// [108544, 109056)  : bias tile (128 floats)
#define ABPAD 40
#define TG_SMEM 109056

__device__ __half g_h16[(size_t)NN * HD];
__device__ __half g_trans16[(size_t)NN * NT * HD];
__device__ __half g_msgs16[(size_t)NN * HD];
__device__ float g_gx[(size_t)NN * 3 * HD];
__device__ float g_gh[(size_t)NN * 3 * HD];
__device__ __half g_tw16[2 * NT * HD * HD];   // [l][t][n][k]
__device__ __half g_gW16[2 * 3 * HD * HD];    // [l][n=768][k=256]
__device__ __half g_gU16[2 * 3 * HD * HD];
__device__ float g_gate[NN];
__device__ float g_outs[2 * NN];
__device__ float g_sums[NG];
__device__ unsigned g_gmax;
__device__ int g_deg[NN];
__device__ int g_rowoff[NN + 1];
__device__ int g_cursor[NN];
__device__ int g_csr[NE];
__device__ int g_cum[NG];

__device__ __forceinline__ void mma16(float* d, const unsigned* a, const unsigned* b) {
  asm volatile(
      "mma.sync.aligned.m16n8k16.row.col.f32.f16.f16.f32 "
      "{%0,%1,%2,%3}, {%4,%5,%6,%7}, {%8,%9}, {%0,%1,%2,%3};\n"
      : "+f"(d[0]), "+f"(d[1]), "+f"(d[2]), "+f"(d[3])
      : "r"(a[0]), "r"(a[1]), "r"(a[2]), "r"(a[3]), "r"(b[0]), "r"(b[1]));
}
__device__ __forceinline__ void cpa16s(uint32_t daddr, const void* src, bool pred) {
  int sz = pred ? 16 : 0;
  asm volatile("cp.async.cg.shared.global [%0], [%1], 16, %2;\n" :: "r"(daddr), "l"(src), "r"(sz));
}
__device__ __forceinline__ unsigned fenc(float f) {
  unsigned u = __float_as_uint(f);
  return (u & 0x80000000u) ? ~u : (u | 0x80000000u);
}
__device__ __forceinline__ float fdec(unsigned e) {
  return (e & 0x80000000u) ? __uint_as_float(e & 0x7fffffffu) : __uint_as_float(~e);
}
__device__ __forceinline__ int find_seg(int v) {
  int lo = 0, hi = NG;
  while (lo < hi) { int mid = (lo + hi) >> 1; if (g_cum[mid] > v) hi = mid; else lo = mid + 1; }
  return lo;
}
__device__ __forceinline__ float gru1(float xz, float xr, float xh,
                                      float hz, float hr, float hh, float h) {
  float z = 1.f / (1.f + expf(-(xz + hz)));
  float r = 1.f / (1.f + expf(-(xr + hr)));
  float c = tanhf(xh + r * hh);
  return z * h + (1.f - z) * c;
}

__global__ void k_h_init(const int* __restrict__ nodes, const float* __restrict__ embed) {
  int idx = blockIdx.x * blockDim.x + threadIdx.x;
  if (idx >= NN * HD) return;
  int v = idx >> 8, j = idx & 255;
  int tok = __ldg(&nodes[v]);
  int pos = __ldg(&nodes[NN + v]);
  int p = pos < 512 ? pos : 512;
  float pe = 0.f;
  if (p > 0) {
    float ang = (float)(p - 1) * exp2f(-(float)j * 0.10381025296523f);
    pe = (j & 1) ? cosf(ang) : sinf(ang);
  }
  g_h16[idx] = __float2half(__ldg(&embed[(size_t)tok * HD + j]) + pe);
}

// transpose weights to [n][k] fp16
__global__ void k_round_w(const float* __restrict__ tw, const float* __restrict__ gW,
                          const float* __restrict__ gU) {
  int i = blockIdx.x * blockDim.x + threadIdx.x;
  if (i < 2 * NT * HD * HD) {
    int lt = i >> 16, n = (i >> 8) & 255, k = i & 255;
    g_tw16[i] = __float2half(__ldg(&tw[(lt << 16) + (k << 8) + n]));
  }
  if (i < 2 * 3 * HD * HD) {
    int l = i / 196608;
    int rem = i - l * 196608;
    int n = rem >> 8, k = rem & 255;
    g_gW16[i] = __float2half(__ldg(&gW[l * 196608 + k * 768 + n]));
    g_gU16[i] = __float2half(__ldg(&gU[l * 196608 + k * 768 + n]));
  }
}

__global__ void k_init_misc(const int* __restrict__ sizes, float* __restrict__ out) {
  int i = blockIdx.x * blockDim.x + threadIdx.x;
  if (i < NN) g_deg[i] = 0;
  if (blockIdx.x == 0) {
    int t = threadIdx.x;
    if (t < NG) g_sums[t] = 0.f;
    if (t < 2 * NG) out[t] = 0.f;
    if (t == 0) {
      g_gmax = 0u;
      int s = 0;
      for (int g = 0; g < NG; g++) { s += sizes[g]; g_cum[g] = s; }
    }
  }
}

__global__ void k_count(const int* __restrict__ edges) {
  int i = blockIdx.x * blockDim.x + threadIdx.x;
  if (i < NE) atomicAdd(&g_deg[edges[3 * i + 2]], 1);
}

__global__ void k_scan() {
  __shared__ int sCarry;
  __shared__ int warpTot[32];
  int tid = threadIdx.x;
  int lane = tid & 31, wid = tid >> 5;
  if (tid == 0) sCarry = 0;
  __syncthreads();
  for (int base = 0; base < NN; base += 1024) {
    int i = base + tid;
    int v = (i < NN) ? g_deg[i] : 0;
    int x = v;
#pragma unroll
    for (int off = 1; off < 32; off <<= 1) {
      int y = __shfl_up_sync(~0u, x, off);
      if (lane >= off) x += y;
    }
    if (lane == 31) warpTot[wid] = x;
    __syncthreads();
    if (wid == 0) {
      int w = warpTot[lane];
#pragma unroll
      for (int off = 1; off < 32; off <<= 1) {
        int y = __shfl_up_sync(~0u, w, off);
        if (lane >= off) w += y;
      }
      warpTot[lane] = w;
    }
    __syncthreads();
    int warpPrefix = (wid > 0) ? warpTot[wid - 1] : 0;
    int incl = x + warpPrefix;
    int excl = incl - v;
    int carry = sCarry;
    if (i < NN) { g_rowoff[i] = carry + excl; g_cursor[i] = carry + excl; }
    __syncthreads();
    if (tid == 1023) sCarry = carry + incl;
    __syncthreads();
  }
  if (tid == 0) g_rowoff[NN] = sCarry;
}

__global__ void k_fill(const int* __restrict__ edges) {
  int i = blockIdx.x * blockDim.x + threadIdx.x;
  if (i >= NE) return;
  int et = edges[3 * i], src = edges[3 * i + 1], tgt = edges[3 * i + 2];
  int p = atomicAdd(&g_cursor[tgt], 1);
  g_csr[p] = (src << 2) | et;
}

// C[M, gridX*128] = A[M,256] @ B^T (+bias). A fp16 [m][k], B fp16 [n][k].
// 128x128 tile, BK=32, 2-stage cp.async, 2 CTAs/SM.
__global__ __launch_bounds__(256, 2)
void k_g16(const __half* __restrict__ A, int M, const __half* __restrict__ B,
           int nblk, long nblkStride, const float* __restrict__ bias, int biasBlkStride,
           void* __restrict__ Cv, int ldc, int outHalf) {
  extern __shared__ __half sh[];
  uint32_t sbase;
  asm("{ .reg .u64 t; cvta.to.shared.u64 t, %1; cvt.u32.u64 %0, t; }" : "=r"(sbase) : "l"(sh));
  int tid = threadIdx.x, lane = tid & 31, wid = tid >> 5;
  int n0 = blockIdx.x * 128, m0 = blockIdx.y * 128;
  int tB = n0 / nblk, nb0 = n0 - tB * nblk;
  const __half* Bblk = B + (size_t)tB * nblkStride + (size_t)nb0 * HD;
  float* biasS = (float*)((char*)sh + 108544);
  if (tid < 128) biasS[tid] = __ldg(&bias[(size_t)tB * biasBlkStride + nb0 + tid]);

  int lrow = tid >> 2, lseg = tid & 3;  // loader: thread covers rows {lrow, lrow+64}, 16B seg
  int wm = (wid & 3) * 32, wn = (wid >> 2) * 64;
  int g = lane >> 2, t2 = (lane & 3) * 2;

  float acc[2][8][4];
#pragma unroll
  for (int i = 0; i < 2; i++)
#pragma unroll
    for (int j = 0; j < 8; j++)
#pragma unroll
      for (int k = 0; k < 4; k++) acc[i][j][k] = 0.f;

  // prologue: slab 0 -> buf 0
  {
    uint32_t ab = sbase, bb = sbase + 10240;
#pragma unroll
    for (int it = 0; it < 2; it++) {
      int row = lrow + it * 64;
      uint32_t off = (uint32_t)(row * (ABPAD * 2) + lseg * 16);
      cpa16s(ab + off, A + (size_t)(m0 + row) * HD + lseg * 8, (m0 + row) < M);
      cpa16s(bb + off, Bblk + (size_t)row * HD + lseg * 8, true);
    }
    asm volatile("cp.async.commit_group;\n");
  }

#pragma unroll
  for (int kt = 0; kt < 8; kt++) {
    int s = kt & 1;
    if (kt < 7) {
      int s2 = (kt + 1) & 1;
      int k0 = (kt + 1) * 32;
      uint32_t ab = sbase + s2 * 20480, bb = ab + 10240;
#pragma unroll
      for (int it = 0; it < 2; it++) {
        int row = lrow + it * 64;
        uint32_t off = (uint32_t)(row * (ABPAD * 2) + lseg * 16);
        cpa16s(ab + off, A + (size_t)(m0 + row) * HD + k0 + lseg * 8, (m0 + row) < M);
        cpa16s(bb + off, Bblk + (size_t)row * HD + k0 + lseg * 8, true);
      }
      asm volatile("cp.async.commit_group;\n");
      asm volatile("cp.async.wait_group 1;\n");
    } else {
      asm volatile("cp.async.wait_group 0;\n");
    }
    __syncthreads();
    const __half* Asb = sh + s * 10240;
    const __half* Bsb = Asb + 5120;
#pragma unroll
    for (int ks = 0; ks < 2; ks++) {
      int kk = ks * 16;
      unsigned af[2][4], bf[8][2];
#pragma unroll
      for (int mt = 0; mt < 2; mt++) {
        const __half* base = Asb + (wm + mt * 16 + g) * ABPAD + kk + t2;
        af[mt][0] = *(const unsigned*)(base);
        af[mt][1] = *(const unsigned*)(base + 8 * ABPAD);
        af[mt][2] = *(const unsigned*)(base + 8);
        af[mt][3] = *(const unsigned*)(base + 8 * ABPAD + 8);
      }
#pragma unroll
      for (int nt = 0; nt < 8; nt++) {
        const __half* bb = Bsb + (wn + nt * 8 + g) * ABPAD + kk + t2;
        bf[nt][0] = *(const unsigned*)(bb);
        bf[nt][1] = *(const unsigned*)(bb + 8);
      }
#pragma unroll
      for (int mt = 0; mt < 2; mt++)
#pragma unroll
        for (int nt = 0; nt < 8; nt++) mma16(acc[mt][nt], af[mt], bf[nt]);
    }
    __syncthreads();
  }

  // epilogue: per-warp 32x66 fp32 stage, transposed coalesced store
  float* ep = (float*)((char*)sh + 40960) + wid * 2112;
#pragma unroll
  for (int mt = 0; mt < 2; mt++)
#pragma unroll
    for (int nt = 0; nt < 8; nt++) {
      int lc = nt * 8 + t2;
      float b0 = biasS[wn + lc], b1 = biasS[wn + lc + 1];
      int r0 = mt * 16 + g;
      ep[r0 * 66 + lc] = acc[mt][nt][0] + b0;
      ep[r0 * 66 + lc + 1] = acc[mt][nt][1] + b1;
      ep[(r0 + 8) * 66 + lc] = acc[mt][nt][2] + b0;
      ep[(r0 + 8) * 66 + lc + 1] = acc[mt][nt][3] + b1;
    }
  __syncwarp();
  int colg = n0 + wn + 2 * lane;
#pragma unroll 4
  for (int rr = 0; rr < 32; rr++) {
    int gr = m0 + wm + rr;
    if (gr < M) {
      float2 v = *(float2*)&ep[rr * 66 + 2 * lane];
      if (outHalf) {
        *(__half2*)((__half*)Cv + (size_t)gr * ldc + colg) = __floats2half2_rn(v.x, v.y);
      } else {
        *(float2*)((float*)Cv + (size_t)gr * ldc + colg) = v;
      }
    }
  }
}

__global__ void k_msgs() {
  int gw = (blockIdx.x * blockDim.x + threadIdx.x) >> 5;
  int lane = threadIdx.x & 31;
  if (gw >= NN) return;
  int beg = g_rowoff[gw], end = g_rowoff[gw + 1];
  float a[8] = {0.f, 0.f, 0.f, 0.f, 0.f, 0.f, 0.f, 0.f};
  int i = beg;
  for (; i + 1 < end; i += 2) {
    int e0 = __ldg(&g_csr[i]), e1 = __ldg(&g_csr[i + 1]);
    const uint4* p0 = (const uint4*)(g_trans16 + ((size_t)(e0 >> 2) * (NT * HD) + (size_t)(e0 & 3) * HD));
    const uint4* p1 = (const uint4*)(g_trans16 + ((size_t)(e1 >> 2) * (NT * HD) + (size_t)(e1 & 3) * HD));
    uint4 x = __ldg(p0 + lane), y = __ldg(p1 + lane);
    const __half2* hx = (const __half2*)&x;
    const __half2* hy = (const __half2*)&y;
#pragma unroll
    for (int q = 0; q < 4; q++) {
      float2 fx = __half22float2(hx[q]), fy = __half22float2(hy[q]);
      a[2 * q] += fx.x + fy.x;
      a[2 * q + 1] += fx.y + fy.y;
    }
  }
  if (i < end) {
    int e0 = __ldg(&g_csr[i]);
    const uint4* p0 = (const uint4*)(g_trans16 + ((size_t)(e0 >> 2) * (NT * HD) + (size_t)(e0 & 3) * HD));
    uint4 x = __ldg(p0 + lane);
    const __half2* hx = (const __half2*)&x;
#pragma unroll
    for (int q = 0; q < 4; q++) {
      float2 fx = __half22float2(hx[q]);
      a[2 * q] += fx.x;
      a[2 * q + 1] += fx.y;
    }
  }
  uint4 o;
  __half2* ho = (__half2*)&o;
#pragma unroll
  for (int q = 0; q < 4; q++) ho[q] = __floats2half2_rn(a[2 * q], a[2 * q + 1]);
  ((uint4*)(g_msgs16 + (size_t)gw * HD))[lane] = o;
}

__global__ void k_gru() {
  int idx = blockIdx.x * blockDim.x + threadIdx.x;
  if (idx >= NN * 64) return;
  int v = idx >> 6, q = idx & 63;
  const float4* px = (const float4*)(g_gx + (size_t)v * 768);
  const float4* ph = (const float4*)(g_gh + (size_t)v * 768);
  float4 xz = px[q], xr = px[q + 64], xh = px[q + 128];
  float4 hz = ph[q], hr = ph[q + 64], hh = ph[q + 128];
  uint2 hraw = ((const uint2*)g_h16)[idx];
  float2 h01 = __half22float2(*(__half2*)&hraw.x);
  float2 h23 = __half22float2(*(__half2*)&hraw.y);
  float r0 = gru1(xz.x, xr.x, xh.x, hz.x, hr.x, hh.x, h01.x);
  float r1 = gru1(xz.y, xr.y, xh.y, hz.y, hr.y, hh.y, h01.y);
  float r2 = gru1(xz.z, xr.z, xh.z, hz.z, hr.z, hh.z, h23.x);
  float r3 = gru1(xz.w, xr.w, xh.w, hz.w, hr.w, hh.w, h23.y);
  uint2 o;
  *(__half2*)&o.x = __floats2half2_rn(r0, r1);
  *(__half2*)&o.y = __floats2half2_rn(r2, r3);
  ((uint2*)g_h16)[idx] = o;
}

__global__ void k_readout1(const float* __restrict__ gateW, const float* __restrict__ gateB,
                           const float* __restrict__ outW, const float* __restrict__ outB) {
  int warp = threadIdx.x >> 5, lane = threadIdx.x & 31;
  int v = blockIdx.x * 8 + warp;
  float g = 0.f, o0 = 0.f, o1 = 0.f;
  if (v < NN) {
    const __half* hv = g_h16 + (size_t)v * HD;
#pragma unroll 4
    for (int j = lane; j < HD; j += 32) {
      float x = __half2float(__ldg(&hv[j]));
      g += x * __ldg(&gateW[j]);
      float2 w = __ldg((const float2*)outW + j);
      o0 += x * w.x;
      o1 += x * w.y;
    }
  }
#pragma unroll
  for (int off = 16; off; off >>= 1) {
    g += __shfl_xor_sync(~0u, g, off);
    o0 += __shfl_xor_sync(~0u, o0, off);
    o1 += __shfl_xor_sync(~0u, o1, off);
  }
  float gl = g + __ldg(gateB);
  if (v < NN && lane == 0) {
    g_gate[v] = gl;
    g_outs[2 * v] = o0 + __ldg(&outB[0]);
    g_outs[2 * v + 1] = o1 + __ldg(&outB[1]);
  }
  __shared__ float smax[8];
  if (lane == 0) smax[warp] = (v < NN) ? gl : -3.4e38f;
  __syncthreads();
  if (threadIdx.x == 0) {
    float m = smax[0];
#pragma unroll
    for (int i = 1; i < 8; i++) m = fmaxf(m, smax[i]);
    atomicMax(&g_gmax, fenc(m));
  }
}

__global__ void k_readout2() {
  int v = blockIdx.x * blockDim.x + threadIdx.x;
  __shared__ float part[4];
  __shared__ int s0;
  if (threadIdx.x < 4) part[threadIdx.x] = 0.f;
  if (threadIdx.x == 0) s0 = find_seg(blockIdx.x * blockDim.x);
  __syncthreads();
  if (v < NN) {
    float e = expf(g_gate[v] - fdec(g_gmax));
    g_gate[v] = e;
    int s = find_seg(v);
    atomicAdd(&part[s - s0], e);
  }
  __syncthreads();
  if (threadIdx.x < 4 && part[threadIdx.x] != 0.f)
    atomicAdd(&g_sums[s0 + threadIdx.x], part[threadIdx.x]);
}

__global__ void k_readout3(float* __restrict__ out) {
  int v = blockIdx.x * blockDim.x + threadIdx.x;
  __shared__ float p0[4], p1[4];
  __shared__ int s0;
  if (threadIdx.x < 4) { p0[threadIdx.x] = 0.f; p1[threadIdx.x] = 0.f; }
  if (threadIdx.x == 0) s0 = find_seg(blockIdx.x * blockDim.x);
  __syncthreads();
  if (v < NN) {
    int s = find_seg(v);
    float w = g_gate[v] / (g_sums[s] + 1e-16f);
    atomicAdd(&p0[s - s0], g_outs[2 * v] * w);
    atomicAdd(&p1[s - s0], g_outs[2 * v + 1] * w);
  }
  __syncthreads();
  if (threadIdx.x < 4) {
    int s = s0 + threadIdx.x;
    if (s < NG && (p0[threadIdx.x] != 0.f || p1[threadIdx.x] != 0.f)) {
      atomicAdd(&out[2 * s], p0[threadIdx.x]);
      atomicAdd(&out[2 * s + 1], p1[threadIdx.x]);
    }
  }
}

extern "C" void kernel_launch(void* const* d_in, const int* in_sizes, int n_in,
                              void* d_out, int out_size) {
  const int* nodes = (const int*)d_in[0];
  const int* gsizes = (const int*)d_in[1];
  const int* edges = (const int*)d_in[2];
  const float* embed = (const float*)d_in[3];
  const float* tw = (const float*)d_in[4];
  const float* tb = (const float*)d_in[5];
  const float* gW = (const float*)d_in[6];
  const float* gU = (const float*)d_in[7];
  const float* gbi = (const float*)d_in[8];
  const float* gbr = (const float*)d_in[9];
  const float* gateW = (const float*)d_in[10];
  const float* gateB = (const float*)d_in[11];
  const float* outW = (const float*)d_in[12];
  const float* outB = (const float*)d_in[13];
  float* out = (float*)d_out;

  cudaFuncSetAttribute(k_g16, cudaFuncAttributeMaxDynamicSharedMemorySize, TG_SMEM);

  __half* h16;  cudaGetSymbolAddress((void**)&h16, g_h16);
  __half* tr16; cudaGetSymbolAddress((void**)&tr16, g_trans16);
  __half* ms16; cudaGetSymbolAddress((void**)&ms16, g_msgs16);
  float* gxptr; cudaGetSymbolAddress((void**)&gxptr, g_gx);
  float* ghptr; cudaGetSymbolAddress((void**)&ghptr, g_gh);
  __half* tw16; cudaGetSymbolAddress((void**)&tw16, g_tw16);
  __half* gW16; cudaGetSymbolAddress((void**)&gW16, g_gW16);
  __half* gU16; cudaGetSymbolAddress((void**)&gU16, g_gU16);

  const int steps[2] = {3, 1};
  dim3 gT(8, (NN + 127) / 128);
  dim3 gG(6, (NN + 127) / 128);

  k_h_init<<<(NN * HD + 255) / 256, 256>>>(nodes, embed);
  k_round_w<<<2048, 256>>>(tw, gW, gU);
  k_init_misc<<<(NN + 255) / 256, 256>>>(gsizes, out);
  // launch 3: first trans GEMM (profiled slot)
  k_g16<<<gT, 256, TG_SMEM>>>(h16, NN, tw16, HD, (long)HD * HD, tb, HD, tr16, NT * HD, 1);
  k_count<<<(NE + 255) / 256, 256>>>(edges);
  k_scan<<<1, 1024>>>();
  k_fill<<<(NE + 255) / 256, 256>>>(edges);

  for (int l = 0; l < 2; l++) {
    const __half* Wt = tw16 + (size_t)l * NT * HD * HD;
    const float* bt = tb + (size_t)l * NT * HD;
    const __half* Wx = gW16 + (size_t)l * 3 * HD * HD;
    const __half* Uh = gU16 + (size_t)l * 3 * HD * HD;
    const float* bi = gbi + (size_t)l * 768;
    const float* br = gbr + (size_t)l * 768;
    for (int s = 0; s < steps[l]; s++) {
      if (l != 0 || s != 0)
        k_g16<<<gT, 256, TG_SMEM>>>(h16, NN, Wt, HD, (long)HD * HD, bt, HD, tr16, NT * HD, 1);
      k_msgs<<<(NN * 32 + 255) / 256, 256>>>();
      k_g16<<<gG, 256, TG_SMEM>>>(ms16, NN, Wx, 768, 0, bi, 0, gxptr, 768, 0);
      k_g16<<<gG, 256, TG_SMEM>>>(h16, NN, Uh, 768, 0, br, 0, ghptr, 768, 0);
      k_gru<<<(NN * 64 + 255) / 256, 256>>>();
    }
  }
  k_readout1<<<(NN + 7) / 8, 256>>>(gateW, gateB, outW, outB);
  k_readout2<<<(NN + 255) / 256, 256>>>();
  k_readout3<<<(NN + 255) / 256, 256>>>(out);
}

// round 10
// speedup vs baseline: 2.5851x; 1.0851x over previous
#include <cuda_runtime.h>
#include <cuda_fp16.h>
#include <cstdint>
#include <math.h>

#define NN 100000
#define NG 100
#define NE 1000000
#define HD 256
#define NT 4

// fp16 GEMM smem (bytes):
// [0, 40960)        : 2 stages x (A 10240 + B 10240)   (tiles 128x32 halves, pad 40)
// [40960, 108544)   : epilogue stage: 8 warps x 32x66 floats
// [108544, 109056)  : bias tile (128 floats)
#define ABPAD 40
#define TG_SMEM 109056

__device__ __half g_h16[(size_t)NN * HD];
__device__ __half g_trans16[(size_t)NN * NT * HD];
__device__ __half g_msgs16[(size_t)NN * HD];
__device__ __half g_gx16[(size_t)NN * 3 * HD];
__device__ __half g_gh16[(size_t)NN * 3 * HD];
__device__ __half g_tw16[2 * NT * HD * HD];   // [l][t][n][k]
__device__ __half g_gW16[2 * 3 * HD * HD];    // [l][n=768][k=256]
__device__ __half g_gU16[2 * 3 * HD * HD];
__device__ float g_gate[NN];
__device__ float g_outs[2 * NN];
__device__ float g_sums[NG];
__device__ unsigned g_gmax;
__device__ int g_deg[NN];
__device__ int g_rowoff[NN + 1];
__device__ int g_cursor[NN];
__device__ int g_csr[NE];
__device__ int g_cum[NG];

__device__ __forceinline__ void mma16(float* d, const unsigned* a, const unsigned* b) {
  asm volatile(
      "mma.sync.aligned.m16n8k16.row.col.f32.f16.f16.f32 "
      "{%0,%1,%2,%3}, {%4,%5,%6,%7}, {%8,%9}, {%0,%1,%2,%3};\n"
      : "+f"(d[0]), "+f"(d[1]), "+f"(d[2]), "+f"(d[3])
      : "r"(a[0]), "r"(a[1]), "r"(a[2]), "r"(a[3]), "r"(b[0]), "r"(b[1]));
}
__device__ __forceinline__ void ldsm4(unsigned* r, uint32_t addr) {
  asm volatile("ldmatrix.sync.aligned.m8n8.x4.shared.b16 {%0,%1,%2,%3}, [%4];"
               : "=r"(r[0]), "=r"(r[1]), "=r"(r[2]), "=r"(r[3]) : "r"(addr));
}
__device__ __forceinline__ void cpa16s(uint32_t daddr, const void* src, bool pred) {
  int sz = pred ? 16 : 0;
  asm volatile("cp.async.cg.shared.global [%0], [%1], 16, %2;\n" :: "r"(daddr), "l"(src), "r"(sz));
}
__device__ __forceinline__ unsigned fenc(float f) {
  unsigned u = __float_as_uint(f);
  return (u & 0x80000000u) ? ~u : (u | 0x80000000u);
}
__device__ __forceinline__ float fdec(unsigned e) {
  return (e & 0x80000000u) ? __uint_as_float(e & 0x7fffffffu) : __uint_as_float(~e);
}
__device__ __forceinline__ int find_seg(int v) {
  int lo = 0, hi = NG;
  while (lo < hi) { int mid = (lo + hi) >> 1; if (g_cum[mid] > v) hi = mid; else lo = mid + 1; }
  return lo;
}
__device__ __forceinline__ float gru1(float xz, float xr, float xh,
                                      float hz, float hr, float hh, float h) {
  float z = 1.f / (1.f + expf(-(xz + hz)));
  float r = 1.f / (1.f + expf(-(xr + hr)));
  float c = tanhf(xh + r * hh);
  return z * h + (1.f - z) * c;
}

__global__ void k_h_init(const int* __restrict__ nodes, const float* __restrict__ embed) {
  int idx = blockIdx.x * blockDim.x + threadIdx.x;
  if (idx >= NN * HD) return;
  int v = idx >> 8, j = idx & 255;
  int tok = __ldg(&nodes[v]);
  int pos = __ldg(&nodes[NN + v]);
  int p = pos < 512 ? pos : 512;
  float pe = 0.f;
  if (p > 0) {
    float ang = (float)(p - 1) * exp2f(-(float)j * 0.10381025296523f);
    pe = (j & 1) ? cosf(ang) : sinf(ang);
  }
  g_h16[idx] = __float2half(__ldg(&embed[(size_t)tok * HD + j]) + pe);
}

// transpose weights to [n][k] fp16
__global__ void k_round_w(const float* __restrict__ tw, const float* __restrict__ gW,
                          const float* __restrict__ gU) {
  int i = blockIdx.x * blockDim.x + threadIdx.x;
  if (i < 2 * NT * HD * HD) {
    int lt = i >> 16, n = (i >> 8) & 255, k = i & 255;
    g_tw16[i] = __float2half(__ldg(&tw[(lt << 16) + (k << 8) + n]));
  }
  if (i < 2 * 3 * HD * HD) {
    int l = i / 196608;
    int rem = i - l * 196608;
    int n = rem >> 8, k = rem & 255;
    g_gW16[i] = __float2half(__ldg(&gW[l * 196608 + k * 768 + n]));
    g_gU16[i] = __float2half(__ldg(&gU[l * 196608 + k * 768 + n]));
  }
}

__global__ void k_init_misc(const int* __restrict__ sizes, float* __restrict__ out) {
  int i = blockIdx.x * blockDim.x + threadIdx.x;
  if (i < NN) g_deg[i] = 0;
  if (blockIdx.x == 0) {
    int t = threadIdx.x;
    if (t < NG) g_sums[t] = 0.f;
    if (t < 2 * NG) out[t] = 0.f;
    if (t == 0) {
      g_gmax = 0u;
      int s = 0;
      for (int g = 0; g < NG; g++) { s += sizes[g]; g_cum[g] = s; }
    }
  }
}

__global__ void k_count(const int* __restrict__ edges) {
  int i = blockIdx.x * blockDim.x + threadIdx.x;
  if (i < NE) atomicAdd(&g_deg[edges[3 * i + 2]], 1);
}

__global__ void k_scan() {
  __shared__ int sCarry;
  __shared__ int warpTot[32];
  int tid = threadIdx.x;
  int lane = tid & 31, wid = tid >> 5;
  if (tid == 0) sCarry = 0;
  __syncthreads();
  for (int base = 0; base < NN; base += 1024) {
    int i = base + tid;
    int v = (i < NN) ? g_deg[i] : 0;
    int x = v;
#pragma unroll
    for (int off = 1; off < 32; off <<= 1) {
      int y = __shfl_up_sync(~0u, x, off);
      if (lane >= off) x += y;
    }
    if (lane == 31) warpTot[wid] = x;
    __syncthreads();
    if (wid == 0) {
      int w = warpTot[lane];
#pragma unroll
      for (int off = 1; off < 32; off <<= 1) {
        int y = __shfl_up_sync(~0u, w, off);
        if (lane >= off) w += y;
      }
      warpTot[lane] = w;
    }
    __syncthreads();
    int warpPrefix = (wid > 0) ? warpTot[wid - 1] : 0;
    int incl = x + warpPrefix;
    int excl = incl - v;
    int carry = sCarry;
    if (i < NN) { g_rowoff[i] = carry + excl; g_cursor[i] = carry + excl; }
    __syncthreads();
    if (tid == 1023) sCarry = carry + incl;
    __syncthreads();
  }
  if (tid == 0) g_rowoff[NN] = sCarry;
}

__global__ void k_fill(const int* __restrict__ edges) {
  int i = blockIdx.x * blockDim.x + threadIdx.x;
  if (i >= NE) return;
  int et = edges[3 * i], src = edges[3 * i + 1], tgt = edges[3 * i + 2];
  int p = atomicAdd(&g_cursor[tgt], 1);
  g_csr[p] = (src << 2) | et;
}

// C[M, gridX*128] = A[M,256] @ B^T (+bias). A fp16 [m][k], B fp16 [n][k].
// 128x128 tile, BK=32, 2-stage cp.async, ldmatrix fragments, 2 CTAs/SM.
__global__ __launch_bounds__(256, 2)
void k_g16(const __half* __restrict__ A, int M, const __half* __restrict__ B,
           int nblk, long nblkStride, const float* __restrict__ bias, int biasBlkStride,
           void* __restrict__ Cv, int ldc, int outHalf) {
  extern __shared__ __half sh[];
  uint32_t sbase;
  asm("{ .reg .u64 t; cvta.to.shared.u64 t, %1; cvt.u32.u64 %0, t; }" : "=r"(sbase) : "l"(sh));
  int tid = threadIdx.x, lane = tid & 31, wid = tid >> 5;
  int n0 = blockIdx.x * 128, m0 = blockIdx.y * 128;
  int tB = n0 / nblk, nb0 = n0 - tB * nblk;
  const __half* Bblk = B + (size_t)tB * nblkStride + (size_t)nb0 * HD;
  float* biasS = (float*)((char*)sh + 108544);
  if (tid < 128) biasS[tid] = __ldg(&bias[(size_t)tB * biasBlkStride + nb0 + tid]);

  int lrow = tid >> 2, lseg = tid & 3;
  int wm = (wid & 3) * 32, wn = (wid >> 2) * 64;
  int g = lane >> 2, t2 = (lane & 3) * 2;
  int grp = lane >> 3, l8 = lane & 7;
  int rsel = (grp & 1) * 8;   // A: row-high, B: k-high
  int csel = (grp >> 1) * 8;  // A: k-high,   B: n-high

  float acc[2][8][4];
#pragma unroll
  for (int i = 0; i < 2; i++)
#pragma unroll
    for (int j = 0; j < 8; j++)
#pragma unroll
      for (int k = 0; k < 4; k++) acc[i][j][k] = 0.f;

  {
    uint32_t ab = sbase, bb = sbase + 10240;
#pragma unroll
    for (int it = 0; it < 2; it++) {
      int row = lrow + it * 64;
      uint32_t off = (uint32_t)(row * (ABPAD * 2) + lseg * 16);
      cpa16s(ab + off, A + (size_t)(m0 + row) * HD + lseg * 8, (m0 + row) < M);
      cpa16s(bb + off, Bblk + (size_t)row * HD + lseg * 8, true);
    }
    asm volatile("cp.async.commit_group;\n");
  }

#pragma unroll
  for (int kt = 0; kt < 8; kt++) {
    int s = kt & 1;
    if (kt < 7) {
      int s2 = (kt + 1) & 1;
      int k0 = (kt + 1) * 32;
      uint32_t ab = sbase + s2 * 20480, bb = ab + 10240;
#pragma unroll
      for (int it = 0; it < 2; it++) {
        int row = lrow + it * 64;
        uint32_t off = (uint32_t)(row * (ABPAD * 2) + lseg * 16);
        cpa16s(ab + off, A + (size_t)(m0 + row) * HD + k0 + lseg * 8, (m0 + row) < M);
        cpa16s(bb + off, Bblk + (size_t)row * HD + k0 + lseg * 8, true);
      }
      asm volatile("cp.async.commit_group;\n");
      asm volatile("cp.async.wait_group 1;\n");
    } else {
      asm volatile("cp.async.wait_group 0;\n");
    }
    __syncthreads();
    uint32_t aStage = sbase + s * 20480;
    uint32_t bStage = aStage + 10240;
#pragma unroll
    for (int ks = 0; ks < 2; ks++) {
      int kk = ks * 16;
      unsigned af[2][4], bf[8][2];
      int rowA = wm + rsel + l8;
      int colA = kk + csel;
      ldsm4(af[0], aStage + (uint32_t)(rowA * ABPAD + colA) * 2);
      ldsm4(af[1], aStage + (uint32_t)((rowA + 16) * ABPAD + colA) * 2);
      int nB = wn + csel + l8;
      int kB = kk + rsel;
#pragma unroll
      for (int p = 0; p < 4; p++) {
        unsigned t[4];
        ldsm4(t, bStage + (uint32_t)((nB + p * 16) * ABPAD + kB) * 2);
        bf[2 * p][0] = t[0]; bf[2 * p][1] = t[1];
        bf[2 * p + 1][0] = t[2]; bf[2 * p + 1][1] = t[3];
      }
#pragma unroll
      for (int mt = 0; mt < 2; mt++)
#pragma unroll
        for (int nt = 0; nt < 8; nt++) mma16(acc[mt][nt], af[mt], bf[nt]);
    }
    __syncthreads();
  }

  // epilogue: per-warp 32x66 fp32 stage, transposed coalesced store
  float* ep = (float*)((char*)sh + 40960) + wid * 2112;
#pragma unroll
  for (int mt = 0; mt < 2; mt++)
#pragma unroll
    for (int nt = 0; nt < 8; nt++) {
      int lc = nt * 8 + t2;
      float b0 = biasS[wn + lc], b1 = biasS[wn + lc + 1];
      int r0 = mt * 16 + g;
      ep[r0 * 66 + lc] = acc[mt][nt][0] + b0;
      ep[r0 * 66 + lc + 1] = acc[mt][nt][1] + b1;
      ep[(r0 + 8) * 66 + lc] = acc[mt][nt][2] + b0;
      ep[(r0 + 8) * 66 + lc + 1] = acc[mt][nt][3] + b1;
    }
  __syncwarp();
  int colg = n0 + wn + 2 * lane;
#pragma unroll 4
  for (int rr = 0; rr < 32; rr++) {
    int gr = m0 + wm + rr;
    if (gr < M) {
      float2 v = *(float2*)&ep[rr * 66 + 2 * lane];
      if (outHalf) {
        *(__half2*)((__half*)Cv + (size_t)gr * ldc + colg) = __floats2half2_rn(v.x, v.y);
      } else {
        *(float2*)((float*)Cv + (size_t)gr * ldc + colg) = v;
      }
    }
  }
}

__global__ void k_msgs() {
  int gw = (blockIdx.x * blockDim.x + threadIdx.x) >> 5;
  int lane = threadIdx.x & 31;
  if (gw >= NN) return;
  int beg = g_rowoff[gw], end = g_rowoff[gw + 1];
  float a[8] = {0.f, 0.f, 0.f, 0.f, 0.f, 0.f, 0.f, 0.f};
  int i = beg;
  for (; i + 1 < end; i += 2) {
    int e0 = __ldg(&g_csr[i]), e1 = __ldg(&g_csr[i + 1]);
    const uint4* p0 = (const uint4*)(g_trans16 + ((size_t)(e0 >> 2) * (NT * HD) + (size_t)(e0 & 3) * HD));
    const uint4* p1 = (const uint4*)(g_trans16 + ((size_t)(e1 >> 2) * (NT * HD) + (size_t)(e1 & 3) * HD));
    uint4 x = __ldg(p0 + lane), y = __ldg(p1 + lane);
    const __half2* hx = (const __half2*)&x;
    const __half2* hy = (const __half2*)&y;
#pragma unroll
    for (int q = 0; q < 4; q++) {
      float2 fx = __half22float2(hx[q]), fy = __half22float2(hy[q]);
      a[2 * q] += fx.x + fy.x;
      a[2 * q + 1] += fx.y + fy.y;
    }
  }
  if (i < end) {
    int e0 = __ldg(&g_csr[i]);
    const uint4* p0 = (const uint4*)(g_trans16 + ((size_t)(e0 >> 2) * (NT * HD) + (size_t)(e0 & 3) * HD));
    uint4 x = __ldg(p0 + lane);
    const __half2* hx = (const __half2*)&x;
#pragma unroll
    for (int q = 0; q < 4; q++) {
      float2 fx = __half22float2(hx[q]);
      a[2 * q] += fx.x;
      a[2 * q + 1] += fx.y;
    }
  }
  uint4 o;
  __half2* ho = (__half2*)&o;
#pragma unroll
  for (int q = 0; q < 4; q++) ho[q] = __floats2half2_rn(a[2 * q], a[2 * q + 1]);
  ((uint4*)(g_msgs16 + (size_t)gw * HD))[lane] = o;
}

__global__ void k_gru() {
  int idx = blockIdx.x * blockDim.x + threadIdx.x;
  if (idx >= NN * 64) return;
  int v = idx >> 6, q = idx & 63;
  const uint2* px = (const uint2*)(g_gx16 + (size_t)v * 768);
  const uint2* ph = (const uint2*)(g_gh16 + (size_t)v * 768);
  uint2 XZ = px[q], XR = px[q + 64], XH = px[q + 128];
  uint2 HZ = ph[q], HR = ph[q + 64], HH = ph[q + 128];
  float2 xz0 = __half22float2(*(__half2*)&XZ.x), xz1 = __half22float2(*(__half2*)&XZ.y);
  float2 xr0 = __half22float2(*(__half2*)&XR.x), xr1 = __half22float2(*(__half2*)&XR.y);
  float2 xh0 = __half22float2(*(__half2*)&XH.x), xh1 = __half22float2(*(__half2*)&XH.y);
  float2 hz0 = __half22float2(*(__half2*)&HZ.x), hz1 = __half22float2(*(__half2*)&HZ.y);
  float2 hr0 = __half22float2(*(__half2*)&HR.x), hr1 = __half22float2(*(__half2*)&HR.y);
  float2 hh0 = __half22float2(*(__half2*)&HH.x), hh1 = __half22float2(*(__half2*)&HH.y);
  uint2 hraw = ((const uint2*)g_h16)[idx];
  float2 h01 = __half22float2(*(__half2*)&hraw.x);
  float2 h23 = __half22float2(*(__half2*)&hraw.y);
  float r0 = gru1(xz0.x, xr0.x, xh0.x, hz0.x, hr0.x, hh0.x, h01.x);
  float r1 = gru1(xz0.y, xr0.y, xh0.y, hz0.y, hr0.y, hh0.y, h01.y);
  float r2 = gru1(xz1.x, xr1.x, xh1.x, hz1.x, hr1.x, hh1.x, h23.x);
  float r3 = gru1(xz1.y, xr1.y, xh1.y, hz1.y, hr1.y, hh1.y, h23.y);
  uint2 o;
  *(__half2*)&o.x = __floats2half2_rn(r0, r1);
  *(__half2*)&o.y = __floats2half2_rn(r2, r3);
  ((uint2*)g_h16)[idx] = o;
}

__global__ void k_readout1(const float* __restrict__ gateW, const float* __restrict__ gateB,
                           const float* __restrict__ outW, const float* __restrict__ outB) {
  int warp = threadIdx.x >> 5, lane = threadIdx.x & 31;
  int v = blockIdx.x * 8 + warp;
  float g = 0.f, o0 = 0.f, o1 = 0.f;
  if (v < NN) {
    const __half* hv = g_h16 + (size_t)v * HD;
#pragma unroll 4
    for (int j = lane; j < HD; j += 32) {
      float x = __half2float(__ldg(&hv[j]));
      g += x * __ldg(&gateW[j]);
      float2 w = __ldg((const float2*)outW + j);
      o0 += x * w.x;
      o1 += x * w.y;
    }
  }
#pragma unroll
  for (int off = 16; off; off >>= 1) {
    g += __shfl_xor_sync(~0u, g, off);
    o0 += __shfl_xor_sync(~0u, o0, off);
    o1 += __shfl_xor_sync(~0u, o1, off);
  }
  float gl = g + __ldg(gateB);
  if (v < NN && lane == 0) {
    g_gate[v] = gl;
    g_outs[2 * v] = o0 + __ldg(&outB[0]);
    g_outs[2 * v + 1] = o1 + __ldg(&outB[1]);
  }
  __shared__ float smax[8];
  if (lane == 0) smax[warp] = (v < NN) ? gl : -3.4e38f;
  __syncthreads();
  if (threadIdx.x == 0) {
    float m = smax[0];
#pragma unroll
    for (int i = 1; i < 8; i++) m = fmaxf(m, smax[i]);
    atomicMax(&g_gmax, fenc(m));
  }
}

__global__ void k_readout2() {
  int v = blockIdx.x * blockDim.x + threadIdx.x;
  __shared__ float part[4];
  __shared__ int s0;
  if (threadIdx.x < 4) part[threadIdx.x] = 0.f;
  if (threadIdx.x == 0) s0 = find_seg(blockIdx.x * blockDim.x);
  __syncthreads();
  if (v < NN) {
    float e = expf(g_gate[v] - fdec(g_gmax));
    g_gate[v] = e;
    int s = find_seg(v);
    atomicAdd(&part[s - s0], e);
  }
  __syncthreads();
  if (threadIdx.x < 4 && part[threadIdx.x] != 0.f)
    atomicAdd(&g_sums[s0 + threadIdx.x], part[threadIdx.x]);
}

__global__ void k_readout3(float* __restrict__ out) {
  int v = blockIdx.x * blockDim.x + threadIdx.x;
  __shared__ float p0[4], p1[4];
  __shared__ int s0;
  if (threadIdx.x < 4) { p0[threadIdx.x] = 0.f; p1[threadIdx.x] = 0.f; }
  if (threadIdx.x == 0) s0 = find_seg(blockIdx.x * blockDim.x);
  __syncthreads();
  if (v < NN) {
    int s = find_seg(v);
    float w = g_gate[v] / (g_sums[s] + 1e-16f);
    atomicAdd(&p0[s - s0], g_outs[2 * v] * w);
    atomicAdd(&p1[s - s0], g_outs[2 * v + 1] * w);
  }
  __syncthreads();
  if (threadIdx.x < 4) {
    int s = s0 + threadIdx.x;
    if (s < NG && (p0[threadIdx.x] != 0.f || p1[threadIdx.x] != 0.f)) {
      atomicAdd(&out[2 * s], p0[threadIdx.x]);
      atomicAdd(&out[2 * s + 1], p1[threadIdx.x]);
    }
  }
}

extern "C" void kernel_launch(void* const* d_in, const int* in_sizes, int n_in,
                              void* d_out, int out_size) {
  const int* nodes = (const int*)d_in[0];
  const int* gsizes = (const int*)d_in[1];
  const int* edges = (const int*)d_in[2];
  const float* embed = (const float*)d_in[3];
  const float* tw = (const float*)d_in[4];
  const float* tb = (const float*)d_in[5];
  const float* gW = (const float*)d_in[6];
  const float* gU = (const float*)d_in[7];
  const float* gbi = (const float*)d_in[8];
  const float* gbr = (const float*)d_in[9];
  const float* gateW = (const float*)d_in[10];
  const float* gateB = (const float*)d_in[11];
  const float* outW = (const float*)d_in[12];
  const float* outB = (const float*)d_in[13];
  float* out = (float*)d_out;

  cudaFuncSetAttribute(k_g16, cudaFuncAttributeMaxDynamicSharedMemorySize, TG_SMEM);

  __half* h16;  cudaGetSymbolAddress((void**)&h16, g_h16);
  __half* tr16; cudaGetSymbolAddress((void**)&tr16, g_trans16);
  __half* ms16; cudaGetSymbolAddress((void**)&ms16, g_msgs16);
  __half* gx16; cudaGetSymbolAddress((void**)&gx16, g_gx16);
  __half* gh16; cudaGetSymbolAddress((void**)&gh16, g_gh16);
  __half* tw16; cudaGetSymbolAddress((void**)&tw16, g_tw16);
  __half* gW16; cudaGetSymbolAddress((void**)&gW16, g_gW16);
  __half* gU16; cudaGetSymbolAddress((void**)&gU16, g_gU16);

  const int steps[2] = {3, 1};
  dim3 gT(8, (NN + 127) / 128);
  dim3 gG(6, (NN + 127) / 128);

  k_h_init<<<(NN * HD + 255) / 256, 256>>>(nodes, embed);
  k_round_w<<<2048, 256>>>(tw, gW, gU);
  k_init_misc<<<(NN + 255) / 256, 256>>>(gsizes, out);
  // launch 3: first trans GEMM (profiled slot)
  k_g16<<<gT, 256, TG_SMEM>>>(h16, NN, tw16, HD, (long)HD * HD, tb, HD, tr16, NT * HD, 1);
  k_count<<<(NE + 255) / 256, 256>>>(edges);
  k_scan<<<1, 1024>>>();
  k_fill<<<(NE + 255) / 256, 256>>>(edges);

  for (int l = 0; l < 2; l++) {
    const __half* Wt = tw16 + (size_t)l * NT * HD * HD;
    const float* bt = tb + (size_t)l * NT * HD;
    const __half* Wx = gW16 + (size_t)l * 3 * HD * HD;
    const __half* Uh = gU16 + (size_t)l * 3 * HD * HD;
    const float* bi = gbi + (size_t)l * 768;
    const float* br = gbr + (size_t)l * 768;
    for (int s = 0; s < steps[l]; s++) {
      if (l != 0 || s != 0)
        k_g16<<<gT, 256, TG_SMEM>>>(h16, NN, Wt, HD, (long)HD * HD, bt, HD, tr16, NT * HD, 1);
      k_msgs<<<(NN * 32 + 255) / 256, 256>>>();
      k_g16<<<gG, 256, TG_SMEM>>>(ms16, NN, Wx, 768, 0, bi, 0, gx16, 768, 1);
      k_g16<<<gG, 256, TG_SMEM>>>(h16, NN, Uh, 768, 0, br, 0, gh16, 768, 1);
      k_gru<<<(NN * 64 + 255) / 256, 256>>>();
    }
  }
  k_readout1<<<(NN + 7) / 8, 256>>>(gateW, gateB, outW, outB);
  k_readout2<<<(NN + 255) / 256, 256>>>();
  k_readout3<<<(NN + 255) / 256, 256>>>(out);
}

// round 11
// speedup vs baseline: 2.8607x; 1.1066x over previous
#include <cuda_runtime.h>
#include <cuda_fp16.h>
#include <cstdint>
#include <math.h>

#define NN 100000
#define NG 100
#define NE 1000000
#define HD 256
#define NT 4

// fp16 GEMM smem (bytes), BK=64:
// [0, 73728)   : 2 stages x (A 18432 + B 18432); rows padded to 72 halves (144B)
//                epilogue (8 warps x 32x66 floats = 67584B) OVERLAYS this after mainloop
// [73728,74240): bias tile (128 floats)
#define KPAD 72
#define STG_BYTES 36864
#define TG_SMEM 74240

__device__ __half g_h16[(size_t)NN * HD];
__device__ __half g_trans16[(size_t)NN * NT * HD];
__device__ __half g_msgs16[(size_t)NN * HD];
__device__ __half g_gx16[(size_t)NN * 3 * HD];
__device__ __half g_gh16[(size_t)NN * 3 * HD];
__device__ __half g_tw16[2 * NT * HD * HD];   // [l][t][n][k]
__device__ __half g_gW16[2 * 3 * HD * HD];    // [l][n=768][k=256]
__device__ __half g_gU16[2 * 3 * HD * HD];
__device__ float g_gate[NN];
__device__ float g_outs[2 * NN];
__device__ float g_sums[NG];
__device__ unsigned g_gmax;
__device__ int g_deg[NN];
__device__ int g_rowoff[NN + 1];
__device__ int g_cursor[NN];
__device__ int g_csr[NE];
__device__ int g_cum[NG];

__device__ __forceinline__ void mma16(float* d, const unsigned* a, const unsigned* b) {
  asm volatile(
      "mma.sync.aligned.m16n8k16.row.col.f32.f16.f16.f32 "
      "{%0,%1,%2,%3}, {%4,%5,%6,%7}, {%8,%9}, {%0,%1,%2,%3};\n"
      : "+f"(d[0]), "+f"(d[1]), "+f"(d[2]), "+f"(d[3])
      : "r"(a[0]), "r"(a[1]), "r"(a[2]), "r"(a[3]), "r"(b[0]), "r"(b[1]));
}
__device__ __forceinline__ void ldsm4(unsigned* r, uint32_t addr) {
  asm volatile("ldmatrix.sync.aligned.m8n8.x4.shared.b16 {%0,%1,%2,%3}, [%4];"
               : "=r"(r[0]), "=r"(r[1]), "=r"(r[2]), "=r"(r[3]) : "r"(addr));
}
__device__ __forceinline__ void cpa16s(uint32_t daddr, const void* src, bool pred) {
  int sz = pred ? 16 : 0;
  asm volatile("cp.async.cg.shared.global [%0], [%1], 16, %2;\n" :: "r"(daddr), "l"(src), "r"(sz));
}
__device__ __forceinline__ unsigned fenc(float f) {
  unsigned u = __float_as_uint(f);
  return (u & 0x80000000u) ? ~u : (u | 0x80000000u);
}
__device__ __forceinline__ float fdec(unsigned e) {
  return (e & 0x80000000u) ? __uint_as_float(e & 0x7fffffffu) : __uint_as_float(~e);
}
__device__ __forceinline__ int find_seg(int v) {
  int lo = 0, hi = NG;
  while (lo < hi) { int mid = (lo + hi) >> 1; if (g_cum[mid] > v) hi = mid; else lo = mid + 1; }
  return lo;
}
__device__ __forceinline__ float gru1(float xz, float xr, float xh,
                                      float hz, float hr, float hh, float h) {
  float z = 1.f / (1.f + expf(-(xz + hz)));
  float r = 1.f / (1.f + expf(-(xr + hr)));
  float c = tanhf(xh + r * hh);
  return z * h + (1.f - z) * c;
}

__global__ void k_h_init(const int* __restrict__ nodes, const float* __restrict__ embed) {
  int idx = blockIdx.x * blockDim.x + threadIdx.x;
  if (idx >= NN * HD) return;
  int v = idx >> 8, j = idx & 255;
  int tok = __ldg(&nodes[v]);
  int pos = __ldg(&nodes[NN + v]);
  int p = pos < 512 ? pos : 512;
  float pe = 0.f;
  if (p > 0) {
    float ang = (float)(p - 1) * exp2f(-(float)j * 0.10381025296523f);
    pe = (j & 1) ? cosf(ang) : sinf(ang);
  }
  g_h16[idx] = __float2half(__ldg(&embed[(size_t)tok * HD + j]) + pe);
}

// transpose weights to [n][k] fp16
__global__ void k_round_w(const float* __restrict__ tw, const float* __restrict__ gW,
                          const float* __restrict__ gU) {
  int i = blockIdx.x * blockDim.x + threadIdx.x;
  if (i < 2 * NT * HD * HD) {
    int lt = i >> 16, n = (i >> 8) & 255, k = i & 255;
    g_tw16[i] = __float2half(__ldg(&tw[(lt << 16) + (k << 8) + n]));
  }
  if (i < 2 * 3 * HD * HD) {
    int l = i / 196608;
    int rem = i - l * 196608;
    int n = rem >> 8, k = rem & 255;
    g_gW16[i] = __float2half(__ldg(&gW[l * 196608 + k * 768 + n]));
    g_gU16[i] = __float2half(__ldg(&gU[l * 196608 + k * 768 + n]));
  }
}

__global__ void k_init_misc(const int* __restrict__ sizes, float* __restrict__ out) {
  int i = blockIdx.x * blockDim.x + threadIdx.x;
  if (i < NN) g_deg[i] = 0;
  if (blockIdx.x == 0) {
    int t = threadIdx.x;
    if (t < NG) g_sums[t] = 0.f;
    if (t < 2 * NG) out[t] = 0.f;
    if (t == 0) {
      g_gmax = 0u;
      int s = 0;
      for (int g = 0; g < NG; g++) { s += sizes[g]; g_cum[g] = s; }
    }
  }
}

__global__ void k_count(const int* __restrict__ edges) {
  int i = blockIdx.x * blockDim.x + threadIdx.x;
  if (i < NE) atomicAdd(&g_deg[edges[3 * i + 2]], 1);
}

__global__ void k_scan() {
  __shared__ int sCarry;
  __shared__ int warpTot[32];
  int tid = threadIdx.x;
  int lane = tid & 31, wid = tid >> 5;
  if (tid == 0) sCarry = 0;
  __syncthreads();
  for (int base = 0; base < NN; base += 1024) {
    int i = base + tid;
    int v = (i < NN) ? g_deg[i] : 0;
    int x = v;
#pragma unroll
    for (int off = 1; off < 32; off <<= 1) {
      int y = __shfl_up_sync(~0u, x, off);
      if (lane >= off) x += y;
    }
    if (lane == 31) warpTot[wid] = x;
    __syncthreads();
    if (wid == 0) {
      int w = warpTot[lane];
#pragma unroll
      for (int off = 1; off < 32; off <<= 1) {
        int y = __shfl_up_sync(~0u, w, off);
        if (lane >= off) w += y;
      }
      warpTot[lane] = w;
    }
    __syncthreads();
    int warpPrefix = (wid > 0) ? warpTot[wid - 1] : 0;
    int incl = x + warpPrefix;
    int excl = incl - v;
    int carry = sCarry;
    if (i < NN) { g_rowoff[i] = carry + excl; g_cursor[i] = carry + excl; }
    __syncthreads();
    if (tid == 1023) sCarry = carry + incl;
    __syncthreads();
  }
  if (tid == 0) g_rowoff[NN] = sCarry;
}

__global__ void k_fill(const int* __restrict__ edges) {
  int i = blockIdx.x * blockDim.x + threadIdx.x;
  if (i >= NE) return;
  int et = edges[3 * i], src = edges[3 * i + 1], tgt = edges[3 * i + 2];
  int p = atomicAdd(&g_cursor[tgt], 1);
  g_csr[p] = (src << 2) | et;
}

// C[M, gridX*128] = A[M,256] @ B^T (+bias). A fp16 [m][k], B fp16 [n][k].
// 128x128 tile, BK=64, 2-stage cp.async, ONE sync per slab, ldmatrix, 2 CTAs/SM.
__global__ __launch_bounds__(256, 2)
void k_g16(const __half* __restrict__ A, int M, const __half* __restrict__ B,
           int nblk, long nblkStride, const float* __restrict__ bias, int biasBlkStride,
           void* __restrict__ Cv, int ldc, int outHalf) {
  extern __shared__ __half sh[];
  uint32_t sbase;
  asm("{ .reg .u64 t; cvta.to.shared.u64 t, %1; cvt.u32.u64 %0, t; }" : "=r"(sbase) : "l"(sh));
  int tid = threadIdx.x, lane = tid & 31, wid = tid >> 5;
  int n0 = blockIdx.x * 128, m0 = blockIdx.y * 128;
  int tB = n0 / nblk, nb0 = n0 - tB * nblk;
  const __half* Bblk = B + (size_t)tB * nblkStride + (size_t)nb0 * HD;
  float* biasS = (float*)((char*)sh + 73728);
  if (tid < 128) biasS[tid] = __ldg(&bias[(size_t)tB * biasBlkStride + nb0 + tid]);

  int lrow = tid >> 3, lseg = tid & 7;   // loader: 32 rows x 8 segs of 16B per pass
  int wm = (wid & 3) * 32, wn = (wid >> 2) * 64;
  int g = lane >> 2, t2 = (lane & 3) * 2;
  int grp = lane >> 3, l8 = lane & 7;
  int rsel = (grp & 1) * 8;
  int csel = (grp >> 1) * 8;

  float acc[2][8][4];
#pragma unroll
  for (int i = 0; i < 2; i++)
#pragma unroll
    for (int j = 0; j < 8; j++)
#pragma unroll
      for (int k = 0; k < 4; k++) acc[i][j][k] = 0.f;

  // prologue: slab 0 -> stage 0
  {
    uint32_t ab = sbase, bb = sbase + 18432;
#pragma unroll
    for (int it = 0; it < 4; it++) {
      int row = lrow + it * 32;
      uint32_t off = (uint32_t)(row * (KPAD * 2) + lseg * 16);
      cpa16s(ab + off, A + (size_t)(m0 + row) * HD + lseg * 8, (m0 + row) < M);
      cpa16s(bb + off, Bblk + (size_t)row * HD + lseg * 8, true);
    }
    asm volatile("cp.async.commit_group;\n");
  }

#pragma unroll
  for (int kt = 0; kt < 4; kt++) {
    int s = kt & 1;
    asm volatile("cp.async.wait_group 0;\n");
    __syncthreads();
    if (kt < 3) {
      int s2 = s ^ 1;
      int k0 = (kt + 1) * 64;
      uint32_t ab = sbase + s2 * STG_BYTES, bb = ab + 18432;
#pragma unroll
      for (int it = 0; it < 4; it++) {
        int row = lrow + it * 32;
        uint32_t off = (uint32_t)(row * (KPAD * 2) + lseg * 16);
        cpa16s(ab + off, A + (size_t)(m0 + row) * HD + k0 + lseg * 8, (m0 + row) < M);
        cpa16s(bb + off, Bblk + (size_t)row * HD + k0 + lseg * 8, true);
      }
      asm volatile("cp.async.commit_group;\n");
    }
    uint32_t aStage = sbase + s * STG_BYTES;
    uint32_t bStage = aStage + 18432;
#pragma unroll
    for (int ks = 0; ks < 4; ks++) {
      int kk = ks * 16;
      unsigned af[2][4], bf[8][2];
      int rowA = wm + rsel + l8;
      int colA = kk + csel;
      ldsm4(af[0], aStage + (uint32_t)(rowA * KPAD + colA) * 2);
      ldsm4(af[1], aStage + (uint32_t)((rowA + 16) * KPAD + colA) * 2);
      int nB = wn + csel + l8;
      int kB = kk + rsel;
#pragma unroll
      for (int p = 0; p < 4; p++) {
        unsigned t[4];
        ldsm4(t, bStage + (uint32_t)((nB + p * 16) * KPAD + kB) * 2);
        bf[2 * p][0] = t[0]; bf[2 * p][1] = t[1];
        bf[2 * p + 1][0] = t[2]; bf[2 * p + 1][1] = t[3];
      }
#pragma unroll
      for (int mt = 0; mt < 2; mt++)
#pragma unroll
        for (int nt = 0; nt < 8; nt++) mma16(acc[mt][nt], af[mt], bf[nt]);
    }
  }
  __syncthreads();  // before epilogue overlays operand buffers

  // epilogue: per-warp 32x66 fp32 stage (overlaid), transposed coalesced store
  float* ep = (float*)sh + wid * 2112;
#pragma unroll
  for (int mt = 0; mt < 2; mt++)
#pragma unroll
    for (int nt = 0; nt < 8; nt++) {
      int lc = nt * 8 + t2;
      float b0 = biasS[wn + lc], b1 = biasS[wn + lc + 1];
      int r0 = mt * 16 + g;
      ep[r0 * 66 + lc] = acc[mt][nt][0] + b0;
      ep[r0 * 66 + lc + 1] = acc[mt][nt][1] + b1;
      ep[(r0 + 8) * 66 + lc] = acc[mt][nt][2] + b0;
      ep[(r0 + 8) * 66 + lc + 1] = acc[mt][nt][3] + b1;
    }
  __syncwarp();
  int colg = n0 + wn + 2 * lane;
#pragma unroll 4
  for (int rr = 0; rr < 32; rr++) {
    int gr = m0 + wm + rr;
    if (gr < M) {
      float2 v = *(float2*)&ep[rr * 66 + 2 * lane];
      if (outHalf) {
        *(__half2*)((__half*)Cv + (size_t)gr * ldc + colg) = __floats2half2_rn(v.x, v.y);
      } else {
        *(float2*)((float*)Cv + (size_t)gr * ldc + colg) = v;
      }
    }
  }
}

__global__ void k_msgs() {
  int gw = (blockIdx.x * blockDim.x + threadIdx.x) >> 5;
  int lane = threadIdx.x & 31;
  if (gw >= NN) return;
  int beg = g_rowoff[gw], end = g_rowoff[gw + 1];
  float a[8] = {0.f, 0.f, 0.f, 0.f, 0.f, 0.f, 0.f, 0.f};
  int i = beg;
  for (; i + 1 < end; i += 2) {
    int e0 = __ldg(&g_csr[i]), e1 = __ldg(&g_csr[i + 1]);
    const uint4* p0 = (const uint4*)(g_trans16 + ((size_t)(e0 >> 2) * (NT * HD) + (size_t)(e0 & 3) * HD));
    const uint4* p1 = (const uint4*)(g_trans16 + ((size_t)(e1 >> 2) * (NT * HD) + (size_t)(e1 & 3) * HD));
    uint4 x = __ldg(p0 + lane), y = __ldg(p1 + lane);
    const __half2* hx = (const __half2*)&x;
    const __half2* hy = (const __half2*)&y;
#pragma unroll
    for (int q = 0; q < 4; q++) {
      float2 fx = __half22float2(hx[q]), fy = __half22float2(hy[q]);
      a[2 * q] += fx.x + fy.x;
      a[2 * q + 1] += fx.y + fy.y;
    }
  }
  if (i < end) {
    int e0 = __ldg(&g_csr[i]);
    const uint4* p0 = (const uint4*)(g_trans16 + ((size_t)(e0 >> 2) * (NT * HD) + (size_t)(e0 & 3) * HD));
    uint4 x = __ldg(p0 + lane);
    const __half2* hx = (const __half2*)&x;
#pragma unroll
    for (int q = 0; q < 4; q++) {
      float2 fx = __half22float2(hx[q]);
      a[2 * q] += fx.x;
      a[2 * q + 1] += fx.y;
    }
  }
  uint4 o;
  __half2* ho = (__half2*)&o;
#pragma unroll
  for (int q = 0; q < 4; q++) ho[q] = __floats2half2_rn(a[2 * q], a[2 * q + 1]);
  ((uint4*)(g_msgs16 + (size_t)gw * HD))[lane] = o;
}

__global__ void k_gru() {
  int idx = blockIdx.x * blockDim.x + threadIdx.x;
  if (idx >= NN * 64) return;
  int v = idx >> 6, q = idx & 63;
  const uint2* px = (const uint2*)(g_gx16 + (size_t)v * 768);
  const uint2* ph = (const uint2*)(g_gh16 + (size_t)v * 768);
  uint2 XZ = px[q], XR = px[q + 64], XH = px[q + 128];
  uint2 HZ = ph[q], HR = ph[q + 64], HH = ph[q + 128];
  float2 xz0 = __half22float2(*(__half2*)&XZ.x), xz1 = __half22float2(*(__half2*)&XZ.y);
  float2 xr0 = __half22float2(*(__half2*)&XR.x), xr1 = __half22float2(*(__half2*)&XR.y);
  float2 xh0 = __half22float2(*(__half2*)&XH.x), xh1 = __half22float2(*(__half2*)&XH.y);
  float2 hz0 = __half22float2(*(__half2*)&HZ.x), hz1 = __half22float2(*(__half2*)&HZ.y);
  float2 hr0 = __half22float2(*(__half2*)&HR.x), hr1 = __half22float2(*(__half2*)&HR.y);
  float2 hh0 = __half22float2(*(__half2*)&HH.x), hh1 = __half22float2(*(__half2*)&HH.y);
  uint2 hraw = ((const uint2*)g_h16)[idx];
  float2 h01 = __half22float2(*(__half2*)&hraw.x);
  float2 h23 = __half22float2(*(__half2*)&hraw.y);
  float r0 = gru1(xz0.x, xr0.x, xh0.x, hz0.x, hr0.x, hh0.x, h01.x);
  float r1 = gru1(xz0.y, xr0.y, xh0.y, hz0.y, hr0.y, hh0.y, h01.y);
  float r2 = gru1(xz1.x, xr1.x, xh1.x, hz1.x, hr1.x, hh1.x, h23.x);
  float r3 = gru1(xz1.y, xr1.y, xh1.y, hz1.y, hr1.y, hh1.y, h23.y);
  uint2 o;
  *(__half2*)&o.x = __floats2half2_rn(r0, r1);
  *(__half2*)&o.y = __floats2half2_rn(r2, r3);
  ((uint2*)g_h16)[idx] = o;
}

__global__ void k_readout1(const float* __restrict__ gateW, const float* __restrict__ gateB,
                           const float* __restrict__ outW, const float* __restrict__ outB) {
  int warp = threadIdx.x >> 5, lane = threadIdx.x & 31;
  int v = blockIdx.x * 8 + warp;
  float g = 0.f, o0 = 0.f, o1 = 0.f;
  if (v < NN) {
    const __half* hv = g_h16 + (size_t)v * HD;
#pragma unroll 4
    for (int j = lane; j < HD; j += 32) {
      float x = __half2float(__ldg(&hv[j]));
      g += x * __ldg(&gateW[j]);
      float2 w = __ldg((const float2*)outW + j);
      o0 += x * w.x;
      o1 += x * w.y;
    }
  }
#pragma unroll
  for (int off = 16; off; off >>= 1) {
    g += __shfl_xor_sync(~0u, g, off);
    o0 += __shfl_xor_sync(~0u, o0, off);
    o1 += __shfl_xor_sync(~0u, o1, off);
  }
  float gl = g + __ldg(gateB);
  if (v < NN && lane == 0) {
    g_gate[v] = gl;
    g_outs[2 * v] = o0 + __ldg(&outB[0]);
    g_outs[2 * v + 1] = o1 + __ldg(&outB[1]);
  }
  __shared__ float smax[8];
  if (lane == 0) smax[warp] = (v < NN) ? gl : -3.4e38f;
  __syncthreads();
  if (threadIdx.x == 0) {
    float m = smax[0];
#pragma unroll
    for (int i = 1; i < 8; i++) m = fmaxf(m, smax[i]);
    atomicMax(&g_gmax, fenc(m));
  }
}

__global__ void k_readout2() {
  int v = blockIdx.x * blockDim.x + threadIdx.x;
  __shared__ float part[4];
  __shared__ int s0;
  if (threadIdx.x < 4) part[threadIdx.x] = 0.f;
  if (threadIdx.x == 0) s0 = find_seg(blockIdx.x * blockDim.x);
  __syncthreads();
  if (v < NN) {
    float e = expf(g_gate[v] - fdec(g_gmax));
    g_gate[v] = e;
    int s = find_seg(v);
    atomicAdd(&part[s - s0], e);
  }
  __syncthreads();
  if (threadIdx.x < 4 && part[threadIdx.x] != 0.f)
    atomicAdd(&g_sums[s0 + threadIdx.x], part[threadIdx.x]);
}

__global__ void k_readout3(float* __restrict__ out) {
  int v = blockIdx.x * blockDim.x + threadIdx.x;
  __shared__ float p0[4], p1[4];
  __shared__ int s0;
  if (threadIdx.x < 4) { p0[threadIdx.x] = 0.f; p1[threadIdx.x] = 0.f; }
  if (threadIdx.x == 0) s0 = find_seg(blockIdx.x * blockDim.x);
  __syncthreads();
  if (v < NN) {
    int s = find_seg(v);
    float w = g_gate[v] / (g_sums[s] + 1e-16f);
    atomicAdd(&p0[s - s0], g_outs[2 * v] * w);
    atomicAdd(&p1[s - s0], g_outs[2 * v + 1] * w);
  }
  __syncthreads();
  if (threadIdx.x < 4) {
    int s = s0 + threadIdx.x;
    if (s < NG && (p0[threadIdx.x] != 0.f || p1[threadIdx.x] != 0.f)) {
      atomicAdd(&out[2 * s], p0[threadIdx.x]);
      atomicAdd(&out[2 * s + 1], p1[threadIdx.x]);
    }
  }
}

extern "C" void kernel_launch(void* const* d_in, const int* in_sizes, int n_in,
                              void* d_out, int out_size) {
  const int* nodes = (const int*)d_in[0];
  const int* gsizes = (const int*)d_in[1];
  const int* edges = (const int*)d_in[2];
  const float* embed = (const float*)d_in[3];
  const float* tw = (const float*)d_in[4];
  const float* tb = (const float*)d_in[5];
  const float* gW = (const float*)d_in[6];
  const float* gU = (const float*)d_in[7];
  const float* gbi = (const float*)d_in[8];
  const float* gbr = (const float*)d_in[9];
  const float* gateW = (const float*)d_in[10];
  const float* gateB = (const float*)d_in[11];
  const float* outW = (const float*)d_in[12];
  const float* outB = (const float*)d_in[13];
  float* out = (float*)d_out;

  cudaFuncSetAttribute(k_g16, cudaFuncAttributeMaxDynamicSharedMemorySize, TG_SMEM);

  __half* h16;  cudaGetSymbolAddress((void**)&h16, g_h16);
  __half* tr16; cudaGetSymbolAddress((void**)&tr16, g_trans16);
  __half* ms16; cudaGetSymbolAddress((void**)&ms16, g_msgs16);
  __half* gx16; cudaGetSymbolAddress((void**)&gx16, g_gx16);
  __half* gh16; cudaGetSymbolAddress((void**)&gh16, g_gh16);
  __half* tw16; cudaGetSymbolAddress((void**)&tw16, g_tw16);
  __half* gW16; cudaGetSymbolAddress((void**)&gW16, g_gW16);
  __half* gU16; cudaGetSymbolAddress((void**)&gU16, g_gU16);

  const int steps[2] = {3, 1};
  dim3 gT(8, (NN + 127) / 128);
  dim3 gG(6, (NN + 127) / 128);

  k_h_init<<<(NN * HD + 255) / 256, 256>>>(nodes, embed);
  k_round_w<<<2048, 256>>>(tw, gW, gU);
  k_init_misc<<<(NN + 255) / 256, 256>>>(gsizes, out);
  // launch 3: first trans GEMM (profiled slot)
  k_g16<<<gT, 256, TG_SMEM>>>(h16, NN, tw16, HD, (long)HD * HD, tb, HD, tr16, NT * HD, 1);
  k_count<<<(NE + 255) / 256, 256>>>(edges);
  k_scan<<<1, 1024>>>();
  k_fill<<<(NE + 255) / 256, 256>>>(edges);

  for (int l = 0; l < 2; l++) {
    const __half* Wt = tw16 + (size_t)l * NT * HD * HD;
    const float* bt = tb + (size_t)l * NT * HD;
    const __half* Wx = gW16 + (size_t)l * 3 * HD * HD;
    const __half* Uh = gU16 + (size_t)l * 3 * HD * HD;
    const float* bi = gbi + (size_t)l * 768;
    const float* br = gbr + (size_t)l * 768;
    for (int s = 0; s < steps[l]; s++) {
      if (l != 0 || s != 0)
        k_g16<<<gT, 256, TG_SMEM>>>(h16, NN, Wt, HD, (long)HD * HD, bt, HD, tr16, NT * HD, 1);
      k_msgs<<<(NN * 32 + 255) / 256, 256>>>();
      k_g16<<<gG, 256, TG_SMEM>>>(ms16, NN, Wx, 768, 0, bi, 0, gx16, 768, 1);
      k_g16<<<gG, 256, TG_SMEM>>>(h16, NN, Uh, 768, 0, br, 0, gh16, 768, 1);
      k_gru<<<(NN * 64 + 255) / 256, 256>>>();
    }
  }
  k_readout1<<<(NN + 7) / 8, 256>>>(gateW, gateB, outW, outB);
  k_readout2<<<(NN + 255) / 256, 256>>>();
  k_readout3<<<(NN + 255) / 256, 256>>>(out);
}

// round 12
// speedup vs baseline: 2.9172x; 1.0197x over previous
#include <cuda_runtime.h>
#include <cuda_fp16.h>
#include <cstdint>
#include <math.h>

#define NN 100000
#define NG 100
#define NE 1000000
#define HD 256
#define NT 4

// fp16 GEMM smem (bytes), BK=64, 3 stages:
// [0, 110592)  : 3 stages x (A 18432 + B 18432); rows padded to 72 halves (144B)
//                epilogue (8 warps x 32x66 floats = 67584B) OVERLAYS this after mainloop
// [110592,111104): bias tile (128 floats)
#define KPAD 72
#define STG_BYTES 36864
#define TG_SMEM 111104

__device__ __half g_h16[(size_t)NN * HD];
__device__ __half g_trans16[(size_t)NN * NT * HD];
__device__ __half g_msgs16[(size_t)NN * HD];
__device__ __half g_gx16[(size_t)NN * 3 * HD];
__device__ __half g_gh16[(size_t)NN * 3 * HD];
__device__ __half g_tw16[2 * NT * HD * HD];   // [l][t][n][k]
__device__ __half g_gW16[2 * 3 * HD * HD];    // [l][n=768][k=256]
__device__ __half g_gU16[2 * 3 * HD * HD];
__device__ float g_gate[NN];
__device__ float g_outs[2 * NN];
__device__ float g_sums[NG];
__device__ unsigned g_gmax;
__device__ int g_deg[NN];
__device__ int g_rowoff[NN + 1];
__device__ int g_cursor[NN];
__device__ int g_csr[NE];
__device__ int g_cum[NG];

__device__ __forceinline__ void mma16(float* d, const unsigned* a, const unsigned* b) {
  asm volatile(
      "mma.sync.aligned.m16n8k16.row.col.f32.f16.f16.f32 "
      "{%0,%1,%2,%3}, {%4,%5,%6,%7}, {%8,%9}, {%0,%1,%2,%3};\n"
      : "+f"(d[0]), "+f"(d[1]), "+f"(d[2]), "+f"(d[3])
      : "r"(a[0]), "r"(a[1]), "r"(a[2]), "r"(a[3]), "r"(b[0]), "r"(b[1]));
}
__device__ __forceinline__ void ldsm4(unsigned* r, uint32_t addr) {
  asm volatile("ldmatrix.sync.aligned.m8n8.x4.shared.b16 {%0,%1,%2,%3}, [%4];"
               : "=r"(r[0]), "=r"(r[1]), "=r"(r[2]), "=r"(r[3]) : "r"(addr));
}
__device__ __forceinline__ void cpa16s(uint32_t daddr, const void* src, bool pred) {
  int sz = pred ? 16 : 0;
  asm volatile("cp.async.cg.shared.global [%0], [%1], 16, %2;\n" :: "r"(daddr), "l"(src), "r"(sz));
}
__device__ __forceinline__ unsigned fenc(float f) {
  unsigned u = __float_as_uint(f);
  return (u & 0x80000000u) ? ~u : (u | 0x80000000u);
}
__device__ __forceinline__ float fdec(unsigned e) {
  return (e & 0x80000000u) ? __uint_as_float(e & 0x7fffffffu) : __uint_as_float(~e);
}
__device__ __forceinline__ int find_seg(int v) {
  int lo = 0, hi = NG;
  while (lo < hi) { int mid = (lo + hi) >> 1; if (g_cum[mid] > v) hi = mid; else lo = mid + 1; }
  return lo;
}
__device__ __forceinline__ float gru1(float xz, float xr, float xh,
                                      float hz, float hr, float hh, float h) {
  float z = 1.f / (1.f + expf(-(xz + hz)));
  float r = 1.f / (1.f + expf(-(xr + hr)));
  float c = tanhf(xh + r * hh);
  return z * h + (1.f - z) * c;
}

__global__ void k_h_init(const int* __restrict__ nodes, const float* __restrict__ embed) {
  int idx = blockIdx.x * blockDim.x + threadIdx.x;
  if (idx >= NN * HD) return;
  int v = idx >> 8, j = idx & 255;
  int tok = __ldg(&nodes[v]);
  int pos = __ldg(&nodes[NN + v]);
  int p = pos < 512 ? pos : 512;
  float pe = 0.f;
  if (p > 0) {
    float ang = (float)(p - 1) * exp2f(-(float)j * 0.10381025296523f);
    pe = (j & 1) ? cosf(ang) : sinf(ang);
  }
  g_h16[idx] = __float2half(__ldg(&embed[(size_t)tok * HD + j]) + pe);
}

// transpose weights to [n][k] fp16
__global__ void k_round_w(const float* __restrict__ tw, const float* __restrict__ gW,
                          const float* __restrict__ gU) {
  int i = blockIdx.x * blockDim.x + threadIdx.x;
  if (i < 2 * NT * HD * HD) {
    int lt = i >> 16, n = (i >> 8) & 255, k = i & 255;
    g_tw16[i] = __float2half(__ldg(&tw[(lt << 16) + (k << 8) + n]));
  }
  if (i < 2 * 3 * HD * HD) {
    int l = i / 196608;
    int rem = i - l * 196608;
    int n = rem >> 8, k = rem & 255;
    g_gW16[i] = __float2half(__ldg(&gW[l * 196608 + k * 768 + n]));
    g_gU16[i] = __float2half(__ldg(&gU[l * 196608 + k * 768 + n]));
  }
}

__global__ void k_init_misc(const int* __restrict__ sizes, float* __restrict__ out) {
  int i = blockIdx.x * blockDim.x + threadIdx.x;
  if (i < NN) g_deg[i] = 0;
  if (blockIdx.x == 0) {
    int t = threadIdx.x;
    if (t < NG) g_sums[t] = 0.f;
    if (t < 2 * NG) out[t] = 0.f;
    if (t == 0) {
      g_gmax = 0u;
      int s = 0;
      for (int g = 0; g < NG; g++) { s += sizes[g]; g_cum[g] = s; }
    }
  }
}

__global__ void k_count(const int* __restrict__ edges) {
  int i = blockIdx.x * blockDim.x + threadIdx.x;
  if (i < NE) atomicAdd(&g_deg[edges[3 * i + 2]], 1);
}

__global__ void k_scan() {
  __shared__ int sCarry;
  __shared__ int warpTot[32];
  int tid = threadIdx.x;
  int lane = tid & 31, wid = tid >> 5;
  if (tid == 0) sCarry = 0;
  __syncthreads();
  for (int base = 0; base < NN; base += 1024) {
    int i = base + tid;
    int v = (i < NN) ? g_deg[i] : 0;
    int x = v;
#pragma unroll
    for (int off = 1; off < 32; off <<= 1) {
      int y = __shfl_up_sync(~0u, x, off);
      if (lane >= off) x += y;
    }
    if (lane == 31) warpTot[wid] = x;
    __syncthreads();
    if (wid == 0) {
      int w = warpTot[lane];
#pragma unroll
      for (int off = 1; off < 32; off <<= 1) {
        int y = __shfl_up_sync(~0u, w, off);
        if (lane >= off) w += y;
      }
      warpTot[lane] = w;
    }
    __syncthreads();
    int warpPrefix = (wid > 0) ? warpTot[wid - 1] : 0;
    int incl = x + warpPrefix;
    int excl = incl - v;
    int carry = sCarry;
    if (i < NN) { g_rowoff[i] = carry + excl; g_cursor[i] = carry + excl; }
    __syncthreads();
    if (tid == 1023) sCarry = carry + incl;
    __syncthreads();
  }
  if (tid == 0) g_rowoff[NN] = sCarry;
}

__global__ void k_fill(const int* __restrict__ edges) {
  int i = blockIdx.x * blockDim.x + threadIdx.x;
  if (i >= NE) return;
  int et = edges[3 * i], src = edges[3 * i + 1], tgt = edges[3 * i + 2];
  int p = atomicAdd(&g_cursor[tgt], 1);
  g_csr[p] = (src << 2) | et;
}

__device__ __forceinline__ void g16_load_slab(uint32_t sbase, int stage,
                                              const __half* A, const __half* Bblk,
                                              int m0, int M, int k0, int lrow, int lseg) {
  uint32_t ab = sbase + stage * STG_BYTES, bb = ab + 18432;
#pragma unroll
  for (int it = 0; it < 4; it++) {
    int row = lrow + it * 32;
    uint32_t off = (uint32_t)(row * (KPAD * 2) + lseg * 16);
    cpa16s(ab + off, A + (size_t)(m0 + row) * HD + k0 + lseg * 8, (m0 + row) < M);
    cpa16s(bb + off, Bblk + (size_t)row * HD + k0 + lseg * 8, true);
  }
  asm volatile("cp.async.commit_group;\n");
}

// C[M, gridX*128] = A[M,256] @ B^T (+bias). A fp16 [m][k], B fp16 [n][k].
// 128x128 tile, BK=64, 3-stage cp.async, one sync per slab, ldmatrix, 2 CTAs/SM.
__global__ __launch_bounds__(256, 2)
void k_g16(const __half* __restrict__ A, int M, const __half* __restrict__ B,
           int nblk, long nblkStride, const float* __restrict__ bias, int biasBlkStride,
           void* __restrict__ Cv, int ldc, int outHalf) {
  extern __shared__ __half sh[];
  uint32_t sbase;
  asm("{ .reg .u64 t; cvta.to.shared.u64 t, %1; cvt.u32.u64 %0, t; }" : "=r"(sbase) : "l"(sh));
  int tid = threadIdx.x, lane = tid & 31, wid = tid >> 5;
  int n0 = blockIdx.x * 128, m0 = blockIdx.y * 128;
  int tB = n0 / nblk, nb0 = n0 - tB * nblk;
  const __half* Bblk = B + (size_t)tB * nblkStride + (size_t)nb0 * HD;
  float* biasS = (float*)((char*)sh + 110592);
  if (tid < 128) biasS[tid] = __ldg(&bias[(size_t)tB * biasBlkStride + nb0 + tid]);

  int lrow = tid >> 3, lseg = tid & 7;
  int wm = (wid & 3) * 32, wn = (wid >> 2) * 64;
  int g = lane >> 2, t2 = (lane & 3) * 2;
  int grp = lane >> 3, l8 = lane & 7;
  int rsel = (grp & 1) * 8;
  int csel = (grp >> 1) * 8;

  float acc[2][8][4];
#pragma unroll
  for (int i = 0; i < 2; i++)
#pragma unroll
    for (int j = 0; j < 8; j++)
#pragma unroll
      for (int k = 0; k < 4; k++) acc[i][j][k] = 0.f;

  // prologue: slabs 0,1 -> stages 0,1
  g16_load_slab(sbase, 0, A, Bblk, m0, M, 0, lrow, lseg);
  g16_load_slab(sbase, 1, A, Bblk, m0, M, 64, lrow, lseg);

#pragma unroll
  for (int kt = 0; kt < 4; kt++) {
    int s = kt % 3;
    if (kt < 3) {
      asm volatile("cp.async.wait_group 1;\n");
    } else {
      asm volatile("cp.async.wait_group 0;\n");
    }
    __syncthreads();
    if (kt < 2) {
      // prefetch slab kt+2 into stage (kt+2)%3 (freed by compute of iter kt-1)
      g16_load_slab(sbase, (kt + 2) % 3, A, Bblk, m0, M, (kt + 2) * 64, lrow, lseg);
    }
    uint32_t aStage = sbase + s * STG_BYTES;
    uint32_t bStage = aStage + 18432;
#pragma unroll
    for (int ks = 0; ks < 4; ks++) {
      int kk = ks * 16;
      unsigned af[2][4], bf[8][2];
      int rowA = wm + rsel + l8;
      int colA = kk + csel;
      ldsm4(af[0], aStage + (uint32_t)(rowA * KPAD + colA) * 2);
      ldsm4(af[1], aStage + (uint32_t)((rowA + 16) * KPAD + colA) * 2);
      int nB = wn + csel + l8;
      int kB = kk + rsel;
#pragma unroll
      for (int p = 0; p < 4; p++) {
        unsigned t[4];
        ldsm4(t, bStage + (uint32_t)((nB + p * 16) * KPAD + kB) * 2);
        bf[2 * p][0] = t[0]; bf[2 * p][1] = t[1];
        bf[2 * p + 1][0] = t[2]; bf[2 * p + 1][1] = t[3];
      }
#pragma unroll
      for (int mt = 0; mt < 2; mt++)
#pragma unroll
        for (int nt = 0; nt < 8; nt++) mma16(acc[mt][nt], af[mt], bf[nt]);
    }
  }
  __syncthreads();  // before epilogue overlays operand buffers

  // epilogue: per-warp 32x66 fp32 stage (overlaid), transposed coalesced store
  float* ep = (float*)sh + wid * 2112;
#pragma unroll
  for (int mt = 0; mt < 2; mt++)
#pragma unroll
    for (int nt = 0; nt < 8; nt++) {
      int lc = nt * 8 + t2;
      float b0 = biasS[wn + lc], b1 = biasS[wn + lc + 1];
      int r0 = mt * 16 + g;
      ep[r0 * 66 + lc] = acc[mt][nt][0] + b0;
      ep[r0 * 66 + lc + 1] = acc[mt][nt][1] + b1;
      ep[(r0 + 8) * 66 + lc] = acc[mt][nt][2] + b0;
      ep[(r0 + 8) * 66 + lc + 1] = acc[mt][nt][3] + b1;
    }
  __syncwarp();
  int colg = n0 + wn + 2 * lane;
#pragma unroll 4
  for (int rr = 0; rr < 32; rr++) {
    int gr = m0 + wm + rr;
    if (gr < M) {
      float2 v = *(float2*)&ep[rr * 66 + 2 * lane];
      if (outHalf) {
        *(__half2*)((__half*)Cv + (size_t)gr * ldc + colg) = __floats2half2_rn(v.x, v.y);
      } else {
        *(float2*)((float*)Cv + (size_t)gr * ldc + colg) = v;
      }
    }
  }
}

__global__ void k_msgs() {
  int gw = (blockIdx.x * blockDim.x + threadIdx.x) >> 5;
  int lane = threadIdx.x & 31;
  if (gw >= NN) return;
  int beg = g_rowoff[gw], end = g_rowoff[gw + 1];
  float a[8] = {0.f, 0.f, 0.f, 0.f, 0.f, 0.f, 0.f, 0.f};
  int i = beg;
  for (; i + 1 < end; i += 2) {
    int e0 = __ldg(&g_csr[i]), e1 = __ldg(&g_csr[i + 1]);
    const uint4* p0 = (const uint4*)(g_trans16 + ((size_t)(e0 >> 2) * (NT * HD) + (size_t)(e0 & 3) * HD));
    const uint4* p1 = (const uint4*)(g_trans16 + ((size_t)(e1 >> 2) * (NT * HD) + (size_t)(e1 & 3) * HD));
    uint4 x = __ldg(p0 + lane), y = __ldg(p1 + lane);
    const __half2* hx = (const __half2*)&x;
    const __half2* hy = (const __half2*)&y;
#pragma unroll
    for (int q = 0; q < 4; q++) {
      float2 fx = __half22float2(hx[q]), fy = __half22float2(hy[q]);
      a[2 * q] += fx.x + fy.x;
      a[2 * q + 1] += fx.y + fy.y;
    }
  }
  if (i < end) {
    int e0 = __ldg(&g_csr[i]);
    const uint4* p0 = (const uint4*)(g_trans16 + ((size_t)(e0 >> 2) * (NT * HD) + (size_t)(e0 & 3) * HD));
    uint4 x = __ldg(p0 + lane);
    const __half2* hx = (const __half2*)&x;
#pragma unroll
    for (int q = 0; q < 4; q++) {
      float2 fx = __half22float2(hx[q]);
      a[2 * q] += fx.x;
      a[2 * q + 1] += fx.y;
    }
  }
  uint4 o;
  __half2* ho = (__half2*)&o;
#pragma unroll
  for (int q = 0; q < 4; q++) ho[q] = __floats2half2_rn(a[2 * q], a[2 * q + 1]);
  ((uint4*)(g_msgs16 + (size_t)gw * HD))[lane] = o;
}

__global__ void k_gru() {
  int idx = blockIdx.x * blockDim.x + threadIdx.x;
  if (idx >= NN * 64) return;
  int v = idx >> 6, q = idx & 63;
  const uint2* px = (const uint2*)(g_gx16 + (size_t)v * 768);
  const uint2* ph = (const uint2*)(g_gh16 + (size_t)v * 768);
  uint2 XZ = px[q], XR = px[q + 64], XH = px[q + 128];
  uint2 HZ = ph[q], HR = ph[q + 64], HH = ph[q + 128];
  float2 xz0 = __half22float2(*(__half2*)&XZ.x), xz1 = __half22float2(*(__half2*)&XZ.y);
  float2 xr0 = __half22float2(*(__half2*)&XR.x), xr1 = __half22float2(*(__half2*)&XR.y);
  float2 xh0 = __half22float2(*(__half2*)&XH.x), xh1 = __half22float2(*(__half2*)&XH.y);
  float2 hz0 = __half22float2(*(__half2*)&HZ.x), hz1 = __half22float2(*(__half2*)&HZ.y);
  float2 hr0 = __half22float2(*(__half2*)&HR.x), hr1 = __half22float2(*(__half2*)&HR.y);
  float2 hh0 = __half22float2(*(__half2*)&HH.x), hh1 = __half22float2(*(__half2*)&HH.y);
  uint2 hraw = ((const uint2*)g_h16)[idx];
  float2 h01 = __half22float2(*(__half2*)&hraw.x);
  float2 h23 = __half22float2(*(__half2*)&hraw.y);
  float r0 = gru1(xz0.x, xr0.x, xh0.x, hz0.x, hr0.x, hh0.x, h01.x);
  float r1 = gru1(xz0.y, xr0.y, xh0.y, hz0.y, hr0.y, hh0.y, h01.y);
  float r2 = gru1(xz1.x, xr1.x, xh1.x, hz1.x, hr1.x, hh1.x, h23.x);
  float r3 = gru1(xz1.y, xr1.y, xh1.y, hz1.y, hr1.y, hh1.y, h23.y);
  uint2 o;
  *(__half2*)&o.x = __floats2half2_rn(r0, r1);
  *(__half2*)&o.y = __floats2half2_rn(r2, r3);
  ((uint2*)g_h16)[idx] = o;
}

__global__ void k_readout1(const float* __restrict__ gateW, const float* __restrict__ gateB,
                           const float* __restrict__ outW, const float* __restrict__ outB) {
  int warp = threadIdx.x >> 5, lane = threadIdx.x & 31;
  int v = blockIdx.x * 8 + warp;
  float g = 0.f, o0 = 0.f, o1 = 0.f;
  if (v < NN) {
    const __half* hv = g_h16 + (size_t)v * HD;
#pragma unroll 4
    for (int j = lane; j < HD; j += 32) {
      float x = __half2float(__ldg(&hv[j]));
      g += x * __ldg(&gateW[j]);
      float2 w = __ldg((const float2*)outW + j);
      o0 += x * w.x;
      o1 += x * w.y;
    }
  }
#pragma unroll
  for (int off = 16; off; off >>= 1) {
    g += __shfl_xor_sync(~0u, g, off);
    o0 += __shfl_xor_sync(~0u, o0, off);
    o1 += __shfl_xor_sync(~0u, o1, off);
  }
  float gl = g + __ldg(gateB);
  if (v < NN && lane == 0) {
    g_gate[v] = gl;
    g_outs[2 * v] = o0 + __ldg(&outB[0]);
    g_outs[2 * v + 1] = o1 + __ldg(&outB[1]);
  }
  __shared__ float smax[8];
  if (lane == 0) smax[warp] = (v < NN) ? gl : -3.4e38f;
  __syncthreads();
  if (threadIdx.x == 0) {
    float m = smax[0];
#pragma unroll
    for (int i = 1; i < 8; i++) m = fmaxf(m, smax[i]);
    atomicMax(&g_gmax, fenc(m));
  }
}

__global__ void k_readout2() {
  int v = blockIdx.x * blockDim.x + threadIdx.x;
  __shared__ float part[4];
  __shared__ int s0;
  if (threadIdx.x < 4) part[threadIdx.x] = 0.f;
  if (threadIdx.x == 0) s0 = find_seg(blockIdx.x * blockDim.x);
  __syncthreads();
  if (v < NN) {
    float e = expf(g_gate[v] - fdec(g_gmax));
    g_gate[v] = e;
    int s = find_seg(v);
    atomicAdd(&part[s - s0], e);
  }
  __syncthreads();
  if (threadIdx.x < 4 && part[threadIdx.x] != 0.f)
    atomicAdd(&g_sums[s0 + threadIdx.x], part[threadIdx.x]);
}

__global__ void k_readout3(float* __restrict__ out) {
  int v = blockIdx.x * blockDim.x + threadIdx.x;
  __shared__ float p0[4], p1[4];
  __shared__ int s0;
  if (threadIdx.x < 4) { p0[threadIdx.x] = 0.f; p1[threadIdx.x] = 0.f; }
  if (threadIdx.x == 0) s0 = find_seg(blockIdx.x * blockDim.x);
  __syncthreads();
  if (v < NN) {
    int s = find_seg(v);
    float w = g_gate[v] / (g_sums[s] + 1e-16f);
    atomicAdd(&p0[s - s0], g_outs[2 * v] * w);
    atomicAdd(&p1[s - s0], g_outs[2 * v + 1] * w);
  }
  __syncthreads();
  if (threadIdx.x < 4) {
    int s = s0 + threadIdx.x;
    if (s < NG && (p0[threadIdx.x] != 0.f || p1[threadIdx.x] != 0.f)) {
      atomicAdd(&out[2 * s], p0[threadIdx.x]);
      atomicAdd(&out[2 * s + 1], p1[threadIdx.x]);
    }
  }
}

extern "C" void kernel_launch(void* const* d_in, const int* in_sizes, int n_in,
                              void* d_out, int out_size) {
  const int* nodes = (const int*)d_in[0];
  const int* gsizes = (const int*)d_in[1];
  const int* edges = (const int*)d_in[2];
  const float* embed = (const float*)d_in[3];
  const float* tw = (const float*)d_in[4];
  const float* tb = (const float*)d_in[5];
  const float* gW = (const float*)d_in[6];
  const float* gU = (const float*)d_in[7];
  const float* gbi = (const float*)d_in[8];
  const float* gbr = (const float*)d_in[9];
  const float* gateW = (const float*)d_in[10];
  const float* gateB = (const float*)d_in[11];
  const float* outW = (const float*)d_in[12];
  const float* outB = (const float*)d_in[13];
  float* out = (float*)d_out;

  cudaFuncSetAttribute(k_g16, cudaFuncAttributeMaxDynamicSharedMemorySize, TG_SMEM);

  __half* h16;  cudaGetSymbolAddress((void**)&h16, g_h16);
  __half* tr16; cudaGetSymbolAddress((void**)&tr16, g_trans16);
  __half* ms16; cudaGetSymbolAddress((void**)&ms16, g_msgs16);
  __half* gx16; cudaGetSymbolAddress((void**)&gx16, g_gx16);
  __half* gh16; cudaGetSymbolAddress((void**)&gh16, g_gh16);
  __half* tw16; cudaGetSymbolAddress((void**)&tw16, g_tw16);
  __half* gW16; cudaGetSymbolAddress((void**)&gW16, g_gW16);
  __half* gU16; cudaGetSymbolAddress((void**)&gU16, g_gU16);

  const int steps[2] = {3, 1};
  dim3 gT(8, (NN + 127) / 128);
  dim3 gG(6, (NN + 127) / 128);

  k_h_init<<<(NN * HD + 255) / 256, 256>>>(nodes, embed);
  k_round_w<<<2048, 256>>>(tw, gW, gU);
  k_init_misc<<<(NN + 255) / 256, 256>>>(gsizes, out);
  // launch 3: first trans GEMM (profiled slot)
  k_g16<<<gT, 256, TG_SMEM>>>(h16, NN, tw16, HD, (long)HD * HD, tb, HD, tr16, NT * HD, 1);
  k_count<<<(NE + 255) / 256, 256>>>(edges);
  k_scan<<<1, 1024>>>();
  k_fill<<<(NE + 255) / 256, 256>>>(edges);

  for (int l = 0; l < 2; l++) {
    const __half* Wt = tw16 + (size_t)l * NT * HD * HD;
    const float* bt = tb + (size_t)l * NT * HD;
    const __half* Wx = gW16 + (size_t)l * 3 * HD * HD;
    const __half* Uh = gU16 + (size_t)l * 3 * HD * HD;
    const float* bi = gbi + (size_t)l * 768;
    const float* br = gbr + (size_t)l * 768;
    for (int s = 0; s < steps[l]; s++) {
      if (l != 0 || s != 0)
        k_g16<<<gT, 256, TG_SMEM>>>(h16, NN, Wt, HD, (long)HD * HD, bt, HD, tr16, NT * HD, 1);
      k_msgs<<<(NN * 32 + 255) / 256, 256>>>();
      k_g16<<<gG, 256, TG_SMEM>>>(ms16, NN, Wx, 768, 0, bi, 0, gx16, 768, 1);
      k_g16<<<gG, 256, TG_SMEM>>>(h16, NN, Uh, 768, 0, br, 0, gh16, 768, 1);
      k_gru<<<(NN * 64 + 255) / 256, 256>>>();
    }
  }
  k_readout1<<<(NN + 7) / 8, 256>>>(gateW, gateB, outW, outB);
  k_readout2<<<(NN + 255) / 256, 256>>>();
  k_readout3<<<(NN + 255) / 256, 256>>>(out);
}

// round 13
// speedup vs baseline: 3.3027x; 1.1322x over previous
#include <cuda_runtime.h>
#include <cuda_fp16.h>
#include <cstdint>
#include <math.h>

#define NN 100000
#define NG 100
#define NE 1000000
#define HD 256
#define NT 4

// fp16 GEMM smem (bytes), BK=64, 3 stages:
// [0, 110592)  : 3 stages x (A 18432 + B 18432); rows padded to 72 halves (144B)
//                epilogue (8 warps x 32x33 uints = 33792B) OVERLAYS this after mainloop
// [110592,111104): bias tile (128 floats)
#define KPAD 72
#define STG_BYTES 36864
#define TG_SMEM 111104

__device__ __half g_h16[(size_t)NN * HD];
__device__ __half g_trans16[(size_t)NN * NT * HD];
__device__ __half g_msgs16[(size_t)NN * HD];
__device__ __half g_gx16[(size_t)NN * 3 * HD];
__device__ __half g_gh16[(size_t)NN * 3 * HD];
__device__ __half g_tw16[2 * NT * HD * HD];   // [l][t][n][k]
__device__ __half g_gW16[2 * 3 * HD * HD];    // [l][n=768][k=256]
__device__ __half g_gU16[2 * 3 * HD * HD];
__device__ float g_gate[NN];
__device__ float g_outs[2 * NN];
__device__ float g_sums[NG];
__device__ unsigned g_gmax;
__device__ int g_deg[NN];
__device__ int g_rowoff[NN + 1];
__device__ int g_cursor[NN];
__device__ int g_csr[NE];
__device__ int g_cum[NG];

__device__ __forceinline__ void mma16(float* d, const unsigned* a, const unsigned* b) {
  asm volatile(
      "mma.sync.aligned.m16n8k16.row.col.f32.f16.f16.f32 "
      "{%0,%1,%2,%3}, {%4,%5,%6,%7}, {%8,%9}, {%0,%1,%2,%3};\n"
      : "+f"(d[0]), "+f"(d[1]), "+f"(d[2]), "+f"(d[3])
      : "r"(a[0]), "r"(a[1]), "r"(a[2]), "r"(a[3]), "r"(b[0]), "r"(b[1]));
}
__device__ __forceinline__ void ldsm4(unsigned* r, uint32_t addr) {
  asm volatile("ldmatrix.sync.aligned.m8n8.x4.shared.b16 {%0,%1,%2,%3}, [%4];"
               : "=r"(r[0]), "=r"(r[1]), "=r"(r[2]), "=r"(r[3]) : "r"(addr));
}
__device__ __forceinline__ void cpa16s(uint32_t daddr, const void* src, bool pred) {
  int sz = pred ? 16 : 0;
  asm volatile("cp.async.cg.shared.global [%0], [%1], 16, %2;\n" :: "r"(daddr), "l"(src), "r"(sz));
}
__device__ __forceinline__ unsigned fenc(float f) {
  unsigned u = __float_as_uint(f);
  return (u & 0x80000000u) ? ~u : (u | 0x80000000u);
}
__device__ __forceinline__ float fdec(unsigned e) {
  return (e & 0x80000000u) ? __uint_as_float(e & 0x7fffffffu) : __uint_as_float(~e);
}
__device__ __forceinline__ int find_seg(int v) {
  int lo = 0, hi = NG;
  while (lo < hi) { int mid = (lo + hi) >> 1; if (g_cum[mid] > v) hi = mid; else lo = mid + 1; }
  return lo;
}
__device__ __forceinline__ float gru1(float xz, float xr, float xh,
                                      float hz, float hr, float hh, float h) {
  float z = 1.f / (1.f + expf(-(xz + hz)));
  float r = 1.f / (1.f + expf(-(xr + hr)));
  float c = tanhf(xh + r * hh);
  return z * h + (1.f - z) * c;
}

__global__ void k_h_init(const int* __restrict__ nodes, const float* __restrict__ embed) {
  int idx = blockIdx.x * blockDim.x + threadIdx.x;
  if (idx >= NN * HD) return;
  int v = idx >> 8, j = idx & 255;
  int tok = __ldg(&nodes[v]);
  int pos = __ldg(&nodes[NN + v]);
  int p = pos < 512 ? pos : 512;
  float pe = 0.f;
  if (p > 0) {
    float ang = (float)(p - 1) * exp2f(-(float)j * 0.10381025296523f);
    pe = (j & 1) ? cosf(ang) : sinf(ang);
  }
  g_h16[idx] = __float2half(__ldg(&embed[(size_t)tok * HD + j]) + pe);
}

// transpose weights to [n][k] fp16
__global__ void k_round_w(const float* __restrict__ tw, const float* __restrict__ gW,
                          const float* __restrict__ gU) {
  int i = blockIdx.x * blockDim.x + threadIdx.x;
  if (i < 2 * NT * HD * HD) {
    int lt = i >> 16, n = (i >> 8) & 255, k = i & 255;
    g_tw16[i] = __float2half(__ldg(&tw[(lt << 16) + (k << 8) + n]));
  }
  if (i < 2 * 3 * HD * HD) {
    int l = i / 196608;
    int rem = i - l * 196608;
    int n = rem >> 8, k = rem & 255;
    g_gW16[i] = __float2half(__ldg(&gW[l * 196608 + k * 768 + n]));
    g_gU16[i] = __float2half(__ldg(&gU[l * 196608 + k * 768 + n]));
  }
}

__global__ void k_init_misc(const int* __restrict__ sizes, float* __restrict__ out) {
  int i = blockIdx.x * blockDim.x + threadIdx.x;
  if (i < NN) g_deg[i] = 0;
  if (blockIdx.x == 0) {
    int t = threadIdx.x;
    if (t < NG) g_sums[t] = 0.f;
    if (t < 2 * NG) out[t] = 0.f;
    if (t == 0) {
      g_gmax = 0u;
      int s = 0;
      for (int g = 0; g < NG; g++) { s += sizes[g]; g_cum[g] = s; }
    }
  }
}

__global__ void k_count(const int* __restrict__ edges) {
  int i = blockIdx.x * blockDim.x + threadIdx.x;
  if (i < NE) atomicAdd(&g_deg[edges[3 * i + 2]], 1);
}

__global__ void k_scan() {
  __shared__ int sCarry;
  __shared__ int warpTot[32];
  int tid = threadIdx.x;
  int lane = tid & 31, wid = tid >> 5;
  if (tid == 0) sCarry = 0;
  __syncthreads();
  for (int base = 0; base < NN; base += 1024) {
    int i = base + tid;
    int v = (i < NN) ? g_deg[i] : 0;
    int x = v;
#pragma unroll
    for (int off = 1; off < 32; off <<= 1) {
      int y = __shfl_up_sync(~0u, x, off);
      if (lane >= off) x += y;
    }
    if (lane == 31) warpTot[wid] = x;
    __syncthreads();
    if (wid == 0) {
      int w = warpTot[lane];
#pragma unroll
      for (int off = 1; off < 32; off <<= 1) {
        int y = __shfl_up_sync(~0u, w, off);
        if (lane >= off) w += y;
      }
      warpTot[lane] = w;
    }
    __syncthreads();
    int warpPrefix = (wid > 0) ? warpTot[wid - 1] : 0;
    int incl = x + warpPrefix;
    int excl = incl - v;
    int carry = sCarry;
    if (i < NN) { g_rowoff[i] = carry + excl; g_cursor[i] = carry + excl; }
    __syncthreads();
    if (tid == 1023) sCarry = carry + incl;
    __syncthreads();
  }
  if (tid == 0) g_rowoff[NN] = sCarry;
}

__global__ void k_fill(const int* __restrict__ edges) {
  int i = blockIdx.x * blockDim.x + threadIdx.x;
  if (i >= NE) return;
  int et = edges[3 * i], src = edges[3 * i + 1], tgt = edges[3 * i + 2];
  int p = atomicAdd(&g_cursor[tgt], 1);
  g_csr[p] = (src << 2) | et;
}

__device__ __forceinline__ void g16_load_slab(uint32_t sbase, int stage,
                                              const __half* A, const __half* Bblk,
                                              int m0, int M, int k0, int lrow, int lseg) {
  uint32_t ab = sbase + stage * STG_BYTES, bb = ab + 18432;
#pragma unroll
  for (int it = 0; it < 4; it++) {
    int row = lrow + it * 32;
    uint32_t off = (uint32_t)(row * (KPAD * 2) + lseg * 16);
    cpa16s(ab + off, A + (size_t)(m0 + row) * HD + k0 + lseg * 8, (m0 + row) < M);
    cpa16s(bb + off, Bblk + (size_t)row * HD + k0 + lseg * 8, true);
  }
  asm volatile("cp.async.commit_group;\n");
}

// Fused-output GEMM: C[:, n0] for column tiles. Tiles with n0 < nsplit use
// (B1, bias1 blocked by nblk1, C1/ldc1); tiles beyond use (B2, bias2, C2/ldc2).
// A fp16 [m][256]; B* fp16 [n][256]; outputs fp16. 128x128 tile, BK=64,
// 3-stage cp.async, ldmatrix, fp16 epilogue staging, 2 CTAs/SM.
__global__ __launch_bounds__(256, 2)
void k_g16(const __half* __restrict__ A, int M,
           const __half* __restrict__ B1, int nblk1, long nblkStride1,
           const float* __restrict__ bias1, int biasStride1,
           __half* __restrict__ C1, int ldc1,
           const __half* __restrict__ B2, const float* __restrict__ bias2,
           __half* __restrict__ C2, int ldc2, int nsplit) {
  extern __shared__ __half sh[];
  uint32_t sbase;
  asm("{ .reg .u64 t; cvta.to.shared.u64 t, %1; cvt.u32.u64 %0, t; }" : "=r"(sbase) : "l"(sh));
  int tid = threadIdx.x, lane = tid & 31, wid = tid >> 5;
  int n0 = blockIdx.x * 128, m0 = blockIdx.y * 128;

  const __half* Bblk;
  __half* C;
  int ldc, ccol;
  float* biasS = (float*)((char*)sh + 110592);
  if (n0 < nsplit) {
    int tB = n0 / nblk1, nb0 = n0 - tB * nblk1;
    Bblk = B1 + (size_t)tB * nblkStride1 + (size_t)nb0 * HD;
    if (tid < 128) biasS[tid] = __ldg(&bias1[(size_t)tB * biasStride1 + nb0 + tid]);
    C = C1; ldc = ldc1; ccol = n0;
  } else {
    int nn = n0 - nsplit;
    Bblk = B2 + (size_t)nn * HD;
    if (tid < 128) biasS[tid] = __ldg(&bias2[nn + tid]);
    C = C2; ldc = ldc2; ccol = nn;
  }

  int lrow = tid >> 3, lseg = tid & 7;
  int wm = (wid & 3) * 32, wn = (wid >> 2) * 64;
  int g = lane >> 2, t2 = (lane & 3) * 2;
  int grp = lane >> 3, l8 = lane & 7;
  int rsel = (grp & 1) * 8;
  int csel = (grp >> 1) * 8;

  float acc[2][8][4];
#pragma unroll
  for (int i = 0; i < 2; i++)
#pragma unroll
    for (int j = 0; j < 8; j++)
#pragma unroll
      for (int k = 0; k < 4; k++) acc[i][j][k] = 0.f;

  g16_load_slab(sbase, 0, A, Bblk, m0, M, 0, lrow, lseg);
  g16_load_slab(sbase, 1, A, Bblk, m0, M, 64, lrow, lseg);

#pragma unroll
  for (int kt = 0; kt < 4; kt++) {
    int s = kt % 3;
    if (kt < 3) {
      asm volatile("cp.async.wait_group 1;\n");
    } else {
      asm volatile("cp.async.wait_group 0;\n");
    }
    __syncthreads();
    if (kt < 2) {
      g16_load_slab(sbase, (kt + 2) % 3, A, Bblk, m0, M, (kt + 2) * 64, lrow, lseg);
    }
    uint32_t aStage = sbase + s * STG_BYTES;
    uint32_t bStage = aStage + 18432;
#pragma unroll
    for (int ks = 0; ks < 4; ks++) {
      int kk = ks * 16;
      unsigned af[2][4], bf[8][2];
      int rowA = wm + rsel + l8;
      int colA = kk + csel;
      ldsm4(af[0], aStage + (uint32_t)(rowA * KPAD + colA) * 2);
      ldsm4(af[1], aStage + (uint32_t)((rowA + 16) * KPAD + colA) * 2);
      int nB = wn + csel + l8;
      int kB = kk + rsel;
#pragma unroll
      for (int p = 0; p < 4; p++) {
        unsigned t[4];
        ldsm4(t, bStage + (uint32_t)((nB + p * 16) * KPAD + kB) * 2);
        bf[2 * p][0] = t[0]; bf[2 * p][1] = t[1];
        bf[2 * p + 1][0] = t[2]; bf[2 * p + 1][1] = t[3];
      }
#pragma unroll
      for (int mt = 0; mt < 2; mt++)
#pragma unroll
        for (int nt = 0; nt < 8; nt++) mma16(acc[mt][nt], af[mt], bf[nt]);
    }
  }
  __syncthreads();  // before epilogue overlays operand buffers

  // epilogue: per-warp 32x33 uint (half2) stage, coalesced half2 stores
  uint32_t* epu = (uint32_t*)sh + wid * 1056;
#pragma unroll
  for (int mt = 0; mt < 2; mt++)
#pragma unroll
    for (int nt = 0; nt < 8; nt++) {
      int lc = nt * 8 + t2;
      float b0 = biasS[wn + lc], b1 = biasS[wn + lc + 1];
      int c2 = nt * 4 + (lane & 3);
      int r0 = mt * 16 + g;
      __half2 v0 = __floats2half2_rn(acc[mt][nt][0] + b0, acc[mt][nt][1] + b1);
      __half2 v1 = __floats2half2_rn(acc[mt][nt][2] + b0, acc[mt][nt][3] + b1);
      epu[r0 * 33 + c2] = *(uint32_t*)&v0;
      epu[(r0 + 8) * 33 + c2] = *(uint32_t*)&v1;
    }
  __syncwarp();
#pragma unroll 4
  for (int rr = 0; rr < 32; rr++) {
    int gr = m0 + wm + rr;
    if (gr < M) {
      uint32_t v = epu[rr * 33 + lane];
      *(uint32_t*)(C + (size_t)gr * ldc + ccol + wn + 2 * lane) = v;
    }
  }
}

__global__ void k_msgs() {
  int gw = (blockIdx.x * blockDim.x + threadIdx.x) >> 5;
  int lane = threadIdx.x & 31;
  if (gw >= NN) return;
  int beg = g_rowoff[gw], end = g_rowoff[gw + 1];
  float a[8] = {0.f, 0.f, 0.f, 0.f, 0.f, 0.f, 0.f, 0.f};
  int i = beg;
  for (; i + 1 < end; i += 2) {
    int e0 = __ldg(&g_csr[i]), e1 = __ldg(&g_csr[i + 1]);
    const uint4* p0 = (const uint4*)(g_trans16 + ((size_t)(e0 >> 2) * (NT * HD) + (size_t)(e0 & 3) * HD));
    const uint4* p1 = (const uint4*)(g_trans16 + ((size_t)(e1 >> 2) * (NT * HD) + (size_t)(e1 & 3) * HD));
    uint4 x = __ldg(p0 + lane), y = __ldg(p1 + lane);
    const __half2* hx = (const __half2*)&x;
    const __half2* hy = (const __half2*)&y;
#pragma unroll
    for (int q = 0; q < 4; q++) {
      float2 fx = __half22float2(hx[q]), fy = __half22float2(hy[q]);
      a[2 * q] += fx.x + fy.x;
      a[2 * q + 1] += fx.y + fy.y;
    }
  }
  if (i < end) {
    int e0 = __ldg(&g_csr[i]);
    const uint4* p0 = (const uint4*)(g_trans16 + ((size_t)(e0 >> 2) * (NT * HD) + (size_t)(e0 & 3) * HD));
    uint4 x = __ldg(p0 + lane);
    const __half2* hx = (const __half2*)&x;
#pragma unroll
    for (int q = 0; q < 4; q++) {
      float2 fx = __half22float2(hx[q]);
      a[2 * q] += fx.x;
      a[2 * q + 1] += fx.y;
    }
  }
  uint4 o;
  __half2* ho = (__half2*)&o;
#pragma unroll
  for (int q = 0; q < 4; q++) ho[q] = __floats2half2_rn(a[2 * q], a[2 * q + 1]);
  ((uint4*)(g_msgs16 + (size_t)gw * HD))[lane] = o;
}

__global__ void k_gru() {
  int idx = blockIdx.x * blockDim.x + threadIdx.x;
  if (idx >= NN * 64) return;
  int v = idx >> 6, q = idx & 63;
  const uint2* px = (const uint2*)(g_gx16 + (size_t)v * 768);
  const uint2* ph = (const uint2*)(g_gh16 + (size_t)v * 768);
  uint2 XZ = px[q], XR = px[q + 64], XH = px[q + 128];
  uint2 HZ = ph[q], HR = ph[q + 64], HH = ph[q + 128];
  float2 xz0 = __half22float2(*(__half2*)&XZ.x), xz1 = __half22float2(*(__half2*)&XZ.y);
  float2 xr0 = __half22float2(*(__half2*)&XR.x), xr1 = __half22float2(*(__half2*)&XR.y);
  float2 xh0 = __half22float2(*(__half2*)&XH.x), xh1 = __half22float2(*(__half2*)&XH.y);
  float2 hz0 = __half22float2(*(__half2*)&HZ.x), hz1 = __half22float2(*(__half2*)&HZ.y);
  float2 hr0 = __half22float2(*(__half2*)&HR.x), hr1 = __half22float2(*(__half2*)&HR.y);
  float2 hh0 = __half22float2(*(__half2*)&HH.x), hh1 = __half22float2(*(__half2*)&HH.y);
  uint2 hraw = ((const uint2*)g_h16)[idx];
  float2 h01 = __half22float2(*(__half2*)&hraw.x);
  float2 h23 = __half22float2(*(__half2*)&hraw.y);
  float r0 = gru1(xz0.x, xr0.x, xh0.x, hz0.x, hr0.x, hh0.x, h01.x);
  float r1 = gru1(xz0.y, xr0.y, xh0.y, hz0.y, hr0.y, hh0.y, h01.y);
  float r2 = gru1(xz1.x, xr1.x, xh1.x, hz1.x, hr1.x, hh1.x, h23.x);
  float r3 = gru1(xz1.y, xr1.y, xh1.y, hz1.y, hr1.y, hh1.y, h23.y);
  uint2 o;
  *(__half2*)&o.x = __floats2half2_rn(r0, r1);
  *(__half2*)&o.y = __floats2half2_rn(r2, r3);
  ((uint2*)g_h16)[idx] = o;
}

__global__ void k_readout1(const float* __restrict__ gateW, const float* __restrict__ gateB,
                           const float* __restrict__ outW, const float* __restrict__ outB) {
  int warp = threadIdx.x >> 5, lane = threadIdx.x & 31;
  int v = blockIdx.x * 8 + warp;
  float g = 0.f, o0 = 0.f, o1 = 0.f;
  if (v < NN) {
    const __half* hv = g_h16 + (size_t)v * HD;
#pragma unroll 4
    for (int j = lane; j < HD; j += 32) {
      float x = __half2float(__ldg(&hv[j]));
      g += x * __ldg(&gateW[j]);
      float2 w = __ldg((const float2*)outW + j);
      o0 += x * w.x;
      o1 += x * w.y;
    }
  }
#pragma unroll
  for (int off = 16; off; off >>= 1) {
    g += __shfl_xor_sync(~0u, g, off);
    o0 += __shfl_xor_sync(~0u, o0, off);
    o1 += __shfl_xor_sync(~0u, o1, off);
  }
  float gl = g + __ldg(gateB);
  if (v < NN && lane == 0) {
    g_gate[v] = gl;
    g_outs[2 * v] = o0 + __ldg(&outB[0]);
    g_outs[2 * v + 1] = o1 + __ldg(&outB[1]);
  }
  __shared__ float smax[8];
  if (lane == 0) smax[warp] = (v < NN) ? gl : -3.4e38f;
  __syncthreads();
  if (threadIdx.x == 0) {
    float m = smax[0];
#pragma unroll
    for (int i = 1; i < 8; i++) m = fmaxf(m, smax[i]);
    atomicMax(&g_gmax, fenc(m));
  }
}

__global__ void k_readout2() {
  int v = blockIdx.x * blockDim.x + threadIdx.x;
  __shared__ float part[4];
  __shared__ int s0;
  if (threadIdx.x < 4) part[threadIdx.x] = 0.f;
  if (threadIdx.x == 0) s0 = find_seg(blockIdx.x * blockDim.x);
  __syncthreads();
  if (v < NN) {
    float e = expf(g_gate[v] - fdec(g_gmax));
    g_gate[v] = e;
    int s = find_seg(v);
    atomicAdd(&part[s - s0], e);
  }
  __syncthreads();
  if (threadIdx.x < 4 && part[threadIdx.x] != 0.f)
    atomicAdd(&g_sums[s0 + threadIdx.x], part[threadIdx.x]);
}

__global__ void k_readout3(float* __restrict__ out) {
  int v = blockIdx.x * blockDim.x + threadIdx.x;
  __shared__ float p0[4], p1[4];
  __shared__ int s0;
  if (threadIdx.x < 4) { p0[threadIdx.x] = 0.f; p1[threadIdx.x] = 0.f; }
  if (threadIdx.x == 0) s0 = find_seg(blockIdx.x * blockDim.x);
  __syncthreads();
  if (v < NN) {
    int s = find_seg(v);
    float w = g_gate[v] / (g_sums[s] + 1e-16f);
    atomicAdd(&p0[s - s0], g_outs[2 * v] * w);
    atomicAdd(&p1[s - s0], g_outs[2 * v + 1] * w);
  }
  __syncthreads();
  if (threadIdx.x < 4) {
    int s = s0 + threadIdx.x;
    if (s < NG && (p0[threadIdx.x] != 0.f || p1[threadIdx.x] != 0.f)) {
      atomicAdd(&out[2 * s], p0[threadIdx.x]);
      atomicAdd(&out[2 * s + 1], p1[threadIdx.x]);
    }
  }
}

extern "C" void kernel_launch(void* const* d_in, const int* in_sizes, int n_in,
                              void* d_out, int out_size) {
  const int* nodes = (const int*)d_in[0];
  const int* gsizes = (const int*)d_in[1];
  const int* edges = (const int*)d_in[2];
  const float* embed = (const float*)d_in[3];
  const float* tw = (const float*)d_in[4];
  const float* tb = (const float*)d_in[5];
  const float* gW = (const float*)d_in[6];
  const float* gU = (const float*)d_in[7];
  const float* gbi = (const float*)d_in[8];
  const float* gbr = (const float*)d_in[9];
  const float* gateW = (const float*)d_in[10];
  const float* gateB = (const float*)d_in[11];
  const float* outW = (const float*)d_in[12];
  const float* outB = (const float*)d_in[13];
  float* out = (float*)d_out;

  cudaFuncSetAttribute(k_g16, cudaFuncAttributeMaxDynamicSharedMemorySize, TG_SMEM);

  __half* h16;  cudaGetSymbolAddress((void**)&h16, g_h16);
  __half* tr16; cudaGetSymbolAddress((void**)&tr16, g_trans16);
  __half* ms16; cudaGetSymbolAddress((void**)&ms16, g_msgs16);
  __half* gx16; cudaGetSymbolAddress((void**)&gx16, g_gx16);
  __half* gh16; cudaGetSymbolAddress((void**)&gh16, g_gh16);
  __half* tw16; cudaGetSymbolAddress((void**)&tw16, g_tw16);
  __half* gW16; cudaGetSymbolAddress((void**)&gW16, g_gW16);
  __half* gU16; cudaGetSymbolAddress((void**)&gU16, g_gU16);

  const int steps[2] = {3, 1};
  dim3 gC(14, (NN + 127) / 128);  // fused trans(8) + gh(6)
  dim3 gG(6, (NN + 127) / 128);

  k_h_init<<<(NN * HD + 255) / 256, 256>>>(nodes, embed);
  k_round_w<<<2048, 256>>>(tw, gW, gU);
  k_init_misc<<<(NN + 255) / 256, 256>>>(gsizes, out);
  // launch 3: first fused trans+gh GEMM (profiled slot)
  k_g16<<<gC, 256, TG_SMEM>>>(h16, NN, tw16, HD, (long)HD * HD, tb, HD, tr16, NT * HD,
                              gU16, gbr, gh16, 768, 1024);
  k_count<<<(NE + 255) / 256, 256>>>(edges);
  k_scan<<<1, 1024>>>();
  k_fill<<<(NE + 255) / 256, 256>>>(edges);

  for (int l = 0; l < 2; l++) {
    const __half* Wt = tw16 + (size_t)l * NT * HD * HD;
    const float* bt = tb + (size_t)l * NT * HD;
    const __half* Wx = gW16 + (size_t)l * 3 * HD * HD;
    const __half* Uh = gU16 + (size_t)l * 3 * HD * HD;
    const float* bi = gbi + (size_t)l * 768;
    const float* br = gbr + (size_t)l * 768;
    for (int s = 0; s < steps[l]; s++) {
      if (l != 0 || s != 0)
        k_g16<<<gC, 256, TG_SMEM>>>(h16, NN, Wt, HD, (long)HD * HD, bt, HD, tr16, NT * HD,
                                    Uh, br, gh16, 768, 1024);
      k_msgs<<<(NN * 32 + 255) / 256, 256>>>();
      k_g16<<<gG, 256, TG_SMEM>>>(ms16, NN, Wx, 768, 0, bi, 0, gx16, 768,
                                  Wx, bi, gx16, 768, 1 << 30);
      k_gru<<<(NN * 64 + 255) / 256, 256>>>();
    }
  }
  k_readout1<<<(NN + 7) / 8, 256>>>(gateW, gateB, outW, outB);
  k_readout2<<<(NN + 255) / 256, 256>>>();
  k_readout3<<<(NN + 255) / 256, 256>>>(out);
}

// round 14
// speedup vs baseline: 3.3508x; 1.0146x over previous
#include <cuda_runtime.h>
#include <cuda_fp16.h>
#include <cstdint>
#include <math.h>

#define NN 100000
#define NG 100
#define NE 1000000
#define HD 256
#define NT 4

// fp16 GEMM smem (bytes), BK=64, 3 stages:
// [0, 110592)  : 3 stages x (A 18432 + B 18432); rows padded to 72 halves (144B)
//                epilogue (8 warps x 1056 uints = 33792B) overlays STAGE 1 after kt=1
// [110592,111104): bias tile (128 floats)
#define KPAD 72
#define STG_BYTES 36864
#define TG_SMEM 111104

__device__ __half g_h16[(size_t)NN * HD];
__device__ __half g_trans16[(size_t)NN * NT * HD];
__device__ __half g_msgs16[(size_t)NN * HD];
__device__ __half g_gx16[(size_t)NN * 3 * HD];
__device__ __half g_gh16[(size_t)NN * 3 * HD];
__device__ __half g_tw16[2 * NT * HD * HD];   // [l][t][n][k]
__device__ __half g_gW16[2 * 3 * HD * HD];    // [l][n=768][k=256]
__device__ __half g_gU16[2 * 3 * HD * HD];
__device__ float g_gate[NN];
__device__ float g_outs[2 * NN];
__device__ float g_sums[NG];
__device__ unsigned g_gmax;
__device__ int g_deg[NN];
__device__ int g_rowoff[NN + 1];
__device__ int g_cursor[NN];
__device__ int g_csr[NE];
__device__ int g_cum[NG];

__device__ __forceinline__ void mma16(float* d, const unsigned* a, const unsigned* b) {
  asm volatile(
      "mma.sync.aligned.m16n8k16.row.col.f32.f16.f16.f32 "
      "{%0,%1,%2,%3}, {%4,%5,%6,%7}, {%8,%9}, {%0,%1,%2,%3};\n"
      : "+f"(d[0]), "+f"(d[1]), "+f"(d[2]), "+f"(d[3])
      : "r"(a[0]), "r"(a[1]), "r"(a[2]), "r"(a[3]), "r"(b[0]), "r"(b[1]));
}
__device__ __forceinline__ void ldsm4(unsigned* r, uint32_t addr) {
  asm volatile("ldmatrix.sync.aligned.m8n8.x4.shared.b16 {%0,%1,%2,%3}, [%4];"
               : "=r"(r[0]), "=r"(r[1]), "=r"(r[2]), "=r"(r[3]) : "r"(addr));
}
__device__ __forceinline__ void cpa16s(uint32_t daddr, const void* src, bool pred) {
  int sz = pred ? 16 : 0;
  asm volatile("cp.async.cg.shared.global [%0], [%1], 16, %2;\n" :: "r"(daddr), "l"(src), "r"(sz));
}
__device__ __forceinline__ unsigned fenc(float f) {
  unsigned u = __float_as_uint(f);
  return (u & 0x80000000u) ? ~u : (u | 0x80000000u);
}
__device__ __forceinline__ float fdec(unsigned e) {
  return (e & 0x80000000u) ? __uint_as_float(e & 0x7fffffffu) : __uint_as_float(~e);
}
__device__ __forceinline__ int find_seg(int v) {
  int lo = 0, hi = NG;
  while (lo < hi) { int mid = (lo + hi) >> 1; if (g_cum[mid] > v) hi = mid; else lo = mid + 1; }
  return lo;
}
__device__ __forceinline__ float gru1(float xz, float xr, float xh,
                                      float hz, float hr, float hh, float h) {
  float z = 1.f / (1.f + expf(-(xz + hz)));
  float r = 1.f / (1.f + expf(-(xr + hr)));
  float c = tanhf(xh + r * hh);
  return z * h + (1.f - z) * c;
}

__global__ void k_h_init(const int* __restrict__ nodes, const float* __restrict__ embed) {
  int idx = blockIdx.x * blockDim.x + threadIdx.x;
  if (idx >= NN * HD) return;
  int v = idx >> 8, j = idx & 255;
  int tok = __ldg(&nodes[v]);
  int pos = __ldg(&nodes[NN + v]);
  int p = pos < 512 ? pos : 512;
  float pe = 0.f;
  if (p > 0) {
    float ang = (float)(p - 1) * exp2f(-(float)j * 0.10381025296523f);
    pe = (j & 1) ? cosf(ang) : sinf(ang);
  }
  g_h16[idx] = __float2half(__ldg(&embed[(size_t)tok * HD + j]) + pe);
}

// transpose weights to [n][k] fp16
__global__ void k_round_w(const float* __restrict__ tw, const float* __restrict__ gW,
                          const float* __restrict__ gU) {
  int i = blockIdx.x * blockDim.x + threadIdx.x;
  if (i < 2 * NT * HD * HD) {
    int lt = i >> 16, n = (i >> 8) & 255, k = i & 255;
    g_tw16[i] = __float2half(__ldg(&tw[(lt << 16) + (k << 8) + n]));
  }
  if (i < 2 * 3 * HD * HD) {
    int l = i / 196608;
    int rem = i - l * 196608;
    int n = rem >> 8, k = rem & 255;
    g_gW16[i] = __float2half(__ldg(&gW[l * 196608 + k * 768 + n]));
    g_gU16[i] = __float2half(__ldg(&gU[l * 196608 + k * 768 + n]));
  }
}

// init + edge degree histogram merged (grid covers NE threads)
__global__ void k_init_count(const int* __restrict__ sizes, float* __restrict__ out,
                             const int* __restrict__ edges) {
  int i = blockIdx.x * blockDim.x + threadIdx.x;
  if (i < NN) g_deg[i] = 0;
  if (blockIdx.x == 0) {
    int t = threadIdx.x;
    if (t < NG) g_sums[t] = 0.f;
    if (t < 2 * NG) out[t] = 0.f;
    if (t == 0) {
      g_gmax = 0u;
      int s = 0;
      for (int g = 0; g < NG; g++) { s += sizes[g]; g_cum[g] = s; }
    }
  }
}
__global__ void k_count(const int* __restrict__ edges) {
  int i = blockIdx.x * blockDim.x + threadIdx.x;
  if (i < NE) atomicAdd(&g_deg[edges[3 * i + 2]], 1);
}

__global__ void k_scan() {
  __shared__ int sCarry;
  __shared__ int warpTot[32];
  int tid = threadIdx.x;
  int lane = tid & 31, wid = tid >> 5;
  if (tid == 0) sCarry = 0;
  __syncthreads();
  for (int base = 0; base < NN; base += 1024) {
    int i = base + tid;
    int v = (i < NN) ? g_deg[i] : 0;
    int x = v;
#pragma unroll
    for (int off = 1; off < 32; off <<= 1) {
      int y = __shfl_up_sync(~0u, x, off);
      if (lane >= off) x += y;
    }
    if (lane == 31) warpTot[wid] = x;
    __syncthreads();
    if (wid == 0) {
      int w = warpTot[lane];
#pragma unroll
      for (int off = 1; off < 32; off <<= 1) {
        int y = __shfl_up_sync(~0u, w, off);
        if (lane >= off) w += y;
      }
      warpTot[lane] = w;
    }
    __syncthreads();
    int warpPrefix = (wid > 0) ? warpTot[wid - 1] : 0;
    int incl = x + warpPrefix;
    int excl = incl - v;
    int carry = sCarry;
    if (i < NN) { g_rowoff[i] = carry + excl; g_cursor[i] = carry + excl; }
    __syncthreads();
    if (tid == 1023) sCarry = carry + incl;
    __syncthreads();
  }
  if (tid == 0) g_rowoff[NN] = sCarry;
}

__global__ void k_fill(const int* __restrict__ edges) {
  int i = blockIdx.x * blockDim.x + threadIdx.x;
  if (i >= NE) return;
  int et = edges[3 * i], src = edges[3 * i + 1], tgt = edges[3 * i + 2];
  int p = atomicAdd(&g_cursor[tgt], 1);
  g_csr[p] = (src << 2) | et;
}

__device__ __forceinline__ void g16_load_slab(uint32_t abase, const __half* Arow,
                                              const __half* Brow, int rowOk0, int k0,
                                              uint32_t loff) {
  uint32_t bb = abase + 18432;
#pragma unroll
  for (int it = 0; it < 4; it++) {
    uint32_t off = loff + (uint32_t)it * 32 * (KPAD * 2);
    cpa16s(abase + off, Arow + (size_t)it * 32 * HD + k0, rowOk0 > it * 32);
    cpa16s(bb + off, Brow + (size_t)it * 32 * HD + k0, true);
  }
  asm volatile("cp.async.commit_group;\n");
}

// Fused-output GEMM (see R13). 128x128 tile, BK=64, 3-stage cp.async,
// ldmatrix, fp16 epilogue staged in stage-1 region (no extra barrier), 2 CTAs/SM.
__global__ __launch_bounds__(256, 2)
void k_g16(const __half* __restrict__ A, int M,
           const __half* __restrict__ B1, int nblk1, long nblkStride1,
           const float* __restrict__ bias1, int biasStride1,
           __half* __restrict__ C1, int ldc1,
           const __half* __restrict__ B2, const float* __restrict__ bias2,
           __half* __restrict__ C2, int ldc2, int nsplit) {
  extern __shared__ __half sh[];
  uint32_t sbase;
  asm("{ .reg .u64 t; cvta.to.shared.u64 t, %1; cvt.u32.u64 %0, t; }" : "=r"(sbase) : "l"(sh));
  int tid = threadIdx.x, lane = tid & 31, wid = tid >> 5;
  int n0 = blockIdx.x * 128, m0 = blockIdx.y * 128;

  const __half* Bblk;
  __half* C;
  int ldc, ccol;
  float* biasS = (float*)((char*)sh + 110592);
  if (n0 < nsplit) {
    int tB = n0 / nblk1, nb0 = n0 - tB * nblk1;
    Bblk = B1 + (size_t)tB * nblkStride1 + (size_t)nb0 * HD;
    if (tid < 128) biasS[tid] = __ldg(&bias1[(size_t)tB * biasStride1 + nb0 + tid]);
    C = C1; ldc = ldc1; ccol = n0;
  } else {
    int nn = n0 - nsplit;
    Bblk = B2 + (size_t)nn * HD;
    if (tid < 128) biasS[tid] = __ldg(&bias2[nn + tid]);
    C = C2; ldc = ldc2; ccol = nn;
  }

  int lrow = tid >> 3, lseg = tid & 7;
  uint32_t loff = (uint32_t)(lrow * (KPAD * 2) + lseg * 16);
  const __half* Arow = A + (size_t)(m0 + lrow) * HD + lseg * 8;
  const __half* Brow = Bblk + (size_t)lrow * HD + lseg * 8;
  int rowOk = M - m0 - lrow;  // pred: rowOk > it*32

  int wm = (wid & 3) * 32, wn = (wid >> 2) * 64;
  int g = lane >> 2;
  int grp = lane >> 3, l8 = lane & 7;
  int rsel = (grp & 1) * 8;
  int csel = (grp >> 1) * 8;
  // hoisted smem addresses (stage-relative)
  uint32_t aAddr0 = sbase + (uint32_t)((wm + rsel + l8) * KPAD + csel) * 2;
  uint32_t bAddr0 = sbase + 18432 + (uint32_t)((wn + csel + l8) * KPAD + rsel) * 2;

  float acc[2][8][4];
#pragma unroll
  for (int i = 0; i < 2; i++)
#pragma unroll
    for (int j = 0; j < 8; j++)
#pragma unroll
      for (int k = 0; k < 4; k++) acc[i][j][k] = 0.f;

  g16_load_slab(sbase, Arow, Brow, rowOk, 0, loff);
  g16_load_slab(sbase + STG_BYTES, Arow, Brow, rowOk, 64, loff);

#pragma unroll
  for (int kt = 0; kt < 4; kt++) {
    int s = kt % 3;
    if (kt < 3) {
      asm volatile("cp.async.wait_group 1;\n");
    } else {
      asm volatile("cp.async.wait_group 0;\n");
    }
    __syncthreads();
    if (kt < 2) {
      g16_load_slab(sbase + ((kt + 2) % 3) * STG_BYTES, Arow, Brow, rowOk, (kt + 2) * 64, loff);
    }
    uint32_t aA = aAddr0 + s * STG_BYTES;
    uint32_t bA = bAddr0 + s * STG_BYTES;
#pragma unroll
    for (int ks = 0; ks < 4; ks++) {
      uint32_t kOff = (uint32_t)(ks * 16 * 2);
      unsigned af[2][4], bf[8][2];
      ldsm4(af[0], aA + kOff);
      ldsm4(af[1], aA + kOff + (uint32_t)(16 * KPAD * 2));
#pragma unroll
      for (int p = 0; p < 4; p++) {
        unsigned t[4];
        ldsm4(t, bA + kOff + (uint32_t)(p * 16 * KPAD * 2));
        bf[2 * p][0] = t[0]; bf[2 * p][1] = t[1];
        bf[2 * p + 1][0] = t[2]; bf[2 * p + 1][1] = t[3];
      }
#pragma unroll
      for (int mt = 0; mt < 2; mt++)
#pragma unroll
        for (int nt = 0; nt < 8; nt++) mma16(acc[mt][nt], af[mt], bf[nt]);
    }
  }
  // epilogue staged in STAGE-1 region: no warp touches stage 1 after its kt=1
  // iteration (kt=2 reads stage 2, kt=3 reads stage 0; per-iter barriers order those).
  uint32_t* epu = (uint32_t*)((char*)sh + STG_BYTES) + wid * 1056;
  int t2 = (lane & 3) * 2;
#pragma unroll
  for (int mt = 0; mt < 2; mt++)
#pragma unroll
    for (int nt = 0; nt < 8; nt++) {
      int lc = nt * 8 + t2;
      float b0 = biasS[wn + lc], b1 = biasS[wn + lc + 1];
      int c2 = nt * 4 + (lane & 3);
      int r0 = mt * 16 + g;
      __half2 v0 = __floats2half2_rn(acc[mt][nt][0] + b0, acc[mt][nt][1] + b1);
      __half2 v1 = __floats2half2_rn(acc[mt][nt][2] + b0, acc[mt][nt][3] + b1);
      epu[r0 * 33 + c2] = *(uint32_t*)&v0;
      epu[(r0 + 8) * 33 + c2] = *(uint32_t*)&v1;
    }
  __syncwarp();
#pragma unroll 4
  for (int rr = 0; rr < 32; rr++) {
    int gr = m0 + wm + rr;
    if (gr < M) {
      uint32_t v = epu[rr * 33 + lane];
      *(uint32_t*)(C + (size_t)gr * ldc + ccol + wn + 2 * lane) = v;
    }
  }
}

__global__ void k_msgs() {
  int gw = (blockIdx.x * blockDim.x + threadIdx.x) >> 5;
  int lane = threadIdx.x & 31;
  if (gw >= NN) return;
  int beg = g_rowoff[gw], end = g_rowoff[gw + 1];
  float a[8] = {0.f, 0.f, 0.f, 0.f, 0.f, 0.f, 0.f, 0.f};
  int i = beg;
  for (; i + 1 < end; i += 2) {
    int e0 = __ldg(&g_csr[i]), e1 = __ldg(&g_csr[i + 1]);
    const uint4* p0 = (const uint4*)(g_trans16 + ((size_t)(e0 >> 2) * (NT * HD) + (size_t)(e0 & 3) * HD));
    const uint4* p1 = (const uint4*)(g_trans16 + ((size_t)(e1 >> 2) * (NT * HD) + (size_t)(e1 & 3) * HD));
    uint4 x = __ldg(p0 + lane), y = __ldg(p1 + lane);
    const __half2* hx = (const __half2*)&x;
    const __half2* hy = (const __half2*)&y;
#pragma unroll
    for (int q = 0; q < 4; q++) {
      float2 fx = __half22float2(hx[q]), fy = __half22float2(hy[q]);
      a[2 * q] += fx.x + fy.x;
      a[2 * q + 1] += fx.y + fy.y;
    }
  }
  if (i < end) {
    int e0 = __ldg(&g_csr[i]);
    const uint4* p0 = (const uint4*)(g_trans16 + ((size_t)(e0 >> 2) * (NT * HD) + (size_t)(e0 & 3) * HD));
    uint4 x = __ldg(p0 + lane);
    const __half2* hx = (const __half2*)&x;
#pragma unroll
    for (int q = 0; q < 4; q++) {
      float2 fx = __half22float2(hx[q]);
      a[2 * q] += fx.x;
      a[2 * q + 1] += fx.y;
    }
  }
  uint4 o;
  __half2* ho = (__half2*)&o;
#pragma unroll
  for (int q = 0; q < 4; q++) ho[q] = __floats2half2_rn(a[2 * q], a[2 * q + 1]);
  ((uint4*)(g_msgs16 + (size_t)gw * HD))[lane] = o;
}

// 8 halves per thread (uint4), NN*32 threads
__global__ void k_gru() {
  int idx = blockIdx.x * blockDim.x + threadIdx.x;
  if (idx >= NN * 32) return;
  int v = idx >> 5, q = idx & 31;
  const uint4* px = (const uint4*)(g_gx16 + (size_t)v * 768);
  const uint4* ph = (const uint4*)(g_gh16 + (size_t)v * 768);
  uint4 XZ = px[q], XR = px[q + 32], XH = px[q + 64];
  uint4 HZ = ph[q], HR = ph[q + 32], HH = ph[q + 64];
  uint4 hraw = ((const uint4*)g_h16)[idx];
  uint4 o;
  const __half2* xz = (const __half2*)&XZ;
  const __half2* xr = (const __half2*)&XR;
  const __half2* xh = (const __half2*)&XH;
  const __half2* hz = (const __half2*)&HZ;
  const __half2* hr = (const __half2*)&HR;
  const __half2* hh = (const __half2*)&HH;
  const __half2* hv = (const __half2*)&hraw;
  __half2* ho = (__half2*)&o;
#pragma unroll
  for (int p = 0; p < 4; p++) {
    float2 fxz = __half22float2(xz[p]), fxr = __half22float2(xr[p]), fxh = __half22float2(xh[p]);
    float2 fhz = __half22float2(hz[p]), fhr = __half22float2(hr[p]), fhh = __half22float2(hh[p]);
    float2 fh = __half22float2(hv[p]);
    float r0 = gru1(fxz.x, fxr.x, fxh.x, fhz.x, fhr.x, fhh.x, fh.x);
    float r1 = gru1(fxz.y, fxr.y, fxh.y, fhz.y, fhr.y, fhh.y, fh.y);
    ho[p] = __floats2half2_rn(r0, r1);
  }
  ((uint4*)g_h16)[idx] = o;
}

__global__ void k_readout1(const float* __restrict__ gateW, const float* __restrict__ gateB,
                           const float* __restrict__ outW, const float* __restrict__ outB) {
  int warp = threadIdx.x >> 5, lane = threadIdx.x & 31;
  int v = blockIdx.x * 8 + warp;
  float g = 0.f, o0 = 0.f, o1 = 0.f;
  if (v < NN) {
    const __half* hv = g_h16 + (size_t)v * HD;
#pragma unroll 4
    for (int j = lane; j < HD; j += 32) {
      float x = __half2float(__ldg(&hv[j]));
      g += x * __ldg(&gateW[j]);
      float2 w = __ldg((const float2*)outW + j);
      o0 += x * w.x;
      o1 += x * w.y;
    }
  }
#pragma unroll
  for (int off = 16; off; off >>= 1) {
    g += __shfl_xor_sync(~0u, g, off);
    o0 += __shfl_xor_sync(~0u, o0, off);
    o1 += __shfl_xor_sync(~0u, o1, off);
  }
  float gl = g + __ldg(gateB);
  if (v < NN && lane == 0) {
    g_gate[v] = gl;
    g_outs[2 * v] = o0 + __ldg(&outB[0]);
    g_outs[2 * v + 1] = o1 + __ldg(&outB[1]);
  }
  __shared__ float smax[8];
  if (lane == 0) smax[warp] = (v < NN) ? gl : -3.4e38f;
  __syncthreads();
  if (threadIdx.x == 0) {
    float m = smax[0];
#pragma unroll
    for (int i = 1; i < 8; i++) m = fmaxf(m, smax[i]);
    atomicMax(&g_gmax, fenc(m));
  }
}

__global__ void k_readout2() {
  int v = blockIdx.x * blockDim.x + threadIdx.x;
  __shared__ float part[4];
  __shared__ int s0;
  if (threadIdx.x < 4) part[threadIdx.x] = 0.f;
  if (threadIdx.x == 0) s0 = find_seg(blockIdx.x * blockDim.x);
  __syncthreads();
  if (v < NN) {
    float e = expf(g_gate[v] - fdec(g_gmax));
    g_gate[v] = e;
    int s = find_seg(v);
    atomicAdd(&part[s - s0], e);
  }
  __syncthreads();
  if (threadIdx.x < 4 && part[threadIdx.x] != 0.f)
    atomicAdd(&g_sums[s0 + threadIdx.x], part[threadIdx.x]);
}

__global__ void k_readout3(float* __restrict__ out) {
  int v = blockIdx.x * blockDim.x + threadIdx.x;
  __shared__ float p0[4], p1[4];
  __shared__ int s0;
  if (threadIdx.x < 4) { p0[threadIdx.x] = 0.f; p1[threadIdx.x] = 0.f; }
  if (threadIdx.x == 0) s0 = find_seg(blockIdx.x * blockDim.x);
  __syncthreads();
  if (v < NN) {
    int s = find_seg(v);
    float w = g_gate[v] / (g_sums[s] + 1e-16f);
    atomicAdd(&p0[s - s0], g_outs[2 * v] * w);
    atomicAdd(&p1[s - s0], g_outs[2 * v + 1] * w);
  }
  __syncthreads();
  if (threadIdx.x < 4) {
    int s = s0 + threadIdx.x;
    if (s < NG && (p0[threadIdx.x] != 0.f || p1[threadIdx.x] != 0.f)) {
      atomicAdd(&out[2 * s], p0[threadIdx.x]);
      atomicAdd(&out[2 * s + 1], p1[threadIdx.x]);
    }
  }
}

extern "C" void kernel_launch(void* const* d_in, const int* in_sizes, int n_in,
                              void* d_out, int out_size) {
  const int* nodes = (const int*)d_in[0];
  const int* gsizes = (const int*)d_in[1];
  const int* edges = (const int*)d_in[2];
  const float* embed = (const float*)d_in[3];
  const float* tw = (const float*)d_in[4];
  const float* tb = (const float*)d_in[5];
  const float* gW = (const float*)d_in[6];
  const float* gU = (const float*)d_in[7];
  const float* gbi = (const float*)d_in[8];
  const float* gbr = (const float*)d_in[9];
  const float* gateW = (const float*)d_in[10];
  const float* gateB = (const float*)d_in[11];
  const float* outW = (const float*)d_in[12];
  const float* outB = (const float*)d_in[13];
  float* out = (float*)d_out;

  cudaFuncSetAttribute(k_g16, cudaFuncAttributeMaxDynamicSharedMemorySize, TG_SMEM);

  __half* h16;  cudaGetSymbolAddress((void**)&h16, g_h16);
  __half* tr16; cudaGetSymbolAddress((void**)&tr16, g_trans16);
  __half* ms16; cudaGetSymbolAddress((void**)&ms16, g_msgs16);
  __half* gx16; cudaGetSymbolAddress((void**)&gx16, g_gx16);
  __half* gh16; cudaGetSymbolAddress((void**)&gh16, g_gh16);
  __half* tw16; cudaGetSymbolAddress((void**)&tw16, g_tw16);
  __half* gW16; cudaGetSymbolAddress((void**)&gW16, g_gW16);
  __half* gU16; cudaGetSymbolAddress((void**)&gU16, g_gU16);

  const int steps[2] = {3, 1};
  dim3 gC(14, (NN + 127) / 128);  // fused trans(8) + gh(6)
  dim3 gG(6, (NN + 127) / 128);

  k_h_init<<<(NN * HD + 255) / 256, 256>>>(nodes, embed);
  k_round_w<<<2048, 256>>>(tw, gW, gU);
  k_init_count<<<(NN + 255) / 256, 256>>>(gsizes, out, edges);
  // launch 3: first fused trans+gh GEMM (profiled slot)
  k_g16<<<gC, 256, TG_SMEM>>>(h16, NN, tw16, HD, (long)HD * HD, tb, HD, tr16, NT * HD,
                              gU16, gbr, gh16, 768, 1024);
  k_count<<<(NE + 255) / 256, 256>>>(edges);
  k_scan<<<1, 1024>>>();
  k_fill<<<(NE + 255) / 256, 256>>>(edges);

  for (int l = 0; l < 2; l++) {
    const __half* Wt = tw16 + (size_t)l * NT * HD * HD;
    const float* bt = tb + (size_t)l * NT * HD;
    const __half* Wx = gW16 + (size_t)l * 3 * HD * HD;
    const __half* Uh = gU16 + (size_t)l * 3 * HD * HD;
    const float* bi = gbi + (size_t)l * 768;
    const float* br = gbr + (size_t)l * 768;
    for (int s = 0; s < steps[l]; s++) {
      if (l != 0 || s != 0)
        k_g16<<<gC, 256, TG_SMEM>>>(h16, NN, Wt, HD, (long)HD * HD, bt, HD, tr16, NT * HD,
                                    Uh, br, gh16, 768, 1024);
      k_msgs<<<(NN * 32 + 255) / 256, 256>>>();
      k_g16<<<gG, 256, TG_SMEM>>>(ms16, NN, Wx, 768, 0, bi, 0, gx16, 768,
                                  Wx, bi, gx16, 768, 1 << 30);
      k_gru<<<(NN * 32 + 255) / 256, 256>>>();
    }
  }
  k_readout1<<<(NN + 7) / 8, 256>>>(gateW, gateB, outW, outB);
  k_readout2<<<(NN + 255) / 256, 256>>>();
  k_readout3<<<(NN + 255) / 256, 256>>>(out);
}